// round 2
// baseline (speedup 1.0000x reference)
#include <cuda_runtime.h>
#include <math.h>

// ---------------- problem constants ----------------
#define N_NODES 32768
#define C_COMM  512
#define IN_DIM  128
#define HID     512
#define NHEAD   4
#define DHEAD   128
#define NLAYER  2
#define OUT_DIM 64
#define NDIST   31
#define EPS     1e-5f

#define CHUNK   256
#define NCHUNK  (N_NODES / CHUNK)   // 128

// ---------------- scratch (device globals; no allocation allowed) ----------------
__device__ float g_h   [N_NODES * HID];
__device__ float g_t0  [N_NODES * HID];
__device__ float g_t1  [N_NODES * HID];
__device__ float g_q   [N_NODES * HID];
__device__ float g_dots[(size_t)NHEAD * N_NODES * C_COMM];
__device__ float g_comm[C_COMM * HID];
__device__ float g_k   [C_COMM * HID];
__device__ float g_v   [C_COMM * HID];
__device__ int   g_hist     [NCHUNK * C_COMM];
__device__ int   g_chunkbase[NCHUNK * C_COMM];
__device__ int   g_counts [C_COMM];
__device__ int   g_offsets[C_COMM];
__device__ int   g_members[N_NODES];
__device__ float g_logc[C_COMM];
__device__ float g_inv [C_COMM];
__device__ float g_table[NDIST];

// ---------------- community preprocessing (deterministic, stable) ----------------

// one block per chunk of 256 nodes: shared histogram of communities
__global__ void hist_kernel(const int* __restrict__ ntc) {
    __shared__ int sh[C_COMM];
    int chunk = blockIdx.x;
    for (int i = threadIdx.x; i < C_COMM; i += blockDim.x) sh[i] = 0;
    __syncthreads();
    int node = chunk * CHUNK + threadIdx.x;
    atomicAdd(&sh[ntc[node]], 1);
    __syncthreads();
    for (int i = threadIdx.x; i < C_COMM; i += blockDim.x)
        g_hist[chunk * C_COMM + i] = sh[i];
}

// one block per community: exclusive scan over the 128 chunk counts
__global__ void chunk_scan_kernel() {
    int c = blockIdx.x;
    __shared__ int s[NCHUNK];
    int t = threadIdx.x;                 // blockDim == NCHUNK (128)
    int own = g_hist[t * C_COMM + c];
    s[t] = own;
    __syncthreads();
    for (int off = 1; off < NCHUNK; off <<= 1) {
        int v = (t >= off) ? s[t - off] : 0;
        __syncthreads();
        s[t] += v;
        __syncthreads();
    }
    g_chunkbase[t * C_COMM + c] = s[t] - own;   // exclusive
    if (t == NCHUNK - 1) g_counts[c] = s[t];
}

// single block: exclusive scan of counts -> offsets, plus log/inv
__global__ void offsets_kernel() {
    __shared__ int s[C_COMM];
    int t = threadIdx.x;                 // blockDim == C_COMM (512)
    int own = g_counts[t];
    s[t] = own;
    __syncthreads();
    for (int off = 1; off < C_COMM; off <<= 1) {
        int v = (t >= off) ? s[t - off] : 0;
        __syncthreads();
        s[t] += v;
        __syncthreads();
    }
    g_offsets[t] = s[t] - own;
    g_logc[t]    = logf((float)own);              // log(0) = -inf matches jnp
    g_inv[t]     = 1.0f / (float)(own > 0 ? own : 1);
}

// stable scatter: rank within chunk computed by serial scan of shared ntc
__global__ void scatter_kernel(const int* __restrict__ ntc) {
    __shared__ int s[CHUNK];
    int chunk = blockIdx.x;
    int t = threadIdx.x;
    int node = chunk * CHUNK + t;
    int c = ntc[node];
    s[t] = c;
    __syncthreads();
    int lrank = 0;
    for (int j = 0; j < t; j++) lrank += (s[j] == c);
    g_members[g_offsets[c] + g_chunkbase[chunk * C_COMM + c] + lrank] = node;
}

// one block per community: mean of member rows of g_h (deterministic order)
__global__ void comm_avg_kernel() {
    int c = blockIdx.x;
    int t = threadIdx.x;                 // 256 threads, 2 cols each
    int off = g_offsets[c], cnt = g_counts[c];
    float a0 = 0.f, a1 = 0.f;
    for (int m = 0; m < cnt; m++) {
        const float* row = g_h + (size_t)g_members[off + m] * HID;
        a0 += row[t];
        a1 += row[t + 256];
    }
    float inv = g_inv[c];
    g_comm[c * HID + t]       = a0 * inv;
    g_comm[c * HID + t + 256] = a1 * inv;
}

// ---------------- distance-bias table: table[i] = dis_emb[i] . dis_w + dis_b ----------------
__global__ void bias_table_kernel(const float* __restrict__ emb,
                                  const float* __restrict__ w,
                                  const float* __restrict__ bptr) {
    int i = blockIdx.x;                  // 0..30
    int t = threadIdx.x;                 // 128
    float s = emb[i * HID + t]       * w[t]
            + emb[i * HID + t + 128] * w[t + 128]
            + emb[i * HID + t + 256] * w[t + 256]
            + emb[i * HID + t + 384] * w[t + 384];
    for (int o = 16; o; o >>= 1) s += __shfl_xor_sync(0xFFFFFFFFu, s, o);
    __shared__ float r[4];
    if ((t & 31) == 0) r[t >> 5] = s;
    __syncthreads();
    if (t == 0) g_table[i] = r[0] + r[1] + r[2] + r[3] + bptr[0];
}

// ---------------- LayerNorm + ReLU (row length HID=512) ----------------
__global__ void ln_relu_kernel(const float* __restrict__ in, float* __restrict__ out,
                               const float* __restrict__ g, const float* __restrict__ b) {
    size_t row = blockIdx.x;
    int t = threadIdx.x;                 // 256 threads, 2 elems each
    const float* x = in + row * HID;
    float v0 = x[t], v1 = x[t + 256];
    float s = v0 + v1, q = v0 * v0 + v1 * v1;
    for (int o = 16; o; o >>= 1) {
        s += __shfl_xor_sync(0xFFFFFFFFu, s, o);
        q += __shfl_xor_sync(0xFFFFFFFFu, q, o);
    }
    __shared__ float rs[8], rq[8];
    int w = t >> 5, lane = t & 31;
    if (lane == 0) { rs[w] = s; rq[w] = q; }
    __syncthreads();
    __shared__ float smean, srstd;
    if (t == 0) {
        float ts = 0.f, tq = 0.f;
        for (int i = 0; i < 8; i++) { ts += rs[i]; tq += rq[i]; }
        float mean = ts * (1.0f / HID);
        float var  = tq * (1.0f / HID) - mean * mean;
        smean = mean;
        srstd = rsqrtf(var + EPS);
    }
    __syncthreads();
    float mean = smean, rstd = srstd;
    float y0 = (v0 - mean) * rstd * g[t]       + b[t];
    float y1 = (v1 - mean) * rstd * g[t + 256] + b[t + 256];
    out[row * HID + t]       = fmaxf(y0, 0.f);
    out[row * HID + t + 256] = fmaxf(y1, 0.f);
}

// ---------------- row softmax over C=512 (in place) ----------------
__global__ void softmax_kernel(float* __restrict__ dots) {
    size_t row = (size_t)blockIdx.x;
    float* p = dots + row * C_COMM;
    int t = threadIdx.x;                 // 256
    float v0 = p[t], v1 = p[t + 256];
    float m = fmaxf(v0, v1);
    for (int o = 16; o; o >>= 1) m = fmaxf(m, __shfl_xor_sync(0xFFFFFFFFu, m, o));
    __shared__ float rm[8];
    int w = t >> 5, lane = t & 31;
    if (lane == 0) rm[w] = m;
    __syncthreads();
    __shared__ float smax;
    if (t == 0) {
        float mm = rm[0];
        for (int i = 1; i < 8; i++) mm = fmaxf(mm, rm[i]);
        smax = mm;
    }
    __syncthreads();
    m = smax;
    float e0 = __expf(v0 - m), e1 = __expf(v1 - m);
    float s = e0 + e1;
    for (int o = 16; o; o >>= 1) s += __shfl_xor_sync(0xFFFFFFFFu, s, o);
    __shared__ float rsum[8];
    if (lane == 0) rsum[w] = s;
    __syncthreads();
    __shared__ float stot;
    if (t == 0) {
        float ts = 0.f;
        for (int i = 0; i < 8; i++) ts += rsum[i];
        stot = ts;
    }
    __syncthreads();
    float inv = 1.0f / stot;
    p[t]       = e0 * inv;
    p[t + 256] = e1 * inv;
}

// ---------------- generic tiled SGEMM ----------------
// EPI==0: C = A@B + bias (NN; bias may be null)
// EPI==1: C = (A@B^T)*scale + logc[col] + table[dm[row*dmld+col]]   (NT, dots)
// blockIdx.z selects a "head": A += z*zsA, B += z*zsB, C += z*zsC (element offsets)
template<int BM, int BN, int BK, int TM, int TN, int EPI>
__global__ __launch_bounds__((BM / TM) * (BN / TN))
void gemm_kernel(int M, int Nc, int K,
                 const float* __restrict__ A, int lda, size_t zsA,
                 const float* __restrict__ B, int ldb, size_t zsB,
                 const float* __restrict__ bias,
                 float* __restrict__ Cm, int ldc, size_t zsC,
                 float scale,
                 const float* __restrict__ logc,
                 const float* __restrict__ table,
                 const int* __restrict__ dm, int dmld)
{
    constexpr int TX  = BN / TN;
    constexpr int TY  = BM / TM;
    constexpr int NTH = TX * TY;
    __shared__ float As[BK][BM + 4];
    __shared__ float Bs[BK][BN + 4];

    A  += (size_t)blockIdx.z * zsA;
    B  += (size_t)blockIdx.z * zsB;
    Cm += (size_t)blockIdx.z * zsC;

    int t  = threadIdx.x;
    int tx = t % TX, ty = t / TX;
    int bm0 = blockIdx.y * BM, bn0 = blockIdx.x * BN;
    const float* Ab = A + (size_t)bm0 * lda;

    float acc[TM][TN];
    #pragma unroll
    for (int i = 0; i < TM; i++)
        #pragma unroll
        for (int j = 0; j < TN; j++) acc[i][j] = 0.f;

    for (int k0 = 0; k0 < K; k0 += BK) {
        for (int i = t; i < BM * BK / 4; i += NTH) {
            int arow = i / (BK / 4);
            int ac   = (i % (BK / 4)) * 4;
            float4 va = *reinterpret_cast<const float4*>(Ab + (size_t)arow * lda + k0 + ac);
            As[ac + 0][arow] = va.x; As[ac + 1][arow] = va.y;
            As[ac + 2][arow] = va.z; As[ac + 3][arow] = va.w;
        }
        if (EPI == 1) {
            for (int i = t; i < BN * BK / 4; i += NTH) {
                int n  = i / (BK / 4);
                int kc = (i % (BK / 4)) * 4;
                float4 vb = *reinterpret_cast<const float4*>(B + (size_t)(bn0 + n) * ldb + k0 + kc);
                Bs[kc + 0][n] = vb.x; Bs[kc + 1][n] = vb.y;
                Bs[kc + 2][n] = vb.z; Bs[kc + 3][n] = vb.w;
            }
        } else {
            for (int i = t; i < BN * BK / 4; i += NTH) {
                int kr = i / (BN / 4);
                int nc = (i % (BN / 4)) * 4;
                float4 vb = *reinterpret_cast<const float4*>(B + (size_t)(k0 + kr) * ldb + bn0 + nc);
                *reinterpret_cast<float4*>(&Bs[kr][nc]) = vb;
            }
        }
        __syncthreads();
        #pragma unroll
        for (int k = 0; k < BK; k++) {
            float ra[TM], rb[TN];
            #pragma unroll
            for (int i = 0; i < TM; i++) ra[i] = As[k][ty * TM + i];
            #pragma unroll
            for (int j = 0; j < TN; j++) rb[j] = Bs[k][tx * TN + j];
            #pragma unroll
            for (int i = 0; i < TM; i++)
                #pragma unroll
                for (int j = 0; j < TN; j++)
                    acc[i][j] = fmaf(ra[i], rb[j], acc[i][j]);
        }
        __syncthreads();
    }

    #pragma unroll
    for (int i = 0; i < TM; i++) {
        int gm = bm0 + ty * TM + i;
        #pragma unroll
        for (int j = 0; j < TN; j++) {
            int gn = bn0 + tx * TN + j;
            float v = acc[i][j];
            if (EPI == 0) {
                if (bias) v += bias[gn];
            } else {
                v = v * scale + logc[gn] + table[dm[(size_t)gm * dmld + gn]];
            }
            Cm[(size_t)gm * ldc + gn] = v;
        }
    }
}

// ---------------- host-side launch helpers ----------------
static void gemm_nn(int M, int Nc, int K,
                    const float* A, int lda, const float* B, int ldb,
                    const float* bias, float* Cm, int ldc)
{
    if (Nc % 128 == 0) {
        dim3 g(Nc / 128, M / 128, 1);
        gemm_kernel<128, 128, 8, 8, 8, 0><<<g, 256>>>(M, Nc, K, A, lda, 0, B, ldb, 0,
                                                      bias, Cm, ldc, 0,
                                                      0.f, nullptr, nullptr, nullptr, 0);
    } else {  // Nc == 64
        dim3 g(Nc / 64, M / 128, 1);
        gemm_kernel<128, 64, 8, 8, 4, 0><<<g, 256>>>(M, Nc, K, A, lda, 0, B, ldb, 0,
                                                     bias, Cm, ldc, 0,
                                                     0.f, nullptr, nullptr, nullptr, 0);
    }
}

extern "C" void kernel_launch(void* const* d_in, const int* in_sizes, int n_in,
                              void* d_out, int out_size)
{
    // ---- input mapping (auto-detect metadata order) ----
    const float *x      = (const float*)d_in[0];
    const int   *dm     = (const int*)  d_in[1];
    const int   *ntc    = (const int*)  d_in[2];
    const float *W_in1  = (const float*)d_in[3];
    const float *b_in1  = (const float*)d_in[4];
    const float *ln_in_g= (const float*)d_in[5];
    const float *ln_in_b= (const float*)d_in[6];
    const float *W_in2  = (const float*)d_in[7];
    const float *b_in2  = (const float*)d_in[8];
    const float *Wproj, *Wq, *Wk, *Wv, *ffW1, *ffW2;
    const float *bproj, *bq, *bk, *bv, *ffb1, *ffb2;
    const float *dis_emb, *dis_w, *dis_b;
    const float *ffg1, *ffbeta1, *ffg2, *ffbeta2, *Wout, *bout;

    if (in_sizes[10] == NLAYER * HID * HID) {
        // setup_inputs dict order
        Wproj  = (const float*)d_in[9];  Wq     = (const float*)d_in[10];
        Wk     = (const float*)d_in[11]; Wv     = (const float*)d_in[12];
        ffW1   = (const float*)d_in[13]; ffW2   = (const float*)d_in[14];
        bproj  = (const float*)d_in[15]; bq     = (const float*)d_in[16];
        bk     = (const float*)d_in[17]; bv     = (const float*)d_in[18];
        ffb1   = (const float*)d_in[19]; ffb2   = (const float*)d_in[20];
        dis_emb= (const float*)d_in[21]; dis_w  = (const float*)d_in[22];
        dis_b  = (const float*)d_in[23];
        ffg1   = (const float*)d_in[24]; ffbeta1= (const float*)d_in[25];
        ffg2   = (const float*)d_in[26]; ffbeta2= (const float*)d_in[27];
        Wout   = (const float*)d_in[28]; bout   = (const float*)d_in[29];
    } else {
        // reference() signature order
        Wproj  = (const float*)d_in[9];  bproj  = (const float*)d_in[10];
        Wq     = (const float*)d_in[11]; bq     = (const float*)d_in[12];
        Wk     = (const float*)d_in[13]; bk     = (const float*)d_in[14];
        Wv     = (const float*)d_in[15]; bv     = (const float*)d_in[16];
        dis_emb= (const float*)d_in[17]; dis_w  = (const float*)d_in[18];
        dis_b  = (const float*)d_in[19];
        ffW1   = (const float*)d_in[20]; ffb1   = (const float*)d_in[21];
        ffg1   = (const float*)d_in[22]; ffbeta1= (const float*)d_in[23];
        ffW2   = (const float*)d_in[24]; ffb2   = (const float*)d_in[25];
        ffg2   = (const float*)d_in[26]; ffbeta2= (const float*)d_in[27];
        Wout   = (const float*)d_in[28]; bout   = (const float*)d_in[29];
    }

    // ---- scratch pointers ----
    float *p_h, *p_t0, *p_t1, *p_q, *p_dots, *p_comm, *p_k, *p_v, *p_logc, *p_table;
    cudaGetSymbolAddress((void**)&p_h,     g_h);
    cudaGetSymbolAddress((void**)&p_t0,    g_t0);
    cudaGetSymbolAddress((void**)&p_t1,    g_t1);
    cudaGetSymbolAddress((void**)&p_q,     g_q);
    cudaGetSymbolAddress((void**)&p_dots,  g_dots);
    cudaGetSymbolAddress((void**)&p_comm,  g_comm);
    cudaGetSymbolAddress((void**)&p_k,     g_k);
    cudaGetSymbolAddress((void**)&p_v,     g_v);
    cudaGetSymbolAddress((void**)&p_logc,  g_logc);
    cudaGetSymbolAddress((void**)&p_table, g_table);

    const float scale = 1.0f / sqrtf((float)DHEAD);

    // ---- community preprocessing (deterministic) ----
    hist_kernel      <<<NCHUNK, CHUNK>>>(ntc);
    chunk_scan_kernel<<<C_COMM, NCHUNK>>>();
    offsets_kernel   <<<1, C_COMM>>>();
    scatter_kernel   <<<NCHUNK, CHUNK>>>(ntc);

    // ---- fc_in ----
    gemm_nn(N_NODES, HID, IN_DIM, x, IN_DIM, W_in1, HID, b_in1, p_t0, HID);
    ln_relu_kernel<<<N_NODES, 256>>>(p_t0, p_t0, ln_in_g, ln_in_b);
    gemm_nn(N_NODES, HID, HID, p_t0, HID, W_in2, HID, b_in2, p_h, HID);

    // ---- layers ----
    for (int l = 0; l < NLAYER; l++) {
        bias_table_kernel<<<NDIST, 128>>>(dis_emb + (size_t)l * NDIST * HID,
                                          dis_w + (size_t)l * HID, dis_b + l);
        comm_avg_kernel<<<C_COMM, 256>>>();

        gemm_nn(N_NODES, HID, HID, p_h,  HID, Wproj + (size_t)l * HID * HID, HID,
                bproj + (size_t)l * HID, p_t0, HID);
        gemm_nn(N_NODES, HID, HID, p_t0, HID, Wq + (size_t)l * HID * HID, HID,
                bq + (size_t)l * HID, p_q, HID);
        gemm_nn(C_COMM, HID, HID, p_comm, HID, Wk + (size_t)l * HID * HID, HID,
                bk + (size_t)l * HID, p_k, HID);
        gemm_nn(C_COMM, HID, HID, p_comm, HID, Wv + (size_t)l * HID * HID, HID,
                bv + (size_t)l * HID, p_v, HID);

        // dots: all 4 heads in one launch (z = head)
        {
            dim3 g(C_COMM / 128, N_NODES / 128, NHEAD);
            gemm_kernel<128, 128, 8, 8, 8, 1><<<g, 256>>>(
                N_NODES, C_COMM, DHEAD,
                p_q, HID, (size_t)DHEAD,
                p_k, HID, (size_t)DHEAD,
                nullptr,
                p_dots, C_COMM, (size_t)N_NODES * C_COMM,
                scale, p_logc, p_table, dm, C_COMM);
        }
        softmax_kernel<<<NHEAD * N_NODES, 256>>>(p_dots);
        // AV: all 4 heads in one launch (z = head)
        {
            dim3 g(DHEAD / 128, N_NODES / 128, NHEAD);
            gemm_kernel<128, 128, 8, 8, 8, 0><<<g, 256>>>(
                N_NODES, DHEAD, C_COMM,
                p_dots, C_COMM, (size_t)N_NODES * C_COMM,
                p_v, HID, (size_t)DHEAD,
                nullptr,
                p_t0, HID, (size_t)DHEAD,
                0.f, nullptr, nullptr, nullptr, 0);
        }

        gemm_nn(N_NODES, HID, HID, p_t0, HID, ffW1 + (size_t)l * HID * HID, HID,
                ffb1 + (size_t)l * HID, p_t1, HID);
        ln_relu_kernel<<<N_NODES, 256>>>(p_t1, p_t1, ffg1 + (size_t)l * HID,
                                         ffbeta1 + (size_t)l * HID);
        gemm_nn(N_NODES, HID, HID, p_t1, HID, ffW2 + (size_t)l * HID * HID, HID,
                ffb2 + (size_t)l * HID, p_q, HID);
        ln_relu_kernel<<<N_NODES, 256>>>(p_q, p_h, ffg2 + (size_t)l * HID,
                                         ffbeta2 + (size_t)l * HID);
    }

    // ---- output projection ----
    gemm_nn(N_NODES, OUT_DIM, HID, p_h, HID, Wout, OUT_DIM, bout, (float*)d_out, OUT_DIM);
}

// round 5
// speedup vs baseline: 1.8496x; 1.8496x over previous
#include <cuda_runtime.h>
#include <cuda_bf16.h>
#include <math.h>
#include <stdint.h>

// ---------------- problem constants ----------------
#define N_NODES 32768
#define C_COMM  512
#define IN_DIM  128
#define HID     512
#define NHEAD   4
#define DHEAD   128
#define NLAYER  2
#define OUT_DIM 64
#define NDIST   31
#define EPS     1e-5f

#define CHUNK   256
#define NCHUNK  (N_NODES / CHUNK)   // 128

// ---------------- scratch (device globals; no allocation allowed) ----------------
__device__ float g_h   [N_NODES * HID];
__device__ float g_t0  [N_NODES * HID];
__device__ float g_t1  [N_NODES * HID];
__device__ float g_q   [N_NODES * HID];
__device__ float g_dots[(size_t)NHEAD * N_NODES * C_COMM];
__device__ float g_comm[C_COMM * HID];
__device__ float g_k   [C_COMM * HID];
__device__ float g_v   [C_COMM * HID];
__device__ float g_wt  [16][HID * HID];   // transposed weights + vT scratch
__device__ int   g_hist     [NCHUNK * C_COMM];
__device__ int   g_chunkbase[NCHUNK * C_COMM];
__device__ int   g_counts [C_COMM];
__device__ int   g_offsets[C_COMM];
__device__ int   g_members[N_NODES];
__device__ float g_logc[C_COMM];
__device__ float g_inv [C_COMM];
__device__ float g_table[NDIST];

// ---------------- small PTX helpers (all sm_80-compatible) ----------------
__device__ __forceinline__ uint32_t smem_u32(const void* p) {
    uint32_t a;
    asm("{ .reg .u64 t; cvta.to.shared.u64 t, %1; cvt.u32.u64 %0, t; }" : "=r"(a) : "l"(p));
    return a;
}

__device__ __forceinline__ void ldm4(uint32_t* r, uint32_t addr) {
    asm volatile("ldmatrix.sync.aligned.m8n8.x4.shared.b16 {%0,%1,%2,%3}, [%4];"
                 : "=r"(r[0]), "=r"(r[1]), "=r"(r[2]), "=r"(r[3]) : "r"(addr));
}

__device__ __forceinline__ void mma_bf16(float* d, const uint32_t* a, const uint32_t* b) {
    asm volatile(
        "mma.sync.aligned.m16n8k16.row.col.f32.bf16.bf16.f32 "
        "{%0,%1,%2,%3}, {%4,%5,%6,%7}, {%8,%9}, {%0,%1,%2,%3};"
        : "+f"(d[0]), "+f"(d[1]), "+f"(d[2]), "+f"(d[3])
        : "r"(a[0]), "r"(a[1]), "r"(a[2]), "r"(a[3]), "r"(b[0]), "r"(b[1]));
}

// split fp32x4 -> bf16 hi quad + bf16 lo quad (each uint2 = 4 bf16)
__device__ __forceinline__ void split4(float4 v, uint2& H, uint2& L) {
    __nv_bfloat16 hx = __float2bfloat16(v.x), hy = __float2bfloat16(v.y);
    __nv_bfloat16 hz = __float2bfloat16(v.z), hw = __float2bfloat16(v.w);
    H.x = (uint32_t)__bfloat16_as_ushort(hx) | ((uint32_t)__bfloat16_as_ushort(hy) << 16);
    H.y = (uint32_t)__bfloat16_as_ushort(hz) | ((uint32_t)__bfloat16_as_ushort(hw) << 16);
    __nv_bfloat16 lx = __float2bfloat16(v.x - __bfloat162float(hx));
    __nv_bfloat16 ly = __float2bfloat16(v.y - __bfloat162float(hy));
    __nv_bfloat16 lz = __float2bfloat16(v.z - __bfloat162float(hz));
    __nv_bfloat16 lw = __float2bfloat16(v.w - __bfloat162float(hw));
    L.x = (uint32_t)__bfloat16_as_ushort(lx) | ((uint32_t)__bfloat16_as_ushort(ly) << 16);
    L.y = (uint32_t)__bfloat16_as_ushort(lz) | ((uint32_t)__bfloat16_as_ushort(lw) << 16);
}

// ---------------- warp-MMA GEMM: C[M,N] = A[M,K] . B[N,K]^T  (fp32 in/out) ----------------
// EPI==0: + bias (optional).  EPI==1: *scale + logc[col] + table[dm[row,col]]
// blockIdx.z offsets: A += z*zsA, B += z*zsB, C += z*zsC.
// Requires M%128==0, Ncols == gridDim.x*BN, K%32==0, 16B-aligned rows.
template<int BN, int EPI>
__global__ __launch_bounds__(256, 1)
void mma_gemm(int M, int K,
              const float* __restrict__ A, int lda, size_t zsA,
              const float* __restrict__ B, int ldb, size_t zsB,
              const float* __restrict__ bias,
              float* __restrict__ Cm, int ldc, size_t zsC,
              float scale, const float* __restrict__ logc,
              const float* __restrict__ table,
              const int* __restrict__ dm, int dmld)
{
    constexpr int BM  = 128, BK = 32;
    constexpr int LDS = 40;                  // bf16 elems/row (32 + 8 pad -> 80B stride)
    constexpr int NW_N = BN / 32;            // warps along n
    constexpr int NW_M = 8 / NW_N;           // warps along m
    constexpr int WM  = BM / NW_M;           // warp m-tile
    constexpr int MI  = WM / 16;             // m16 tiles per warp
    constexpr int NA  = BM * (BK / 4) / 256; // float4 per thread (A) = 4
    constexpr int NB  = BN * (BK / 4) / 256; // float4 per thread (B)

    __shared__ __nv_bfloat16 Ah[BM * LDS], Al[BM * LDS];
    __shared__ __nv_bfloat16 Bh[BN * LDS], Bl[BN * LDS];

    A  += (size_t)blockIdx.z * zsA;
    B  += (size_t)blockIdx.z * zsB;
    Cm += (size_t)blockIdx.z * zsC;
    const int m0 = blockIdx.y * BM, n0 = blockIdx.x * BN;
    const int tid = threadIdx.x, lane = tid & 31, wid = tid >> 5;
    const int wm = wid % NW_M, wn = wid / NW_M;
    const int mbase = wm * WM, nbase = wn * 32;

    const uint32_t uAh = smem_u32(Ah), uAl = smem_u32(Al);
    const uint32_t uBh = smem_u32(Bh), uBl = smem_u32(Bl);
    const int lr = lane & 15, lc8 = (lane >> 4) * 8;

    float acc[MI][4][4];
    #pragma unroll
    for (int mi = 0; mi < MI; ++mi)
        #pragma unroll
        for (int ni = 0; ni < 4; ++ni)
            #pragma unroll
            for (int q = 0; q < 4; ++q) acc[mi][ni][q] = 0.f;

    float4 pa[NA], pb[NB];
    // prologue: load chunk 0
    #pragma unroll
    for (int t = 0; t < NA; ++t) {
        int j = tid + t * 256, r = j >> 3, c = j & 7;
        pa[t] = *reinterpret_cast<const float4*>(A + (size_t)(m0 + r) * lda + c * 4);
    }
    #pragma unroll
    for (int t = 0; t < NB; ++t) {
        int j = tid + t * 256, r = j >> 3, c = j & 7;
        pb[t] = *reinterpret_cast<const float4*>(B + (size_t)(n0 + r) * ldb + c * 4);
    }

    const int nch = K >> 5;
    for (int ch = 0; ch < nch; ++ch) {
        // split + store to smem
        #pragma unroll
        for (int t = 0; t < NA; ++t) {
            int j = tid + t * 256, r = j >> 3, c = j & 7;
            uint2 H, L; split4(pa[t], H, L);
            *reinterpret_cast<uint2*>(&Ah[r * LDS + c * 4]) = H;
            *reinterpret_cast<uint2*>(&Al[r * LDS + c * 4]) = L;
        }
        #pragma unroll
        for (int t = 0; t < NB; ++t) {
            int j = tid + t * 256, r = j >> 3, c = j & 7;
            uint2 H, L; split4(pb[t], H, L);
            *reinterpret_cast<uint2*>(&Bh[r * LDS + c * 4]) = H;
            *reinterpret_cast<uint2*>(&Bl[r * LDS + c * 4]) = L;
        }
        __syncthreads();

        // prefetch next chunk (overlaps with MMA below)
        if (ch + 1 < nch) {
            int k0 = (ch + 1) << 5;
            #pragma unroll
            for (int t = 0; t < NA; ++t) {
                int j = tid + t * 256, r = j >> 3, c = j & 7;
                pa[t] = *reinterpret_cast<const float4*>(A + (size_t)(m0 + r) * lda + k0 + c * 4);
            }
            #pragma unroll
            for (int t = 0; t < NB; ++t) {
                int j = tid + t * 256, r = j >> 3, c = j & 7;
                pb[t] = *reinterpret_cast<const float4*>(B + (size_t)(n0 + r) * ldb + k0 + c * 4);
            }
        }

        // MMA on current tile
        #pragma unroll
        for (int ks = 0; ks < 2; ++ks) {
            uint32_t ah[MI][4], al[MI][4];
            #pragma unroll
            for (int mi = 0; mi < MI; ++mi) {
                uint32_t off = (uint32_t)((mbase + mi * 16 + lr) * LDS + ks * 16 + lc8) * 2;
                ldm4(ah[mi], uAh + off);
                ldm4(al[mi], uAl + off);
            }
            uint32_t bh[4][2], bl[4][2], r[4];
            uint32_t off0 = (uint32_t)((nbase + lr) * LDS + ks * 16 + lc8) * 2;
            uint32_t off1 = (uint32_t)((nbase + 16 + lr) * LDS + ks * 16 + lc8) * 2;
            ldm4(r, uBh + off0); bh[0][0] = r[0]; bh[0][1] = r[2]; bh[1][0] = r[1]; bh[1][1] = r[3];
            ldm4(r, uBh + off1); bh[2][0] = r[0]; bh[2][1] = r[2]; bh[3][0] = r[1]; bh[3][1] = r[3];
            ldm4(r, uBl + off0); bl[0][0] = r[0]; bl[0][1] = r[2]; bl[1][0] = r[1]; bl[1][1] = r[3];
            ldm4(r, uBl + off1); bl[2][0] = r[0]; bl[2][1] = r[2]; bl[3][0] = r[1]; bl[3][1] = r[3];
            #pragma unroll
            for (int mi = 0; mi < MI; ++mi)
                #pragma unroll
                for (int ni = 0; ni < 4; ++ni) {
                    mma_bf16(acc[mi][ni], ah[mi], bh[ni]);
                    mma_bf16(acc[mi][ni], ah[mi], bl[ni]);
                    mma_bf16(acc[mi][ni], al[mi], bh[ni]);
                }
        }
        __syncthreads();
    }

    // epilogue
    #pragma unroll
    for (int mi = 0; mi < MI; ++mi) {
        int r0 = m0 + mbase + mi * 16 + (lane >> 2);
        #pragma unroll
        for (int ni = 0; ni < 4; ++ni) {
            int cc = n0 + nbase + ni * 8 + (lane & 3) * 2;
            float d0 = acc[mi][ni][0], d1 = acc[mi][ni][1];
            float d2 = acc[mi][ni][2], d3 = acc[mi][ni][3];
            if (EPI == 0) {
                if (bias) {
                    float b0 = bias[cc], b1 = bias[cc + 1];
                    d0 += b0; d1 += b1; d2 += b0; d3 += b1;
                }
            } else {
                float lg0 = logc[cc], lg1 = logc[cc + 1];
                int e0 = dm[(size_t)r0 * dmld + cc],       e1 = dm[(size_t)r0 * dmld + cc + 1];
                int e2 = dm[(size_t)(r0 + 8) * dmld + cc], e3 = dm[(size_t)(r0 + 8) * dmld + cc + 1];
                d0 = d0 * scale + lg0 + table[e0];
                d1 = d1 * scale + lg1 + table[e1];
                d2 = d2 * scale + lg0 + table[e2];
                d3 = d3 * scale + lg1 + table[e3];
            }
            float2 lo = make_float2(d0, d1), hi = make_float2(d2, d3);
            *reinterpret_cast<float2*>(Cm + (size_t)r0 * ldc + cc)       = lo;
            *reinterpret_cast<float2*>(Cm + (size_t)(r0 + 8) * ldc + cc) = hi;
        }
    }
}

// ---------------- fp32 transpose: out[C,R] = in[R,C]^T ----------------
__global__ void transpose_kernel(const float* __restrict__ in, float* __restrict__ out,
                                 int R, int Ccols) {
    __shared__ float tile[32][33];
    int c0 = blockIdx.x * 32, r0 = blockIdx.y * 32;
    int x = threadIdx.x, y = threadIdx.y;           // 32 x 8
    #pragma unroll
    for (int j = 0; j < 32; j += 8)
        tile[y + j][x] = in[(size_t)(r0 + y + j) * Ccols + c0 + x];
    __syncthreads();
    #pragma unroll
    for (int j = 0; j < 32; j += 8)
        out[(size_t)(c0 + y + j) * R + r0 + x] = tile[x][y + j];
}

// ---------------- community preprocessing (deterministic, stable) ----------------
__global__ void hist_kernel(const int* __restrict__ ntc) {
    __shared__ int sh[C_COMM];
    int chunk = blockIdx.x;
    for (int i = threadIdx.x; i < C_COMM; i += blockDim.x) sh[i] = 0;
    __syncthreads();
    int node = chunk * CHUNK + threadIdx.x;
    atomicAdd(&sh[ntc[node]], 1);
    __syncthreads();
    for (int i = threadIdx.x; i < C_COMM; i += blockDim.x)
        g_hist[chunk * C_COMM + i] = sh[i];
}

__global__ void chunk_scan_kernel() {
    int c = blockIdx.x;
    __shared__ int s[NCHUNK];
    int t = threadIdx.x;
    int own = g_hist[t * C_COMM + c];
    s[t] = own;
    __syncthreads();
    for (int off = 1; off < NCHUNK; off <<= 1) {
        int v = (t >= off) ? s[t - off] : 0;
        __syncthreads();
        s[t] += v;
        __syncthreads();
    }
    g_chunkbase[t * C_COMM + c] = s[t] - own;
    if (t == NCHUNK - 1) g_counts[c] = s[t];
}

__global__ void offsets_kernel() {
    __shared__ int s[C_COMM];
    int t = threadIdx.x;
    int own = g_counts[t];
    s[t] = own;
    __syncthreads();
    for (int off = 1; off < C_COMM; off <<= 1) {
        int v = (t >= off) ? s[t - off] : 0;
        __syncthreads();
        s[t] += v;
        __syncthreads();
    }
    g_offsets[t] = s[t] - own;
    g_logc[t]    = logf((float)own);
    g_inv[t]     = 1.0f / (float)(own > 0 ? own : 1);
}

__global__ void scatter_kernel(const int* __restrict__ ntc) {
    __shared__ int s[CHUNK];
    int chunk = blockIdx.x;
    int t = threadIdx.x;
    int node = chunk * CHUNK + t;
    int c = ntc[node];
    s[t] = c;
    __syncthreads();
    int lrank = 0;
    for (int j = 0; j < t; j++) lrank += (s[j] == c);
    g_members[g_offsets[c] + g_chunkbase[chunk * C_COMM + c] + lrank] = node;
}

__global__ void comm_avg_kernel() {
    int c = blockIdx.x;
    int t = threadIdx.x;
    int off = g_offsets[c], cnt = g_counts[c];
    float a0 = 0.f, a1 = 0.f;
    for (int m = 0; m < cnt; m++) {
        const float* row = g_h + (size_t)g_members[off + m] * HID;
        a0 += row[t];
        a1 += row[t + 256];
    }
    float inv = g_inv[c];
    g_comm[c * HID + t]       = a0 * inv;
    g_comm[c * HID + t + 256] = a1 * inv;
}

__global__ void bias_table_kernel(const float* __restrict__ emb,
                                  const float* __restrict__ w,
                                  const float* __restrict__ bptr) {
    int i = blockIdx.x;
    int t = threadIdx.x;
    float s = emb[i * HID + t]       * w[t]
            + emb[i * HID + t + 128] * w[t + 128]
            + emb[i * HID + t + 256] * w[t + 256]
            + emb[i * HID + t + 384] * w[t + 384];
    for (int o = 16; o; o >>= 1) s += __shfl_xor_sync(0xFFFFFFFFu, s, o);
    __shared__ float r[4];
    if ((t & 31) == 0) r[t >> 5] = s;
    __syncthreads();
    if (t == 0) g_table[i] = r[0] + r[1] + r[2] + r[3] + bptr[0];
}

__global__ void ln_relu_kernel(const float* __restrict__ in, float* __restrict__ out,
                               const float* __restrict__ g, const float* __restrict__ b) {
    size_t row = blockIdx.x;
    int t = threadIdx.x;
    const float* x = in + row * HID;
    float v0 = x[t], v1 = x[t + 256];
    float s = v0 + v1, q = v0 * v0 + v1 * v1;
    for (int o = 16; o; o >>= 1) {
        s += __shfl_xor_sync(0xFFFFFFFFu, s, o);
        q += __shfl_xor_sync(0xFFFFFFFFu, q, o);
    }
    __shared__ float rs[8], rq[8];
    int w = t >> 5, lane = t & 31;
    if (lane == 0) { rs[w] = s; rq[w] = q; }
    __syncthreads();
    __shared__ float smean, srstd;
    if (t == 0) {
        float ts = 0.f, tq = 0.f;
        for (int i = 0; i < 8; i++) { ts += rs[i]; tq += rq[i]; }
        float mean = ts * (1.0f / HID);
        float var  = tq * (1.0f / HID) - mean * mean;
        smean = mean;
        srstd = rsqrtf(var + EPS);
    }
    __syncthreads();
    float mean = smean, rstd = srstd;
    float y0 = (v0 - mean) * rstd * g[t]       + b[t];
    float y1 = (v1 - mean) * rstd * g[t + 256] + b[t + 256];
    out[row * HID + t]       = fmaxf(y0, 0.f);
    out[row * HID + t + 256] = fmaxf(y1, 0.f);
}

__global__ void softmax_kernel(float* __restrict__ dots) {
    size_t row = (size_t)blockIdx.x;
    float* p = dots + row * C_COMM;
    int t = threadIdx.x;
    float v0 = p[t], v1 = p[t + 256];
    float m = fmaxf(v0, v1);
    for (int o = 16; o; o >>= 1) m = fmaxf(m, __shfl_xor_sync(0xFFFFFFFFu, m, o));
    __shared__ float rm[8];
    int w = t >> 5, lane = t & 31;
    if (lane == 0) rm[w] = m;
    __syncthreads();
    __shared__ float smax;
    if (t == 0) {
        float mm = rm[0];
        for (int i = 1; i < 8; i++) mm = fmaxf(mm, rm[i]);
        smax = mm;
    }
    __syncthreads();
    m = smax;
    float e0 = __expf(v0 - m), e1 = __expf(v1 - m);
    float s = e0 + e1;
    for (int o = 16; o; o >>= 1) s += __shfl_xor_sync(0xFFFFFFFFu, s, o);
    __shared__ float rsum[8];
    if (lane == 0) rsum[w] = s;
    __syncthreads();
    __shared__ float stot;
    if (t == 0) {
        float ts = 0.f;
        for (int i = 0; i < 8; i++) ts += rsum[i];
        stot = ts;
    }
    __syncthreads();
    float inv = 1.0f / stot;
    p[t]       = e0 * inv;
    p[t + 256] = e1 * inv;
}

// ---------------- host-side helpers ----------------
// C[M,N] = A[M,K] @ Bt[N,K]^T + bias  (Bt pre-transposed, K-major)
static void tc_nn(int M, int Nc, int K,
                  const float* A, int lda, const float* Bt,
                  const float* bias, float* Cm, int ldc)
{
    if (Nc % 128 == 0) {
        dim3 g(Nc / 128, M / 128, 1);
        mma_gemm<128, 0><<<g, 256>>>(M, K, A, lda, 0, Bt, K, 0,
                                     bias, Cm, ldc, 0,
                                     0.f, nullptr, nullptr, nullptr, 0);
    } else { // Nc == 64
        dim3 g(1, M / 128, 1);
        mma_gemm<64, 0><<<g, 256>>>(M, K, A, lda, 0, Bt, K, 0,
                                    bias, Cm, ldc, 0,
                                    0.f, nullptr, nullptr, nullptr, 0);
    }
}

static void do_transpose(const float* in, float* out, int R, int C) {
    dim3 g(C / 32, R / 32), b(32, 8);
    transpose_kernel<<<g, b>>>(in, out, R, C);
}

extern "C" void kernel_launch(void* const* d_in, const int* in_sizes, int n_in,
                              void* d_out, int out_size)
{
    // ---- input mapping (auto-detect metadata order) ----
    const float *x      = (const float*)d_in[0];
    const int   *dm     = (const int*)  d_in[1];
    const int   *ntc    = (const int*)  d_in[2];
    const float *W_in1  = (const float*)d_in[3];
    const float *b_in1  = (const float*)d_in[4];
    const float *ln_in_g= (const float*)d_in[5];
    const float *ln_in_b= (const float*)d_in[6];
    const float *W_in2  = (const float*)d_in[7];
    const float *b_in2  = (const float*)d_in[8];
    const float *Wproj, *Wq, *Wk, *Wv, *ffW1, *ffW2;
    const float *bproj, *bq, *bk, *bv, *ffb1, *ffb2;
    const float *dis_emb, *dis_w, *dis_b;
    const float *ffg1, *ffbeta1, *ffg2, *ffbeta2, *Wout, *bout;

    if (in_sizes[10] == NLAYER * HID * HID) {
        Wproj  = (const float*)d_in[9];  Wq     = (const float*)d_in[10];
        Wk     = (const float*)d_in[11]; Wv     = (const float*)d_in[12];
        ffW1   = (const float*)d_in[13]; ffW2   = (const float*)d_in[14];
        bproj  = (const float*)d_in[15]; bq     = (const float*)d_in[16];
        bk     = (const float*)d_in[17]; bv     = (const float*)d_in[18];
        ffb1   = (const float*)d_in[19]; ffb2   = (const float*)d_in[20];
        dis_emb= (const float*)d_in[21]; dis_w  = (const float*)d_in[22];
        dis_b  = (const float*)d_in[23];
        ffg1   = (const float*)d_in[24]; ffbeta1= (const float*)d_in[25];
        ffg2   = (const float*)d_in[26]; ffbeta2= (const float*)d_in[27];
        Wout   = (const float*)d_in[28]; bout   = (const float*)d_in[29];
    } else {
        Wproj  = (const float*)d_in[9];  bproj  = (const float*)d_in[10];
        Wq     = (const float*)d_in[11]; bq     = (const float*)d_in[12];
        Wk     = (const float*)d_in[13]; bk     = (const float*)d_in[14];
        Wv     = (const float*)d_in[15]; bv     = (const float*)d_in[16];
        dis_emb= (const float*)d_in[17]; dis_w  = (const float*)d_in[18];
        dis_b  = (const float*)d_in[19];
        ffW1   = (const float*)d_in[20]; ffb1   = (const float*)d_in[21];
        ffg1   = (const float*)d_in[22]; ffbeta1= (const float*)d_in[23];
        ffW2   = (const float*)d_in[24]; ffb2   = (const float*)d_in[25];
        ffg2   = (const float*)d_in[26]; ffbeta2= (const float*)d_in[27];
        Wout   = (const float*)d_in[28]; bout   = (const float*)d_in[29];
    }

    // ---- scratch pointers ----
    float *p_h, *p_t0, *p_t1, *p_q, *p_dots, *p_comm, *p_k, *p_v, *p_logc, *p_table, *p_wt;
    cudaGetSymbolAddress((void**)&p_h,     g_h);
    cudaGetSymbolAddress((void**)&p_t0,    g_t0);
    cudaGetSymbolAddress((void**)&p_t1,    g_t1);
    cudaGetSymbolAddress((void**)&p_q,     g_q);
    cudaGetSymbolAddress((void**)&p_dots,  g_dots);
    cudaGetSymbolAddress((void**)&p_comm,  g_comm);
    cudaGetSymbolAddress((void**)&p_k,     g_k);
    cudaGetSymbolAddress((void**)&p_v,     g_v);
    cudaGetSymbolAddress((void**)&p_logc,  g_logc);
    cudaGetSymbolAddress((void**)&p_table, g_table);
    cudaGetSymbolAddress((void**)&p_wt,    g_wt);
    #define WT(i) (p_wt + (size_t)(i) * HID * HID)

    const float scale = 1.0f / sqrtf((float)DHEAD);

    // ---- weight transposes (B operands become [N,K] K-major) ----
    do_transpose(W_in1, WT(0), IN_DIM, HID);      // -> [512,128]
    do_transpose(W_in2, WT(1), HID, HID);
    for (int l = 0; l < NLAYER; l++) {
        const size_t wo = (size_t)l * HID * HID;
        do_transpose(Wproj + wo, WT(2 + l * 6 + 0), HID, HID);
        do_transpose(Wq   + wo, WT(2 + l * 6 + 1), HID, HID);
        do_transpose(Wk   + wo, WT(2 + l * 6 + 2), HID, HID);
        do_transpose(Wv   + wo, WT(2 + l * 6 + 3), HID, HID);
        do_transpose(ffW1 + wo, WT(2 + l * 6 + 4), HID, HID);
        do_transpose(ffW2 + wo, WT(2 + l * 6 + 5), HID, HID);
    }
    do_transpose(Wout, WT(14), HID, OUT_DIM);     // -> [64,512]

    // ---- community preprocessing (deterministic) ----
    hist_kernel      <<<NCHUNK, CHUNK>>>(ntc);
    chunk_scan_kernel<<<C_COMM, NCHUNK>>>();
    offsets_kernel   <<<1, C_COMM>>>();
    scatter_kernel   <<<NCHUNK, CHUNK>>>(ntc);

    // ---- fc_in ----
    tc_nn(N_NODES, HID, IN_DIM, x, IN_DIM, WT(0), b_in1, p_t0, HID);
    ln_relu_kernel<<<N_NODES, 256>>>(p_t0, p_t0, ln_in_g, ln_in_b);
    tc_nn(N_NODES, HID, HID, p_t0, HID, WT(1), b_in2, p_h, HID);

    // ---- layers ----
    for (int l = 0; l < NLAYER; l++) {
        bias_table_kernel<<<NDIST, 128>>>(dis_emb + (size_t)l * NDIST * HID,
                                          dis_w + (size_t)l * HID, dis_b + l);
        comm_avg_kernel<<<C_COMM, 256>>>();

        tc_nn(N_NODES, HID, HID, p_h,  HID, WT(2 + l * 6 + 0), bproj + (size_t)l * HID, p_t0, HID);
        tc_nn(N_NODES, HID, HID, p_t0, HID, WT(2 + l * 6 + 1), bq    + (size_t)l * HID, p_q,  HID);
        tc_nn(C_COMM,  HID, HID, p_comm, HID, WT(2 + l * 6 + 2), bk  + (size_t)l * HID, p_k,  HID);
        tc_nn(C_COMM,  HID, HID, p_comm, HID, WT(2 + l * 6 + 3), bv  + (size_t)l * HID, p_v,  HID);

        // dots: q[., h*128:+128] @ k[., h*128:+128]^T per head, fused epilogue
        {
            dim3 g(C_COMM / 128, N_NODES / 128, NHEAD);
            mma_gemm<128, 1><<<g, 256>>>(
                N_NODES, DHEAD,
                p_q, HID, (size_t)DHEAD,
                p_k, HID, (size_t)DHEAD,
                nullptr,
                p_dots, C_COMM, (size_t)N_NODES * C_COMM,
                scale, p_logc, p_table, dm, C_COMM);
        }
        softmax_kernel<<<NHEAD * N_NODES, 256>>>(p_dots);

        // AV: transpose v -> vT [HID, C], then attn @ vT(head slice)^T
        do_transpose(p_v, WT(15), C_COMM, HID);
        {
            dim3 g(1, N_NODES / 128, NHEAD);
            mma_gemm<128, 0><<<g, 256>>>(
                N_NODES, C_COMM,
                p_dots, C_COMM, (size_t)N_NODES * C_COMM,
                WT(15), C_COMM, (size_t)DHEAD * C_COMM,
                nullptr,
                p_t0, HID, (size_t)DHEAD,
                0.f, nullptr, nullptr, nullptr, 0);
        }

        tc_nn(N_NODES, HID, HID, p_t0, HID, WT(2 + l * 6 + 4), ffb1 + (size_t)l * HID, p_t1, HID);
        ln_relu_kernel<<<N_NODES, 256>>>(p_t1, p_t1, ffg1 + (size_t)l * HID,
                                         ffbeta1 + (size_t)l * HID);
        tc_nn(N_NODES, HID, HID, p_t1, HID, WT(2 + l * 6 + 5), ffb2 + (size_t)l * HID, p_q, HID);
        ln_relu_kernel<<<N_NODES, 256>>>(p_q, p_h, ffg2 + (size_t)l * HID,
                                         ffbeta2 + (size_t)l * HID);
    }

    // ---- output projection ----
    tc_nn(N_NODES, OUT_DIM, HID, p_h, HID, WT(14), bout, (float*)d_out, OUT_DIM);
}

// round 7
// speedup vs baseline: 2.0421x; 1.1041x over previous
#include <cuda_runtime.h>
#include <cuda_bf16.h>
#include <math.h>
#include <stdint.h>

// ---------------- problem constants ----------------
#define N_NODES 32768
#define C_COMM  512
#define IN_DIM  128
#define HID     512
#define NHEAD   4
#define DHEAD   128
#define NLAYER  2
#define OUT_DIM 64
#define NDIST   31
#define EPS     1e-5f

#define CHUNK   256
#define NCHUNK  (N_NODES / CHUNK)   // 128

// ---------------- scratch (device globals; no allocation allowed) ----------------
__device__ float g_h   [N_NODES * HID];
__device__ float g_t0  [N_NODES * HID];
__device__ float g_t1  [N_NODES * HID];
__device__ float g_q   [N_NODES * HID];
__device__ float g_dots[(size_t)NHEAD * N_NODES * C_COMM];
__device__ float g_comm[C_COMM * HID];
__device__ float g_k   [C_COMM * HID];
__device__ float g_v   [C_COMM * HID];
__device__ float g_wt  [15][HID * HID];   // transposed/fused weights + scratch
__device__ float g_bfq [NLAYER * HID];    // fused q bias
__device__ int   g_hist     [NCHUNK * C_COMM];
__device__ int   g_chunkbase[NCHUNK * C_COMM];
__device__ int   g_counts [C_COMM];
__device__ int   g_offsets[C_COMM];
__device__ int   g_members[N_NODES];
__device__ float g_logc[C_COMM];
__device__ float g_inv [C_COMM];
__device__ float g_table[NDIST];

// ---------------- small PTX helpers (all sm_80-compatible) ----------------
__device__ __forceinline__ uint32_t smem_u32(const void* p) {
    uint32_t a;
    asm("{ .reg .u64 t; cvta.to.shared.u64 t, %1; cvt.u32.u64 %0, t; }" : "=r"(a) : "l"(p));
    return a;
}

__device__ __forceinline__ void ldm4(uint32_t* r, uint32_t addr) {
    asm volatile("ldmatrix.sync.aligned.m8n8.x4.shared.b16 {%0,%1,%2,%3}, [%4];"
                 : "=r"(r[0]), "=r"(r[1]), "=r"(r[2]), "=r"(r[3]) : "r"(addr));
}

__device__ __forceinline__ void mma_bf16(float* d, const uint32_t* a, const uint32_t* b) {
    asm volatile(
        "mma.sync.aligned.m16n8k16.row.col.f32.bf16.bf16.f32 "
        "{%0,%1,%2,%3}, {%4,%5,%6,%7}, {%8,%9}, {%0,%1,%2,%3};"
        : "+f"(d[0]), "+f"(d[1]), "+f"(d[2]), "+f"(d[3])
        : "r"(a[0]), "r"(a[1]), "r"(a[2]), "r"(a[3]), "r"(b[0]), "r"(b[1]));
}

// split fp32x4 -> bf16 hi quad + bf16 lo quad (each uint2 = 4 bf16)
__device__ __forceinline__ void split4(float4 v, uint2& H, uint2& L) {
    __nv_bfloat16 hx = __float2bfloat16(v.x), hy = __float2bfloat16(v.y);
    __nv_bfloat16 hz = __float2bfloat16(v.z), hw = __float2bfloat16(v.w);
    H.x = (uint32_t)__bfloat16_as_ushort(hx) | ((uint32_t)__bfloat16_as_ushort(hy) << 16);
    H.y = (uint32_t)__bfloat16_as_ushort(hz) | ((uint32_t)__bfloat16_as_ushort(hw) << 16);
    __nv_bfloat16 lx = __float2bfloat16(v.x - __bfloat162float(hx));
    __nv_bfloat16 ly = __float2bfloat16(v.y - __bfloat162float(hy));
    __nv_bfloat16 lz = __float2bfloat16(v.z - __bfloat162float(hz));
    __nv_bfloat16 lw = __float2bfloat16(v.w - __bfloat162float(hw));
    L.x = (uint32_t)__bfloat16_as_ushort(lx) | ((uint32_t)__bfloat16_as_ushort(ly) << 16);
    L.y = (uint32_t)__bfloat16_as_ushort(lz) | ((uint32_t)__bfloat16_as_ushort(lw) << 16);
}

// ---------------- warp-MMA GEMM: C[M,N] = A[M,K] . B[N,K]^T  (fp32 in/out) ----------------
// Double-buffered smem pipeline (2 stages, dynamic smem).
// EPI==0: + bias (optional).  EPI==1: *scale + logc[col] + table[dm[row,col]]
// blockIdx.z offsets: A += z*zsA, B += z*zsB, C += z*zsC.
// Requires M%128==0, Ncols == gridDim.x*BN, K%32==0, 16B-aligned rows.
template<int BN, int EPI>
__global__ __launch_bounds__(256, 1)
void mma_gemm(int M, int K,
              const float* __restrict__ A, int lda, size_t zsA,
              const float* __restrict__ B, int ldb, size_t zsB,
              const float* __restrict__ bias,
              float* __restrict__ Cm, int ldc, size_t zsC,
              float scale, const float* __restrict__ logc,
              const float* __restrict__ table,
              const int* __restrict__ dm, int dmld)
{
    constexpr int BM  = 128, BK = 32;
    constexpr int LDS = 40;                  // bf16 elems/row (32 + 8 pad -> 80B stride)
    constexpr int NW_N = BN / 32;
    constexpr int NW_M = 8 / NW_N;
    constexpr int WM  = BM / NW_M;
    constexpr int MI  = WM / 16;
    constexpr int NA  = BM * (BK / 4) / 256; // float4 per thread (A) = 4
    constexpr int NB  = BN * (BK / 4) / 256;
    constexpr int ASZ   = BM * LDS * 2;      // bytes per A half-tile
    constexpr int BSZ   = BN * LDS * 2;
    constexpr int STAGE = 2 * ASZ + 2 * BSZ;

    extern __shared__ char smem[];
    const uint32_t uS = smem_u32(smem);

    A  += (size_t)blockIdx.z * zsA;
    B  += (size_t)blockIdx.z * zsB;
    Cm += (size_t)blockIdx.z * zsC;
    const int m0 = blockIdx.y * BM, n0 = blockIdx.x * BN;
    const int tid = threadIdx.x, lane = tid & 31, wid = tid >> 5;
    const int wm = wid % NW_M, wn = wid / NW_M;
    const int mbase = wm * WM, nbase = wn * 32;
    const int lr = lane & 15, lc8 = (lane >> 4) * 8;

    float acc[MI][4][4];
    #pragma unroll
    for (int mi = 0; mi < MI; ++mi)
        #pragma unroll
        for (int ni = 0; ni < 4; ++ni)
            #pragma unroll
            for (int q = 0; q < 4; ++q) acc[mi][ni][q] = 0.f;

    float4 pa[NA], pb[NB];
    // prologue: load chunk 0, store into stage 0
    #pragma unroll
    for (int t = 0; t < NA; ++t) {
        int j = tid + t * 256, r = j >> 3, c = j & 7;
        pa[t] = *reinterpret_cast<const float4*>(A + (size_t)(m0 + r) * lda + c * 4);
    }
    #pragma unroll
    for (int t = 0; t < NB; ++t) {
        int j = tid + t * 256, r = j >> 3, c = j & 7;
        pb[t] = *reinterpret_cast<const float4*>(B + (size_t)(n0 + r) * ldb + c * 4);
    }
    {
        char* st = smem;
        #pragma unroll
        for (int t = 0; t < NA; ++t) {
            int j = tid + t * 256, r = j >> 3, c = j & 7;
            uint2 H, L; split4(pa[t], H, L);
            *reinterpret_cast<uint2*>(st + (r * LDS + c * 4) * 2)       = H;
            *reinterpret_cast<uint2*>(st + ASZ + (r * LDS + c * 4) * 2) = L;
        }
        #pragma unroll
        for (int t = 0; t < NB; ++t) {
            int j = tid + t * 256, r = j >> 3, c = j & 7;
            uint2 H, L; split4(pb[t], H, L);
            *reinterpret_cast<uint2*>(st + 2 * ASZ + (r * LDS + c * 4) * 2)       = H;
            *reinterpret_cast<uint2*>(st + 2 * ASZ + BSZ + (r * LDS + c * 4) * 2) = L;
        }
    }
    __syncthreads();

    const int nch = K >> 5;
    for (int ch = 0; ch < nch; ++ch) {
        const bool more = (ch + 1 < nch);
        // issue next chunk's global loads (latency hidden under MMA below)
        if (more) {
            int k0 = (ch + 1) << 5;
            #pragma unroll
            for (int t = 0; t < NA; ++t) {
                int j = tid + t * 256, r = j >> 3, c = j & 7;
                pa[t] = *reinterpret_cast<const float4*>(A + (size_t)(m0 + r) * lda + k0 + c * 4);
            }
            #pragma unroll
            for (int t = 0; t < NB; ++t) {
                int j = tid + t * 256, r = j >> 3, c = j & 7;
                pb[t] = *reinterpret_cast<const float4*>(B + (size_t)(n0 + r) * ldb + k0 + c * 4);
            }
        }

        // MMA on current stage
        {
            const uint32_t sb = uS + (uint32_t)((ch & 1) * STAGE);
            const uint32_t uAh = sb, uAl = sb + ASZ, uBh = sb + 2 * ASZ, uBl = sb + 2 * ASZ + BSZ;
            #pragma unroll
            for (int ks = 0; ks < 2; ++ks) {
                uint32_t ah[MI][4], al[MI][4];
                #pragma unroll
                for (int mi = 0; mi < MI; ++mi) {
                    uint32_t off = (uint32_t)((mbase + mi * 16 + lr) * LDS + ks * 16 + lc8) * 2;
                    ldm4(ah[mi], uAh + off);
                    ldm4(al[mi], uAl + off);
                }
                uint32_t bh[4][2], bl[4][2], r[4];
                uint32_t off0 = (uint32_t)((nbase + lr) * LDS + ks * 16 + lc8) * 2;
                uint32_t off1 = (uint32_t)((nbase + 16 + lr) * LDS + ks * 16 + lc8) * 2;
                ldm4(r, uBh + off0); bh[0][0] = r[0]; bh[0][1] = r[2]; bh[1][0] = r[1]; bh[1][1] = r[3];
                ldm4(r, uBh + off1); bh[2][0] = r[0]; bh[2][1] = r[2]; bh[3][0] = r[1]; bh[3][1] = r[3];
                ldm4(r, uBl + off0); bl[0][0] = r[0]; bl[0][1] = r[2]; bl[1][0] = r[1]; bl[1][1] = r[3];
                ldm4(r, uBl + off1); bl[2][0] = r[0]; bl[2][1] = r[2]; bl[3][0] = r[1]; bl[3][1] = r[3];
                #pragma unroll
                for (int mi = 0; mi < MI; ++mi)
                    #pragma unroll
                    for (int ni = 0; ni < 4; ++ni) {
                        mma_bf16(acc[mi][ni], ah[mi], bh[ni]);
                        mma_bf16(acc[mi][ni], ah[mi], bl[ni]);
                        mma_bf16(acc[mi][ni], al[mi], bh[ni]);
                    }
            }
        }

        // store next chunk into other stage
        if (more) {
            char* st = smem + ((ch + 1) & 1) * STAGE;
            #pragma unroll
            for (int t = 0; t < NA; ++t) {
                int j = tid + t * 256, r = j >> 3, c = j & 7;
                uint2 H, L; split4(pa[t], H, L);
                *reinterpret_cast<uint2*>(st + (r * LDS + c * 4) * 2)       = H;
                *reinterpret_cast<uint2*>(st + ASZ + (r * LDS + c * 4) * 2) = L;
            }
            #pragma unroll
            for (int t = 0; t < NB; ++t) {
                int j = tid + t * 256, r = j >> 3, c = j & 7;
                uint2 H, L; split4(pb[t], H, L);
                *reinterpret_cast<uint2*>(st + 2 * ASZ + (r * LDS + c * 4) * 2)       = H;
                *reinterpret_cast<uint2*>(st + 2 * ASZ + BSZ + (r * LDS + c * 4) * 2) = L;
            }
        }
        __syncthreads();
    }

    // epilogue
    #pragma unroll
    for (int mi = 0; mi < MI; ++mi) {
        int r0 = m0 + mbase + mi * 16 + (lane >> 2);
        #pragma unroll
        for (int ni = 0; ni < 4; ++ni) {
            int cc = n0 + nbase + ni * 8 + (lane & 3) * 2;
            float d0 = acc[mi][ni][0], d1 = acc[mi][ni][1];
            float d2 = acc[mi][ni][2], d3 = acc[mi][ni][3];
            if (EPI == 0) {
                if (bias) {
                    float b0 = bias[cc], b1 = bias[cc + 1];
                    d0 += b0; d1 += b1; d2 += b0; d3 += b1;
                }
            } else {
                float lg0 = logc[cc], lg1 = logc[cc + 1];
                int e0 = dm[(size_t)r0 * dmld + cc],       e1 = dm[(size_t)r0 * dmld + cc + 1];
                int e2 = dm[(size_t)(r0 + 8) * dmld + cc], e3 = dm[(size_t)(r0 + 8) * dmld + cc + 1];
                d0 = d0 * scale + lg0 + table[e0];
                d1 = d1 * scale + lg1 + table[e1];
                d2 = d2 * scale + lg0 + table[e2];
                d3 = d3 * scale + lg1 + table[e3];
            }
            float2 lo = make_float2(d0, d1), hi = make_float2(d2, d3);
            *reinterpret_cast<float2*>(Cm + (size_t)r0 * ldc + cc)       = lo;
            *reinterpret_cast<float2*>(Cm + (size_t)(r0 + 8) * ldc + cc) = hi;
        }
    }
}

// ---------------- fp32 transpose: out[C,R] = in[R,C]^T ----------------
__global__ void transpose_kernel(const float* __restrict__ in, float* __restrict__ out,
                                 int R, int Ccols) {
    __shared__ float tile[32][33];
    int c0 = blockIdx.x * 32, r0 = blockIdx.y * 32;
    int x = threadIdx.x, y = threadIdx.y;           // 32 x 8
    #pragma unroll
    for (int j = 0; j < 32; j += 8)
        tile[y + j][x] = in[(size_t)(r0 + y + j) * Ccols + c0 + x];
    __syncthreads();
    #pragma unroll
    for (int j = 0; j < 32; j += 8)
        out[(size_t)(c0 + y + j) * R + r0 + x] = tile[x][y + j];
}

// ---------------- fused q bias: out[o] = sum_k bproj[k]*Wq[k,o] + bq[o] ----------------
__global__ void fuse_bias_kernel(const float* __restrict__ bproj,
                                 const float* __restrict__ Wq,
                                 const float* __restrict__ bq,
                                 float* __restrict__ out) {
    int o = blockIdx.x * blockDim.x + threadIdx.x;   // 0..HID-1
    float s = bq[o];
    for (int k = 0; k < HID; k++) s += bproj[k] * Wq[(size_t)k * HID + o];
    out[o] = s;
}

// ---------------- community preprocessing (deterministic, stable) ----------------
__global__ void hist_kernel(const int* __restrict__ ntc) {
    __shared__ int sh[C_COMM];
    int chunk = blockIdx.x;
    for (int i = threadIdx.x; i < C_COMM; i += blockDim.x) sh[i] = 0;
    __syncthreads();
    int node = chunk * CHUNK + threadIdx.x;
    atomicAdd(&sh[ntc[node]], 1);
    __syncthreads();
    for (int i = threadIdx.x; i < C_COMM; i += blockDim.x)
        g_hist[chunk * C_COMM + i] = sh[i];
}

__global__ void chunk_scan_kernel() {
    int c = blockIdx.x;
    __shared__ int s[NCHUNK];
    int t = threadIdx.x;
    int own = g_hist[t * C_COMM + c];
    s[t] = own;
    __syncthreads();
    for (int off = 1; off < NCHUNK; off <<= 1) {
        int v = (t >= off) ? s[t - off] : 0;
        __syncthreads();
        s[t] += v;
        __syncthreads();
    }
    g_chunkbase[t * C_COMM + c] = s[t] - own;
    if (t == NCHUNK - 1) g_counts[c] = s[t];
}

__global__ void offsets_kernel() {
    __shared__ int s[C_COMM];
    int t = threadIdx.x;
    int own = g_counts[t];
    s[t] = own;
    __syncthreads();
    for (int off = 1; off < C_COMM; off <<= 1) {
        int v = (t >= off) ? s[t - off] : 0;
        __syncthreads();
        s[t] += v;
        __syncthreads();
    }
    g_offsets[t] = s[t] - own;
    g_logc[t]    = logf((float)own);
    g_inv[t]     = 1.0f / (float)(own > 0 ? own : 1);
}

__global__ void scatter_kernel(const int* __restrict__ ntc) {
    __shared__ int s[CHUNK];
    int chunk = blockIdx.x;
    int t = threadIdx.x;
    int node = chunk * CHUNK + t;
    int c = ntc[node];
    s[t] = c;
    __syncthreads();
    int lrank = 0;
    for (int j = 0; j < t; j++) lrank += (s[j] == c);
    g_members[g_offsets[c] + g_chunkbase[chunk * C_COMM + c] + lrank] = node;
}

__global__ void comm_avg_kernel() {
    int c = blockIdx.x;
    int t = threadIdx.x;
    int off = g_offsets[c], cnt = g_counts[c];
    float a0 = 0.f, a1 = 0.f;
    for (int m = 0; m < cnt; m++) {
        const float* row = g_h + (size_t)g_members[off + m] * HID;
        a0 += row[t];
        a1 += row[t + 256];
    }
    float inv = g_inv[c];
    g_comm[c * HID + t]       = a0 * inv;
    g_comm[c * HID + t + 256] = a1 * inv;
}

__global__ void bias_table_kernel(const float* __restrict__ emb,
                                  const float* __restrict__ w,
                                  const float* __restrict__ bptr) {
    int i = blockIdx.x;
    int t = threadIdx.x;
    float s = emb[i * HID + t]       * w[t]
            + emb[i * HID + t + 128] * w[t + 128]
            + emb[i * HID + t + 256] * w[t + 256]
            + emb[i * HID + t + 384] * w[t + 384];
    for (int o = 16; o; o >>= 1) s += __shfl_xor_sync(0xFFFFFFFFu, s, o);
    __shared__ float r[4];
    if ((t & 31) == 0) r[t >> 5] = s;
    __syncthreads();
    if (t == 0) g_table[i] = r[0] + r[1] + r[2] + r[3] + bptr[0];
}

__global__ void ln_relu_kernel(const float* __restrict__ in, float* __restrict__ out,
                               const float* __restrict__ g, const float* __restrict__ b) {
    size_t row = blockIdx.x;
    int t = threadIdx.x;
    const float* x = in + row * HID;
    float v0 = x[t], v1 = x[t + 256];
    float s = v0 + v1, q = v0 * v0 + v1 * v1;
    for (int o = 16; o; o >>= 1) {
        s += __shfl_xor_sync(0xFFFFFFFFu, s, o);
        q += __shfl_xor_sync(0xFFFFFFFFu, q, o);
    }
    __shared__ float rs[8], rq[8];
    int w = t >> 5, lane = t & 31;
    if (lane == 0) { rs[w] = s; rq[w] = q; }
    __syncthreads();
    __shared__ float smean, srstd;
    if (t == 0) {
        float ts = 0.f, tq = 0.f;
        for (int i = 0; i < 8; i++) { ts += rs[i]; tq += rq[i]; }
        float mean = ts * (1.0f / HID);
        float var  = tq * (1.0f / HID) - mean * mean;
        smean = mean;
        srstd = rsqrtf(var + EPS);
    }
    __syncthreads();
    float mean = smean, rstd = srstd;
    float y0 = (v0 - mean) * rstd * g[t]       + b[t];
    float y1 = (v1 - mean) * rstd * g[t + 256] + b[t + 256];
    out[row * HID + t]       = fmaxf(y0, 0.f);
    out[row * HID + t + 256] = fmaxf(y1, 0.f);
}

__global__ void softmax_kernel(float* __restrict__ dots) {
    size_t row = (size_t)blockIdx.x;
    float* p = dots + row * C_COMM;
    int t = threadIdx.x;
    float v0 = p[t], v1 = p[t + 256];
    float m = fmaxf(v0, v1);
    for (int o = 16; o; o >>= 1) m = fmaxf(m, __shfl_xor_sync(0xFFFFFFFFu, m, o));
    __shared__ float rm[8];
    int w = t >> 5, lane = t & 31;
    if (lane == 0) rm[w] = m;
    __syncthreads();
    __shared__ float smax;
    if (t == 0) {
        float mm = rm[0];
        for (int i = 1; i < 8; i++) mm = fmaxf(mm, rm[i]);
        smax = mm;
    }
    __syncthreads();
    m = smax;
    float e0 = __expf(v0 - m), e1 = __expf(v1 - m);
    float s = e0 + e1;
    for (int o = 16; o; o >>= 1) s += __shfl_xor_sync(0xFFFFFFFFu, s, o);
    __shared__ float rsum[8];
    if (lane == 0) rsum[w] = s;
    __syncthreads();
    __shared__ float stot;
    if (t == 0) {
        float ts = 0.f;
        for (int i = 0; i < 8; i++) ts += rsum[i];
        stot = ts;
    }
    __syncthreads();
    float inv = 1.0f / stot;
    p[t]       = e0 * inv;
    p[t + 256] = e1 * inv;
}

// ---------------- host-side helpers ----------------
static const int SMEM_128 = 2 * (2 * 128 * 40 * 2 + 2 * 128 * 40 * 2); // 81920
static const int SMEM_64  = 2 * (2 * 128 * 40 * 2 + 2 * 64 * 40 * 2);  // 61440

// C[M,N] = A[M,K] @ Bt[N,K]^T + bias  (Bt pre-transposed, K-major)
static void tc_nn(int M, int Nc, int K,
                  const float* A, int lda, const float* Bt,
                  const float* bias, float* Cm, int ldc)
{
    if (Nc % 128 == 0) {
        dim3 g(Nc / 128, M / 128, 1);
        mma_gemm<128, 0><<<g, 256, SMEM_128>>>(M, K, A, lda, 0, Bt, K, 0,
                                               bias, Cm, ldc, 0,
                                               0.f, nullptr, nullptr, nullptr, 0);
    } else { // Nc == 64
        dim3 g(1, M / 128, 1);
        mma_gemm<64, 0><<<g, 256, SMEM_64>>>(M, K, A, lda, 0, Bt, K, 0,
                                             bias, Cm, ldc, 0,
                                             0.f, nullptr, nullptr, nullptr, 0);
    }
}

static void do_transpose(const float* in, float* out, int R, int C) {
    dim3 g(C / 32, R / 32), b(32, 8);
    transpose_kernel<<<g, b>>>(in, out, R, C);
}

extern "C" void kernel_launch(void* const* d_in, const int* in_sizes, int n_in,
                              void* d_out, int out_size)
{
    // ---- input mapping (auto-detect metadata order) ----
    const float *x      = (const float*)d_in[0];
    const int   *dm     = (const int*)  d_in[1];
    const int   *ntc    = (const int*)  d_in[2];
    const float *W_in1  = (const float*)d_in[3];
    const float *b_in1  = (const float*)d_in[4];
    const float *ln_in_g= (const float*)d_in[5];
    const float *ln_in_b= (const float*)d_in[6];
    const float *W_in2  = (const float*)d_in[7];
    const float *b_in2  = (const float*)d_in[8];
    const float *Wproj, *Wq, *Wk, *Wv, *ffW1, *ffW2;
    const float *bproj, *bq, *bk, *bv, *ffb1, *ffb2;
    const float *dis_emb, *dis_w, *dis_b;
    const float *ffg1, *ffbeta1, *ffg2, *ffbeta2, *Wout, *bout;

    if (in_sizes[10] == NLAYER * HID * HID) {
        Wproj  = (const float*)d_in[9];  Wq     = (const float*)d_in[10];
        Wk     = (const float*)d_in[11]; Wv     = (const float*)d_in[12];
        ffW1   = (const float*)d_in[13]; ffW2   = (const float*)d_in[14];
        bproj  = (const float*)d_in[15]; bq     = (const float*)d_in[16];
        bk     = (const float*)d_in[17]; bv     = (const float*)d_in[18];
        ffb1   = (const float*)d_in[19]; ffb2   = (const float*)d_in[20];
        dis_emb= (const float*)d_in[21]; dis_w  = (const float*)d_in[22];
        dis_b  = (const float*)d_in[23];
        ffg1   = (const float*)d_in[24]; ffbeta1= (const float*)d_in[25];
        ffg2   = (const float*)d_in[26]; ffbeta2= (const float*)d_in[27];
        Wout   = (const float*)d_in[28]; bout   = (const float*)d_in[29];
    } else {
        Wproj  = (const float*)d_in[9];  bproj  = (const float*)d_in[10];
        Wq     = (const float*)d_in[11]; bq     = (const float*)d_in[12];
        Wk     = (const float*)d_in[13]; bk     = (const float*)d_in[14];
        Wv     = (const float*)d_in[15]; bv     = (const float*)d_in[16];
        dis_emb= (const float*)d_in[17]; dis_w  = (const float*)d_in[18];
        dis_b  = (const float*)d_in[19];
        ffW1   = (const float*)d_in[20]; ffb1   = (const float*)d_in[21];
        ffg1   = (const float*)d_in[22]; ffbeta1= (const float*)d_in[23];
        ffW2   = (const float*)d_in[24]; ffb2   = (const float*)d_in[25];
        ffg2   = (const float*)d_in[26]; ffbeta2= (const float*)d_in[27];
        Wout   = (const float*)d_in[28]; bout   = (const float*)d_in[29];
    }

    // ---- opt-in dynamic smem (host API, idempotent, capture-safe) ----
    cudaFuncSetAttribute(mma_gemm<128, 0>, cudaFuncAttributeMaxDynamicSharedMemorySize, SMEM_128);
    cudaFuncSetAttribute(mma_gemm<128, 1>, cudaFuncAttributeMaxDynamicSharedMemorySize, SMEM_128);
    cudaFuncSetAttribute(mma_gemm<64, 0>,  cudaFuncAttributeMaxDynamicSharedMemorySize, SMEM_64);

    // ---- scratch pointers ----
    float *p_h, *p_t0, *p_t1, *p_q, *p_dots, *p_comm, *p_k, *p_v, *p_logc, *p_table, *p_wt, *p_bfq;
    cudaGetSymbolAddress((void**)&p_h,     g_h);
    cudaGetSymbolAddress((void**)&p_t0,    g_t0);
    cudaGetSymbolAddress((void**)&p_t1,    g_t1);
    cudaGetSymbolAddress((void**)&p_q,     g_q);
    cudaGetSymbolAddress((void**)&p_dots,  g_dots);
    cudaGetSymbolAddress((void**)&p_comm,  g_comm);
    cudaGetSymbolAddress((void**)&p_k,     g_k);
    cudaGetSymbolAddress((void**)&p_v,     g_v);
    cudaGetSymbolAddress((void**)&p_logc,  g_logc);
    cudaGetSymbolAddress((void**)&p_table, g_table);
    cudaGetSymbolAddress((void**)&p_wt,    g_wt);
    cudaGetSymbolAddress((void**)&p_bfq,   g_bfq);
    #define WT(i) (p_wt + (size_t)(i) * HID * HID)

    const float scale = 1.0f / sqrtf((float)DHEAD);

    // ---- weight preprocessing ----
    // slots: 0=W_in1T 1=W_in2T; per layer l: 2+l*5+{0:WfqT,1:WkT,2:WvT,3:ffW1T,4:ffW2T};
    // 12=WoutT; 13=tmp WqT; 14=vT scratch
    do_transpose(W_in1, WT(0), IN_DIM, HID);
    do_transpose(W_in2, WT(1), HID, HID);
    for (int l = 0; l < NLAYER; l++) {
        const size_t wo = (size_t)l * HID * HID;
        // fused q weight: WfqT[o,i] = sum_k WqT[o,k] * Wproj[i,k]
        do_transpose(Wq + wo, WT(13), HID, HID);
        {
            dim3 g(HID / 128, HID / 128, 1);
            mma_gemm<128, 0><<<g, 256, SMEM_128>>>(HID, HID,
                                                   WT(13), HID, 0,
                                                   Wproj + wo, HID, 0,
                                                   nullptr, WT(2 + l * 5 + 0), HID, 0,
                                                   0.f, nullptr, nullptr, nullptr, 0);
        }
        fuse_bias_kernel<<<HID / 256, 256>>>(bproj + (size_t)l * HID, Wq + wo,
                                             bq + (size_t)l * HID, p_bfq + (size_t)l * HID);
        do_transpose(Wk   + wo, WT(2 + l * 5 + 1), HID, HID);
        do_transpose(Wv   + wo, WT(2 + l * 5 + 2), HID, HID);
        do_transpose(ffW1 + wo, WT(2 + l * 5 + 3), HID, HID);
        do_transpose(ffW2 + wo, WT(2 + l * 5 + 4), HID, HID);
    }
    do_transpose(Wout, WT(12), HID, OUT_DIM);     // -> [64,512]

    // ---- community preprocessing (deterministic) ----
    hist_kernel      <<<NCHUNK, CHUNK>>>(ntc);
    chunk_scan_kernel<<<C_COMM, NCHUNK>>>();
    offsets_kernel   <<<1, C_COMM>>>();
    scatter_kernel   <<<NCHUNK, CHUNK>>>(ntc);

    // ---- fc_in ----
    tc_nn(N_NODES, HID, IN_DIM, x, IN_DIM, WT(0), b_in1, p_t0, HID);
    ln_relu_kernel<<<N_NODES, 256>>>(p_t0, p_t0, ln_in_g, ln_in_b);
    tc_nn(N_NODES, HID, HID, p_t0, HID, WT(1), b_in2, p_h, HID);

    // ---- layers ----
    for (int l = 0; l < NLAYER; l++) {
        bias_table_kernel<<<NDIST, 128>>>(dis_emb + (size_t)l * NDIST * HID,
                                          dis_w + (size_t)l * HID, dis_b + l);
        comm_avg_kernel<<<C_COMM, 256>>>();

        // q = h @ WfqT^T + bfq (proj+q fused)
        tc_nn(N_NODES, HID, HID, p_h, HID, WT(2 + l * 5 + 0), p_bfq + (size_t)l * HID, p_q, HID);
        tc_nn(C_COMM,  HID, HID, p_comm, HID, WT(2 + l * 5 + 1), bk + (size_t)l * HID, p_k, HID);
        tc_nn(C_COMM,  HID, HID, p_comm, HID, WT(2 + l * 5 + 2), bv + (size_t)l * HID, p_v, HID);

        // dots: q[., h*128:+128] @ k[., h*128:+128]^T per head, fused epilogue
        {
            dim3 g(C_COMM / 128, N_NODES / 128, NHEAD);
            mma_gemm<128, 1><<<g, 256, SMEM_128>>>(
                N_NODES, DHEAD,
                p_q, HID, (size_t)DHEAD,
                p_k, HID, (size_t)DHEAD,
                nullptr,
                p_dots, C_COMM, (size_t)N_NODES * C_COMM,
                scale, p_logc, p_table, dm, C_COMM);
        }
        softmax_kernel<<<NHEAD * N_NODES, 256>>>(p_dots);

        // AV: transpose v -> vT [HID, C], then attn @ vT(head slice)^T
        do_transpose(p_v, WT(14), C_COMM, HID);
        {
            dim3 g(1, N_NODES / 128, NHEAD);
            mma_gemm<128, 0><<<g, 256, SMEM_128>>>(
                N_NODES, C_COMM,
                p_dots, C_COMM, (size_t)N_NODES * C_COMM,
                WT(14), C_COMM, (size_t)DHEAD * C_COMM,
                nullptr,
                p_t0, HID, (size_t)DHEAD,
                0.f, nullptr, nullptr, nullptr, 0);
        }

        tc_nn(N_NODES, HID, HID, p_t0, HID, WT(2 + l * 5 + 3), ffb1 + (size_t)l * HID, p_t1, HID);
        ln_relu_kernel<<<N_NODES, 256>>>(p_t1, p_t1, ffg1 + (size_t)l * HID,
                                         ffbeta1 + (size_t)l * HID);
        tc_nn(N_NODES, HID, HID, p_t1, HID, WT(2 + l * 5 + 4), ffb2 + (size_t)l * HID, p_q, HID);
        ln_relu_kernel<<<N_NODES, 256>>>(p_q, p_h, ffg2 + (size_t)l * HID,
                                         ffbeta2 + (size_t)l * HID);
    }

    // ---- output projection ----
    tc_nn(N_NODES, OUT_DIM, HID, p_h, HID, WT(12), bout, (float*)d_out, OUT_DIM);
}

// round 8
// speedup vs baseline: 2.0864x; 1.0217x over previous
#include <cuda_runtime.h>
#include <cuda_bf16.h>
#include <math.h>
#include <stdint.h>

// ---------------- problem constants ----------------
#define N_NODES 32768
#define C_COMM  512
#define IN_DIM  128
#define HID     512
#define NHEAD   4
#define DHEAD   128
#define NLAYER  2
#define OUT_DIM 64
#define NDIST   31
#define EPS     1e-5f

#define CHUNK   256
#define NCHUNK  (N_NODES / CHUNK)   // 128

typedef __nv_bfloat16 bf16;

// ---------------- scratch (device globals; no allocation allowed) ----------------
__device__ float g_h   [N_NODES * HID];
__device__ float g_t0  [N_NODES * HID];
__device__ float g_t1  [N_NODES * HID];
__device__ float g_dots[(size_t)NHEAD * N_NODES * C_COMM];
__device__ float g_v   [C_COMM * HID];
__device__ float g_bfq [NLAYER * HID];

__device__ bf16 g_xh [N_NODES * IN_DIM], g_xl [N_NODES * IN_DIM];
__device__ bf16 g_hh [N_NODES * HID],    g_hl [N_NODES * HID];
__device__ bf16 g_t0h[N_NODES * HID],    g_t0l[N_NODES * HID];
__device__ bf16 g_t1h[N_NODES * HID],    g_t1l[N_NODES * HID];
__device__ bf16 g_qh [N_NODES * HID],    g_ql [N_NODES * HID];
__device__ bf16 g_ph [(size_t)NHEAD * N_NODES * C_COMM];
__device__ bf16 g_pl [(size_t)NHEAD * N_NODES * C_COMM];
__device__ bf16 g_cmh[C_COMM * HID],     g_cml[C_COMM * HID];
__device__ bf16 g_kh [C_COMM * HID],     g_kl [C_COMM * HID];
__device__ bf16 g_vth[HID * C_COMM],     g_vtl[HID * C_COMM];
__device__ bf16 g_wh [15][HID * HID],    g_wl [15][HID * HID];

__device__ int   g_hist     [NCHUNK * C_COMM];
__device__ int   g_chunkbase[NCHUNK * C_COMM];
__device__ int   g_counts [C_COMM];
__device__ int   g_offsets[C_COMM];
__device__ int   g_members[N_NODES];
__device__ float g_logc[C_COMM];
__device__ float g_inv [C_COMM];
__device__ float g_table[NDIST];

// ---------------- small PTX helpers (all sm_80-compatible) ----------------
__device__ __forceinline__ uint32_t smem_u32(const void* p) {
    uint32_t a;
    asm("{ .reg .u64 t; cvta.to.shared.u64 t, %1; cvt.u32.u64 %0, t; }" : "=r"(a) : "l"(p));
    return a;
}

__device__ __forceinline__ void cpa16(uint32_t dst, const void* src) {
    asm volatile("{ .reg .u64 g; cvta.to.global.u64 g, %1; cp.async.cg.shared.global [%0], [g], 16; }"
                 :: "r"(dst), "l"(src));
}
#define CP_COMMIT() asm volatile("cp.async.commit_group;" ::: "memory")
#define CP_WAIT1()  asm volatile("cp.async.wait_group 1;" ::: "memory")

__device__ __forceinline__ void ldm4(uint32_t* r, uint32_t addr) {
    asm volatile("ldmatrix.sync.aligned.m8n8.x4.shared.b16 {%0,%1,%2,%3}, [%4];"
                 : "=r"(r[0]), "=r"(r[1]), "=r"(r[2]), "=r"(r[3]) : "r"(addr));
}

__device__ __forceinline__ void mma_bf16(float* d, const uint32_t* a, const uint32_t* b) {
    asm volatile(
        "mma.sync.aligned.m16n8k16.row.col.f32.bf16.bf16.f32 "
        "{%0,%1,%2,%3}, {%4,%5,%6,%7}, {%8,%9}, {%0,%1,%2,%3};"
        : "+f"(d[0]), "+f"(d[1]), "+f"(d[2]), "+f"(d[3])
        : "r"(a[0]), "r"(a[1]), "r"(a[2]), "r"(a[3]), "r"(b[0]), "r"(b[1]));
}

// split fp32x4 -> bf16 hi quad + bf16 lo quad
__device__ __forceinline__ void split4(float4 v, uint2& H, uint2& L) {
    bf16 hx = __float2bfloat16(v.x), hy = __float2bfloat16(v.y);
    bf16 hz = __float2bfloat16(v.z), hw = __float2bfloat16(v.w);
    H.x = (uint32_t)__bfloat16_as_ushort(hx) | ((uint32_t)__bfloat16_as_ushort(hy) << 16);
    H.y = (uint32_t)__bfloat16_as_ushort(hz) | ((uint32_t)__bfloat16_as_ushort(hw) << 16);
    bf16 lx = __float2bfloat16(v.x - __bfloat162float(hx));
    bf16 ly = __float2bfloat16(v.y - __bfloat162float(hy));
    bf16 lz = __float2bfloat16(v.z - __bfloat162float(hz));
    bf16 lw = __float2bfloat16(v.w - __bfloat162float(hw));
    L.x = (uint32_t)__bfloat16_as_ushort(lx) | ((uint32_t)__bfloat16_as_ushort(ly) << 16);
    L.y = (uint32_t)__bfloat16_as_ushort(lz) | ((uint32_t)__bfloat16_as_ushort(lw) << 16);
}

__device__ __forceinline__ uint32_t pack_hi_lo(float a, float b, uint32_t& outlo) {
    bf16 ha = __float2bfloat16(a), hb = __float2bfloat16(b);
    bf16 la = __float2bfloat16(a - __bfloat162float(ha));
    bf16 lb = __float2bfloat16(b - __bfloat162float(hb));
    outlo = (uint32_t)__bfloat16_as_ushort(la) | ((uint32_t)__bfloat16_as_ushort(lb) << 16);
    return (uint32_t)__bfloat16_as_ushort(ha) | ((uint32_t)__bfloat16_as_ushort(hb) << 16);
}

// ---------------- warp-MMA GEMM on pre-split bf16 pairs ----------------
// C[M,N] = (Ah+Al)[M,K] . (Bh+Bl)[N,K]^T  (3-term split product)
// 3-stage cp.async pipeline. EPI==0: +bias; EPI==1: dots epilogue.
// Outputs: Cf (fp32, optional), Coh/Col (split bf16 pair, optional).
template<int BN, int EPI>
__global__ __launch_bounds__(256, 1)
void mma_gemm(int M, int K,
              const bf16* __restrict__ Ah, const bf16* __restrict__ Al, int lda, size_t zsA,
              const bf16* __restrict__ Bh, const bf16* __restrict__ Bl, int ldb, size_t zsB,
              const float* __restrict__ bias,
              float* __restrict__ Cf, bf16* __restrict__ Coh, bf16* __restrict__ Col,
              int ldc, size_t zsC,
              float scale, const float* __restrict__ logc,
              const float* __restrict__ table,
              const int* __restrict__ dm, int dmld)
{
    constexpr int BM  = 128;
    constexpr int LDS = 40;                  // bf16 elems per smem row (80B stride)
    constexpr int NW_N = BN / 32;
    constexpr int NW_M = 8 / NW_N;
    constexpr int WM  = BM / NW_M;
    constexpr int MI  = WM / 16;
    constexpr int NBT = BN * 4 / 256;        // B cp.async tasks per thread
    constexpr int ASZ = BM * LDS * 2;        // 10240 B
    constexpr int BSZ = BN * LDS * 2;
    constexpr int STAGE = 2 * ASZ + 2 * BSZ;

    extern __shared__ char smem[];
    const uint32_t uS = smem_u32(smem);

    Ah += (size_t)blockIdx.z * zsA;  Al += (size_t)blockIdx.z * zsA;
    Bh += (size_t)blockIdx.z * zsB;  Bl += (size_t)blockIdx.z * zsB;
    const int m0 = blockIdx.y * BM, n0 = blockIdx.x * BN;
    const int tid = threadIdx.x, lane = tid & 31, wid = tid >> 5;
    const int wm = wid % NW_M, wn = wid / NW_M;
    const int mbase = wm * WM, nbase = wn * 32;
    const int lr = lane & 15, lc8 = (lane >> 4) * 8;

    const int nch = K >> 5;

    auto issue = [&](int s, int kc) {
        const uint32_t sb = uS + (uint32_t)(s * STAGE);
        const int k0 = kc << 5;
        #pragma unroll
        for (int t = 0; t < 2; ++t) {
            int j = tid + t * 256, row = j >> 2, ck = j & 3;
            uint32_t off = (uint32_t)(row * 80 + ck * 16);
            size_t so = (size_t)(m0 + row) * lda + k0 + ck * 8;
            cpa16(sb + off,       Ah + so);
            cpa16(sb + ASZ + off, Al + so);
        }
        #pragma unroll
        for (int t = 0; t < NBT; ++t) {
            int j = tid + t * 256, row = j >> 2, ck = j & 3;
            uint32_t off = (uint32_t)(row * 80 + ck * 16);
            size_t so = (size_t)(n0 + row) * ldb + k0 + ck * 8;
            cpa16(sb + 2 * ASZ + off,       Bh + so);
            cpa16(sb + 2 * ASZ + BSZ + off, Bl + so);
        }
    };

    float acc[MI][4][4];
    #pragma unroll
    for (int mi = 0; mi < MI; ++mi)
        #pragma unroll
        for (int ni = 0; ni < 4; ++ni)
            #pragma unroll
            for (int q = 0; q < 4; ++q) acc[mi][ni][q] = 0.f;

    // prologue: stages 0,1
    issue(0, 0); CP_COMMIT();
    if (nch > 1) issue(1, 1);
    CP_COMMIT();

    for (int ch = 0; ch < nch; ++ch) {
        CP_WAIT1();
        __syncthreads();

        // issue chunk ch+2 into stage (ch+2)%3 (stage consumed at iter ch-1; all warps past it)
        int nx = ch + 2;
        if (nx < nch) issue(nx % 3, nx);
        CP_COMMIT();

        const uint32_t sb = uS + (uint32_t)((ch % 3) * STAGE);
        const uint32_t uAh = sb, uAl = sb + ASZ, uBh = sb + 2 * ASZ, uBl = sb + 2 * ASZ + BSZ;
        #pragma unroll
        for (int ks = 0; ks < 2; ++ks) {
            uint32_t ah[MI][4], al[MI][4];
            #pragma unroll
            for (int mi = 0; mi < MI; ++mi) {
                uint32_t off = (uint32_t)((mbase + mi * 16 + lr) * LDS + ks * 16 + lc8) * 2;
                ldm4(ah[mi], uAh + off);
                ldm4(al[mi], uAl + off);
            }
            uint32_t bh[4][2], bl[4][2], r[4];
            uint32_t off0 = (uint32_t)((nbase + lr) * LDS + ks * 16 + lc8) * 2;
            uint32_t off1 = (uint32_t)((nbase + 16 + lr) * LDS + ks * 16 + lc8) * 2;
            ldm4(r, uBh + off0); bh[0][0] = r[0]; bh[0][1] = r[2]; bh[1][0] = r[1]; bh[1][1] = r[3];
            ldm4(r, uBh + off1); bh[2][0] = r[0]; bh[2][1] = r[2]; bh[3][0] = r[1]; bh[3][1] = r[3];
            ldm4(r, uBl + off0); bl[0][0] = r[0]; bl[0][1] = r[2]; bl[1][0] = r[1]; bl[1][1] = r[3];
            ldm4(r, uBl + off1); bl[2][0] = r[0]; bl[2][1] = r[2]; bl[3][0] = r[1]; bl[3][1] = r[3];
            #pragma unroll
            for (int mi = 0; mi < MI; ++mi)
                #pragma unroll
                for (int ni = 0; ni < 4; ++ni) {
                    mma_bf16(acc[mi][ni], ah[mi], bh[ni]);
                    mma_bf16(acc[mi][ni], ah[mi], bl[ni]);
                    mma_bf16(acc[mi][ni], al[mi], bh[ni]);
                }
        }
        __syncthreads();
    }

    // epilogue
    #pragma unroll
    for (int mi = 0; mi < MI; ++mi) {
        int r0 = m0 + mbase + mi * 16 + (lane >> 2);
        #pragma unroll
        for (int ni = 0; ni < 4; ++ni) {
            int cc = n0 + nbase + ni * 8 + (lane & 3) * 2;
            float d0 = acc[mi][ni][0], d1 = acc[mi][ni][1];
            float d2 = acc[mi][ni][2], d3 = acc[mi][ni][3];
            if (EPI == 0) {
                if (bias) {
                    float b0 = bias[cc], b1 = bias[cc + 1];
                    d0 += b0; d1 += b1; d2 += b0; d3 += b1;
                }
            } else {
                float lg0 = logc[cc], lg1 = logc[cc + 1];
                int e0 = dm[(size_t)r0 * dmld + cc],       e1 = dm[(size_t)r0 * dmld + cc + 1];
                int e2 = dm[(size_t)(r0 + 8) * dmld + cc], e3 = dm[(size_t)(r0 + 8) * dmld + cc + 1];
                d0 = d0 * scale + lg0 + table[e0];
                d1 = d1 * scale + lg1 + table[e1];
                d2 = d2 * scale + lg0 + table[e2];
                d3 = d3 * scale + lg1 + table[e3];
            }
            size_t o0 = (size_t)blockIdx.z * zsC + (size_t)r0 * ldc + cc;
            size_t o1 = (size_t)blockIdx.z * zsC + (size_t)(r0 + 8) * ldc + cc;
            if (Cf) {
                *reinterpret_cast<float2*>(Cf + o0) = make_float2(d0, d1);
                *reinterpret_cast<float2*>(Cf + o1) = make_float2(d2, d3);
            }
            if (Coh) {
                uint32_t lo0, lo1;
                uint32_t hi0 = pack_hi_lo(d0, d1, lo0);
                uint32_t hi1 = pack_hi_lo(d2, d3, lo1);
                *reinterpret_cast<uint32_t*>(Coh + o0) = hi0;
                *reinterpret_cast<uint32_t*>(Col + o0) = lo0;
                *reinterpret_cast<uint32_t*>(Coh + o1) = hi1;
                *reinterpret_cast<uint32_t*>(Col + o1) = lo1;
            }
        }
    }
}

// ---------------- split fp32 -> bf16 pair (elementwise) ----------------
__global__ void split_kernel(const float4* __restrict__ in, uint2* __restrict__ outH,
                             uint2* __restrict__ outL, int n4) {
    int i = blockIdx.x * blockDim.x + threadIdx.x;
    if (i < n4) {
        uint2 H, L; split4(in[i], H, L);
        outH[i] = H; outL[i] = L;
    }
}

// ---------------- transpose + split: out[C,R] (bf16 pair) = in[R,C]^T ----------------
__global__ void transpose_split_kernel(const float* __restrict__ in,
                                       bf16* __restrict__ outH, bf16* __restrict__ outL,
                                       int R, int Ccols) {
    __shared__ float tile[32][33];
    int c0 = blockIdx.x * 32, r0 = blockIdx.y * 32;
    int x = threadIdx.x, y = threadIdx.y;           // 32 x 8
    #pragma unroll
    for (int j = 0; j < 32; j += 8)
        tile[y + j][x] = in[(size_t)(r0 + y + j) * Ccols + c0 + x];
    __syncthreads();
    #pragma unroll
    for (int j = 0; j < 32; j += 8) {
        float v = tile[x][y + j];
        bf16 h = __float2bfloat16(v);
        bf16 l = __float2bfloat16(v - __bfloat162float(h));
        size_t o = (size_t)(c0 + y + j) * R + r0 + x;
        outH[o] = h; outL[o] = l;
    }
}

// ---------------- fused q bias ----------------
__global__ void fuse_bias_kernel(const float* __restrict__ bproj,
                                 const float* __restrict__ Wq,
                                 const float* __restrict__ bq,
                                 float* __restrict__ out) {
    int o = blockIdx.x * blockDim.x + threadIdx.x;
    float s = bq[o];
    for (int k = 0; k < HID; k++) s += bproj[k] * Wq[(size_t)k * HID + o];
    out[o] = s;
}

// ---------------- community preprocessing (deterministic, stable) ----------------
__global__ void hist_kernel(const int* __restrict__ ntc) {
    __shared__ int sh[C_COMM];
    int chunk = blockIdx.x;
    for (int i = threadIdx.x; i < C_COMM; i += blockDim.x) sh[i] = 0;
    __syncthreads();
    atomicAdd(&sh[ntc[chunk * CHUNK + threadIdx.x]], 1);
    __syncthreads();
    for (int i = threadIdx.x; i < C_COMM; i += blockDim.x)
        g_hist[chunk * C_COMM + i] = sh[i];
}

__global__ void chunk_scan_kernel() {
    int c = blockIdx.x;
    __shared__ int s[NCHUNK];
    int t = threadIdx.x;
    int own = g_hist[t * C_COMM + c];
    s[t] = own;
    __syncthreads();
    for (int off = 1; off < NCHUNK; off <<= 1) {
        int v = (t >= off) ? s[t - off] : 0;
        __syncthreads();
        s[t] += v;
        __syncthreads();
    }
    g_chunkbase[t * C_COMM + c] = s[t] - own;
    if (t == NCHUNK - 1) g_counts[c] = s[t];
}

__global__ void offsets_kernel() {
    __shared__ int s[C_COMM];
    int t = threadIdx.x;
    int own = g_counts[t];
    s[t] = own;
    __syncthreads();
    for (int off = 1; off < C_COMM; off <<= 1) {
        int v = (t >= off) ? s[t - off] : 0;
        __syncthreads();
        s[t] += v;
        __syncthreads();
    }
    g_offsets[t] = s[t] - own;
    g_logc[t]    = logf((float)own);
    g_inv[t]     = 1.0f / (float)(own > 0 ? own : 1);
}

__global__ void scatter_kernel(const int* __restrict__ ntc) {
    __shared__ int s[CHUNK];
    int chunk = blockIdx.x;
    int t = threadIdx.x;
    int node = chunk * CHUNK + t;
    int c = ntc[node];
    s[t] = c;
    __syncthreads();
    int lrank = 0;
    for (int j = 0; j < t; j++) lrank += (s[j] == c);
    g_members[g_offsets[c] + g_chunkbase[chunk * C_COMM + c] + lrank] = node;
}

// mean of member rows of g_h (deterministic order) -> split bf16 pair
__global__ void comm_avg_kernel() {
    int c = blockIdx.x;
    int t = threadIdx.x;                 // 256 threads, 2 cols each
    int off = g_offsets[c], cnt = g_counts[c];
    float a0 = 0.f, a1 = 0.f;
    for (int m = 0; m < cnt; m++) {
        const float* row = g_h + (size_t)g_members[off + m] * HID;
        a0 += row[t];
        a1 += row[t + 256];
    }
    float inv = g_inv[c];
    a0 *= inv; a1 *= inv;
    bf16 h0 = __float2bfloat16(a0), h1 = __float2bfloat16(a1);
    g_cmh[c * HID + t]       = h0;
    g_cmh[c * HID + t + 256] = h1;
    g_cml[c * HID + t]       = __float2bfloat16(a0 - __bfloat162float(h0));
    g_cml[c * HID + t + 256] = __float2bfloat16(a1 - __bfloat162float(h1));
}

__global__ void bias_table_kernel(const float* __restrict__ emb,
                                  const float* __restrict__ w,
                                  const float* __restrict__ bptr) {
    int i = blockIdx.x;
    int t = threadIdx.x;
    float s = emb[i * HID + t]       * w[t]
            + emb[i * HID + t + 128] * w[t + 128]
            + emb[i * HID + t + 256] * w[t + 256]
            + emb[i * HID + t + 384] * w[t + 384];
    for (int o = 16; o; o >>= 1) s += __shfl_xor_sync(0xFFFFFFFFu, s, o);
    __shared__ float r[4];
    if ((t & 31) == 0) r[t >> 5] = s;
    __syncthreads();
    if (t == 0) g_table[i] = r[0] + r[1] + r[2] + r[3] + bptr[0];
}

// LayerNorm + ReLU; writes fp32 (optional) + bf16 split pair
__global__ void ln_relu_kernel(const float* __restrict__ in, float* __restrict__ outF,
                               bf16* __restrict__ outH, bf16* __restrict__ outL,
                               const float* __restrict__ g, const float* __restrict__ b) {
    size_t row = blockIdx.x;
    int t = threadIdx.x;
    const float* x = in + row * HID;
    float v0 = x[t], v1 = x[t + 256];
    float s = v0 + v1, q = v0 * v0 + v1 * v1;
    for (int o = 16; o; o >>= 1) {
        s += __shfl_xor_sync(0xFFFFFFFFu, s, o);
        q += __shfl_xor_sync(0xFFFFFFFFu, q, o);
    }
    __shared__ float rs[8], rq[8];
    int w = t >> 5, lane = t & 31;
    if (lane == 0) { rs[w] = s; rq[w] = q; }
    __syncthreads();
    __shared__ float smean, srstd;
    if (t == 0) {
        float ts = 0.f, tq = 0.f;
        for (int i = 0; i < 8; i++) { ts += rs[i]; tq += rq[i]; }
        float mean = ts * (1.0f / HID);
        float var  = tq * (1.0f / HID) - mean * mean;
        smean = mean;
        srstd = rsqrtf(var + EPS);
    }
    __syncthreads();
    float mean = smean, rstd = srstd;
    float y0 = fmaxf((v0 - mean) * rstd * g[t]       + b[t],       0.f);
    float y1 = fmaxf((v1 - mean) * rstd * g[t + 256] + b[t + 256], 0.f);
    size_t o0 = row * HID + t, o1 = row * HID + t + 256;
    if (outF) { outF[o0] = y0; outF[o1] = y1; }
    bf16 h0 = __float2bfloat16(y0), h1 = __float2bfloat16(y1);
    outH[o0] = h0; outH[o1] = h1;
    outL[o0] = __float2bfloat16(y0 - __bfloat162float(h0));
    outL[o1] = __float2bfloat16(y1 - __bfloat162float(h1));
}

// softmax over C=512: reads fp32 dots, writes bf16 split probs
__global__ void softmax_kernel(const float* __restrict__ dots,
                               bf16* __restrict__ ph, bf16* __restrict__ pl) {
    size_t row = (size_t)blockIdx.x;
    const float* p = dots + row * C_COMM;
    int t = threadIdx.x;
    float v0 = p[t], v1 = p[t + 256];
    float m = fmaxf(v0, v1);
    for (int o = 16; o; o >>= 1) m = fmaxf(m, __shfl_xor_sync(0xFFFFFFFFu, m, o));
    __shared__ float rm[8];
    int w = t >> 5, lane = t & 31;
    if (lane == 0) rm[w] = m;
    __syncthreads();
    __shared__ float smax;
    if (t == 0) {
        float mm = rm[0];
        for (int i = 1; i < 8; i++) mm = fmaxf(mm, rm[i]);
        smax = mm;
    }
    __syncthreads();
    m = smax;
    float e0 = __expf(v0 - m), e1 = __expf(v1 - m);
    float s = e0 + e1;
    for (int o = 16; o; o >>= 1) s += __shfl_xor_sync(0xFFFFFFFFu, s, o);
    __shared__ float rsum[8];
    if (lane == 0) rsum[w] = s;
    __syncthreads();
    __shared__ float stot;
    if (t == 0) {
        float ts = 0.f;
        for (int i = 0; i < 8; i++) ts += rsum[i];
        stot = ts;
    }
    __syncthreads();
    float inv = 1.0f / stot;
    float q0 = e0 * inv, q1 = e1 * inv;
    size_t o0 = row * C_COMM + t, o1 = row * C_COMM + t + 256;
    bf16 h0 = __float2bfloat16(q0), h1 = __float2bfloat16(q1);
    ph[o0] = h0; ph[o1] = h1;
    pl[o0] = __float2bfloat16(q0 - __bfloat162float(h0));
    pl[o1] = __float2bfloat16(q1 - __bfloat162float(h1));
}

// ---------------- host-side helpers ----------------
static const int SMEM_128 = 3 * (2 * 128 * 80 + 2 * 128 * 80); // 122880
static const int SMEM_64  = 3 * (2 * 128 * 80 + 2 * 64 * 80);  // 92160

static void tc_nn(int M, int Nc, int K,
                  const bf16* Ah, const bf16* Al, int lda,
                  const bf16* Bth, const bf16* Btl,
                  const float* bias,
                  float* Cf, bf16* Coh, bf16* Col, int ldc)
{
    if (Nc % 128 == 0) {
        dim3 g(Nc / 128, M / 128, 1);
        mma_gemm<128, 0><<<g, 256, SMEM_128>>>(M, K, Ah, Al, lda, 0, Bth, Btl, K, 0,
                                               bias, Cf, Coh, Col, ldc, 0,
                                               0.f, nullptr, nullptr, nullptr, 0);
    } else { // Nc == 64
        dim3 g(1, M / 128, 1);
        mma_gemm<64, 0><<<g, 256, SMEM_64>>>(M, K, Ah, Al, lda, 0, Bth, Btl, K, 0,
                                             bias, Cf, Coh, Col, ldc, 0,
                                             0.f, nullptr, nullptr, nullptr, 0);
    }
}

static void do_transpose_split(const float* in, bf16* outH, bf16* outL, int R, int C) {
    dim3 g(C / 32, R / 32), b(32, 8);
    transpose_split_kernel<<<g, b>>>(in, outH, outL, R, C);
}

extern "C" void kernel_launch(void* const* d_in, const int* in_sizes, int n_in,
                              void* d_out, int out_size)
{
    // ---- input mapping (auto-detect metadata order) ----
    const float *x      = (const float*)d_in[0];
    const int   *dm     = (const int*)  d_in[1];
    const int   *ntc    = (const int*)  d_in[2];
    const float *W_in1  = (const float*)d_in[3];
    const float *b_in1  = (const float*)d_in[4];
    const float *ln_in_g= (const float*)d_in[5];
    const float *ln_in_b= (const float*)d_in[6];
    const float *W_in2  = (const float*)d_in[7];
    const float *b_in2  = (const float*)d_in[8];
    const float *Wproj, *Wq, *Wk, *Wv, *ffW1, *ffW2;
    const float *bproj, *bq, *bk, *bv, *ffb1, *ffb2;
    const float *dis_emb, *dis_w, *dis_b;
    const float *ffg1, *ffbeta1, *ffg2, *ffbeta2, *Wout, *bout;

    if (in_sizes[10] == NLAYER * HID * HID) {
        Wproj  = (const float*)d_in[9];  Wq     = (const float*)d_in[10];
        Wk     = (const float*)d_in[11]; Wv     = (const float*)d_in[12];
        ffW1   = (const float*)d_in[13]; ffW2   = (const float*)d_in[14];
        bproj  = (const float*)d_in[15]; bq     = (const float*)d_in[16];
        bk     = (const float*)d_in[17]; bv     = (const float*)d_in[18];
        ffb1   = (const float*)d_in[19]; ffb2   = (const float*)d_in[20];
        dis_emb= (const float*)d_in[21]; dis_w  = (const float*)d_in[22];
        dis_b  = (const float*)d_in[23];
        ffg1   = (const float*)d_in[24]; ffbeta1= (const float*)d_in[25];
        ffg2   = (const float*)d_in[26]; ffbeta2= (const float*)d_in[27];
        Wout   = (const float*)d_in[28]; bout   = (const float*)d_in[29];
    } else {
        Wproj  = (const float*)d_in[9];  bproj  = (const float*)d_in[10];
        Wq     = (const float*)d_in[11]; bq     = (const float*)d_in[12];
        Wk     = (const float*)d_in[13]; bk     = (const float*)d_in[14];
        Wv     = (const float*)d_in[15]; bv     = (const float*)d_in[16];
        dis_emb= (const float*)d_in[17]; dis_w  = (const float*)d_in[18];
        dis_b  = (const float*)d_in[19];
        ffW1   = (const float*)d_in[20]; ffb1   = (const float*)d_in[21];
        ffg1   = (const float*)d_in[22]; ffbeta1= (const float*)d_in[23];
        ffW2   = (const float*)d_in[24]; ffb2   = (const float*)d_in[25];
        ffg2   = (const float*)d_in[26]; ffbeta2= (const float*)d_in[27];
        Wout   = (const float*)d_in[28]; bout   = (const float*)d_in[29];
    }

    cudaFuncSetAttribute(mma_gemm<128, 0>, cudaFuncAttributeMaxDynamicSharedMemorySize, SMEM_128);
    cudaFuncSetAttribute(mma_gemm<128, 1>, cudaFuncAttributeMaxDynamicSharedMemorySize, SMEM_128);
    cudaFuncSetAttribute(mma_gemm<64, 0>,  cudaFuncAttributeMaxDynamicSharedMemorySize, SMEM_64);

    // ---- scratch pointers ----
    float *p_h, *p_t0, *p_t1, *p_dots, *p_v, *p_logc, *p_table, *p_bfq;
    bf16 *p_xh, *p_xl, *p_hh, *p_hl, *p_t0h, *p_t0l, *p_t1h, *p_t1l, *p_qh, *p_ql;
    bf16 *p_ph, *p_pl, *p_cmh, *p_cml, *p_kh, *p_kl, *p_vth, *p_vtl, *p_wh, *p_wl;
    cudaGetSymbolAddress((void**)&p_h,    g_h);
    cudaGetSymbolAddress((void**)&p_t0,   g_t0);
    cudaGetSymbolAddress((void**)&p_t1,   g_t1);
    cudaGetSymbolAddress((void**)&p_dots, g_dots);
    cudaGetSymbolAddress((void**)&p_v,    g_v);
    cudaGetSymbolAddress((void**)&p_logc, g_logc);
    cudaGetSymbolAddress((void**)&p_table,g_table);
    cudaGetSymbolAddress((void**)&p_bfq,  g_bfq);
    cudaGetSymbolAddress((void**)&p_xh,  g_xh);  cudaGetSymbolAddress((void**)&p_xl,  g_xl);
    cudaGetSymbolAddress((void**)&p_hh,  g_hh);  cudaGetSymbolAddress((void**)&p_hl,  g_hl);
    cudaGetSymbolAddress((void**)&p_t0h, g_t0h); cudaGetSymbolAddress((void**)&p_t0l, g_t0l);
    cudaGetSymbolAddress((void**)&p_t1h, g_t1h); cudaGetSymbolAddress((void**)&p_t1l, g_t1l);
    cudaGetSymbolAddress((void**)&p_qh,  g_qh);  cudaGetSymbolAddress((void**)&p_ql,  g_ql);
    cudaGetSymbolAddress((void**)&p_ph,  g_ph);  cudaGetSymbolAddress((void**)&p_pl,  g_pl);
    cudaGetSymbolAddress((void**)&p_cmh, g_cmh); cudaGetSymbolAddress((void**)&p_cml, g_cml);
    cudaGetSymbolAddress((void**)&p_kh,  g_kh);  cudaGetSymbolAddress((void**)&p_kl,  g_kl);
    cudaGetSymbolAddress((void**)&p_vth, g_vth); cudaGetSymbolAddress((void**)&p_vtl, g_vtl);
    cudaGetSymbolAddress((void**)&p_wh,  g_wh);  cudaGetSymbolAddress((void**)&p_wl,  g_wl);
    #define WH(i) (p_wh + (size_t)(i) * HID * HID)
    #define WL(i) (p_wl + (size_t)(i) * HID * HID)

    const float scale = 1.0f / sqrtf((float)DHEAD);

    // ---- weight preprocessing ----
    // slots: 0=W_in1T 1=W_in2T; per layer l: 2+l*5+{0:WfqT,1:WkT,2:WvT,3:ffW1T,4:ffW2T};
    // 12=WoutT; 13=tmp WqT; 14=tmp Wproj(raw split)
    do_transpose_split(W_in1, WH(0), WL(0), IN_DIM, HID);
    do_transpose_split(W_in2, WH(1), WL(1), HID, HID);
    split_kernel<<<N_NODES * IN_DIM / 1024, 256>>>((const float4*)x, (uint2*)p_xh, (uint2*)p_xl,
                                                   N_NODES * IN_DIM / 4);
    for (int l = 0; l < NLAYER; l++) {
        const size_t wo = (size_t)l * HID * HID;
        int s0 = 2 + l * 5;
        // fused q weight: WfqT[o,i] = sum_k WqT[o,k] * Wproj[i,k]
        do_transpose_split(Wq + wo, WH(13), WL(13), HID, HID);
        split_kernel<<<HID * HID / 1024, 256>>>((const float4*)(Wproj + wo),
                                                (uint2*)WH(14), (uint2*)WL(14), HID * HID / 4);
        {
            dim3 g(HID / 128, HID / 128, 1);
            mma_gemm<128, 0><<<g, 256, SMEM_128>>>(HID, HID,
                                                   WH(13), WL(13), HID, 0,
                                                   WH(14), WL(14), HID, 0,
                                                   nullptr, nullptr, WH(s0), WL(s0), HID, 0,
                                                   0.f, nullptr, nullptr, nullptr, 0);
        }
        fuse_bias_kernel<<<HID / 256, 256>>>(bproj + (size_t)l * HID, Wq + wo,
                                             bq + (size_t)l * HID, p_bfq + (size_t)l * HID);
        do_transpose_split(Wk   + wo, WH(s0 + 1), WL(s0 + 1), HID, HID);
        do_transpose_split(Wv   + wo, WH(s0 + 2), WL(s0 + 2), HID, HID);
        do_transpose_split(ffW1 + wo, WH(s0 + 3), WL(s0 + 3), HID, HID);
        do_transpose_split(ffW2 + wo, WH(s0 + 4), WL(s0 + 4), HID, HID);
    }
    do_transpose_split(Wout, WH(12), WL(12), HID, OUT_DIM);   // -> [64,512]

    // ---- community preprocessing (deterministic) ----
    hist_kernel      <<<NCHUNK, CHUNK>>>(ntc);
    chunk_scan_kernel<<<C_COMM, NCHUNK>>>();
    offsets_kernel   <<<1, C_COMM>>>();
    scatter_kernel   <<<NCHUNK, CHUNK>>>(ntc);

    // ---- fc_in ----
    tc_nn(N_NODES, HID, IN_DIM, p_xh, p_xl, IN_DIM, WH(0), WL(0), b_in1,
          p_t0, nullptr, nullptr, HID);
    ln_relu_kernel<<<N_NODES, 256>>>(p_t0, nullptr, p_t0h, p_t0l, ln_in_g, ln_in_b);
    tc_nn(N_NODES, HID, HID, p_t0h, p_t0l, HID, WH(1), WL(1), b_in2,
          p_h, p_hh, p_hl, HID);

    // ---- layers ----
    for (int l = 0; l < NLAYER; l++) {
        int s0 = 2 + l * 5;
        bias_table_kernel<<<NDIST, 128>>>(dis_emb + (size_t)l * NDIST * HID,
                                          dis_w + (size_t)l * HID, dis_b + l);
        comm_avg_kernel<<<C_COMM, 256>>>();

        // q = h @ WfqT^T + bfq  (split out only)
        tc_nn(N_NODES, HID, HID, p_hh, p_hl, HID, WH(s0), WL(s0),
              p_bfq + (size_t)l * HID, nullptr, p_qh, p_ql, HID);
        // k (split only), v (fp32, for transpose)
        tc_nn(C_COMM, HID, HID, p_cmh, p_cml, HID, WH(s0 + 1), WL(s0 + 1),
              bk + (size_t)l * HID, nullptr, p_kh, p_kl, HID);
        tc_nn(C_COMM, HID, HID, p_cmh, p_cml, HID, WH(s0 + 2), WL(s0 + 2),
              bv + (size_t)l * HID, p_v, nullptr, nullptr, HID);
        do_transpose_split(p_v, p_vth, p_vtl, C_COMM, HID);   // vT [HID, C] split

        // dots per head (z), fused epilogue -> fp32
        {
            dim3 g(C_COMM / 128, N_NODES / 128, NHEAD);
            mma_gemm<128, 1><<<g, 256, SMEM_128>>>(
                N_NODES, DHEAD,
                p_qh, p_ql, HID, (size_t)DHEAD,
                p_kh, p_kl, HID, (size_t)DHEAD,
                nullptr,
                p_dots, nullptr, nullptr, C_COMM, (size_t)N_NODES * C_COMM,
                scale, p_logc, p_table, dm, C_COMM);
        }
        softmax_kernel<<<NHEAD * N_NODES, 256>>>(p_dots, p_ph, p_pl);

        // AV per head -> t0 split only
        {
            dim3 g(1, N_NODES / 128, NHEAD);
            mma_gemm<128, 0><<<g, 256, SMEM_128>>>(
                N_NODES, C_COMM,
                p_ph, p_pl, C_COMM, (size_t)N_NODES * C_COMM,
                p_vth, p_vtl, C_COMM, (size_t)DHEAD * C_COMM,
                nullptr,
                nullptr, p_t0h, p_t0l, HID, (size_t)DHEAD,
                0.f, nullptr, nullptr, nullptr, 0);
        }

        tc_nn(N_NODES, HID, HID, p_t0h, p_t0l, HID, WH(s0 + 3), WL(s0 + 3),
              ffb1 + (size_t)l * HID, p_t1, nullptr, nullptr, HID);
        ln_relu_kernel<<<N_NODES, 256>>>(p_t1, nullptr, p_t1h, p_t1l,
                                         ffg1 + (size_t)l * HID, ffbeta1 + (size_t)l * HID);
        tc_nn(N_NODES, HID, HID, p_t1h, p_t1l, HID, WH(s0 + 4), WL(s0 + 4),
              ffb2 + (size_t)l * HID, p_t0, nullptr, nullptr, HID);
        ln_relu_kernel<<<N_NODES, 256>>>(p_t0, p_h, p_hh, p_hl,
                                         ffg2 + (size_t)l * HID, ffbeta2 + (size_t)l * HID);
    }

    // ---- output projection ----
    tc_nn(N_NODES, OUT_DIM, HID, p_hh, p_hl, HID, WH(12), WL(12), bout,
          (float*)d_out, nullptr, nullptr, OUT_DIM);
}

// round 9
// speedup vs baseline: 2.3213x; 1.1126x over previous
#include <cuda_runtime.h>
#include <cuda_bf16.h>
#include <math.h>
#include <stdint.h>

// ---------------- problem constants ----------------
#define N_NODES 32768
#define C_COMM  512
#define IN_DIM  128
#define HID     512
#define NHEAD   4
#define DHEAD   128
#define NLAYER  2
#define OUT_DIM 64
#define NDIST   31
#define EPS     1e-5f

#define CHUNK   256
#define NCHUNK  (N_NODES / CHUNK)   // 128

typedef __nv_bfloat16 bf16;

// ---------------- scratch (device globals; no allocation allowed) ----------------
__device__ float g_h   [N_NODES * HID];
__device__ float g_t0  [N_NODES * HID];
__device__ float g_t1  [N_NODES * HID];
__device__ float g_dots[(size_t)NHEAD * N_NODES * C_COMM];
__device__ float g_v   [C_COMM * HID];
__device__ float g_bfq [NLAYER * HID];

__device__ bf16 g_xh [N_NODES * IN_DIM], g_xl [N_NODES * IN_DIM];
__device__ bf16 g_hh [N_NODES * HID],    g_hl [N_NODES * HID];
__device__ bf16 g_t0h[N_NODES * HID],    g_t0l[N_NODES * HID];
__device__ bf16 g_t1h[N_NODES * HID],    g_t1l[N_NODES * HID];
__device__ bf16 g_qh [N_NODES * HID],    g_ql [N_NODES * HID];
__device__ bf16 g_ph [(size_t)NHEAD * N_NODES * C_COMM];
__device__ bf16 g_pl [(size_t)NHEAD * N_NODES * C_COMM];
__device__ bf16 g_cmh[C_COMM * HID],     g_cml[C_COMM * HID];
__device__ bf16 g_kh [C_COMM * HID],     g_kl [C_COMM * HID];
__device__ bf16 g_vth[HID * C_COMM],     g_vtl[HID * C_COMM];
__device__ bf16 g_wh [15][HID * HID],    g_wl [15][HID * HID];

__device__ int   g_hist     [NCHUNK * C_COMM];
__device__ int   g_chunkbase[NCHUNK * C_COMM];
__device__ int   g_counts [C_COMM];
__device__ int   g_offsets[C_COMM];
__device__ int   g_members[N_NODES];
__device__ float g_logc[C_COMM];
__device__ float g_inv [C_COMM];
__device__ float g_table[NDIST];

// ---------------- small PTX helpers (all sm_80-compatible) ----------------
__device__ __forceinline__ uint32_t smem_u32(const void* p) {
    uint32_t a;
    asm("{ .reg .u64 t; cvta.to.shared.u64 t, %1; cvt.u32.u64 %0, t; }" : "=r"(a) : "l"(p));
    return a;
}

__device__ __forceinline__ void cpa16(uint32_t dst, const void* src) {
    asm volatile("{ .reg .u64 g; cvta.to.global.u64 g, %1; cp.async.cg.shared.global [%0], [g], 16; }"
                 :: "r"(dst), "l"(src));
}
#define CP_COMMIT() asm volatile("cp.async.commit_group;" ::: "memory")
#define CP_WAIT1()  asm volatile("cp.async.wait_group 1;" ::: "memory")

__device__ __forceinline__ void ldm4(uint32_t* r, uint32_t addr) {
    asm volatile("ldmatrix.sync.aligned.m8n8.x4.shared.b16 {%0,%1,%2,%3}, [%4];"
                 : "=r"(r[0]), "=r"(r[1]), "=r"(r[2]), "=r"(r[3]) : "r"(addr));
}

__device__ __forceinline__ void mma_bf16(float* d, const uint32_t* a, const uint32_t* b) {
    asm volatile(
        "mma.sync.aligned.m16n8k16.row.col.f32.bf16.bf16.f32 "
        "{%0,%1,%2,%3}, {%4,%5,%6,%7}, {%8,%9}, {%0,%1,%2,%3};"
        : "+f"(d[0]), "+f"(d[1]), "+f"(d[2]), "+f"(d[3])
        : "r"(a[0]), "r"(a[1]), "r"(a[2]), "r"(a[3]), "r"(b[0]), "r"(b[1]));
}

// split fp32x4 -> bf16 hi quad + bf16 lo quad
__device__ __forceinline__ void split4(float4 v, uint2& H, uint2& L) {
    bf16 hx = __float2bfloat16(v.x), hy = __float2bfloat16(v.y);
    bf16 hz = __float2bfloat16(v.z), hw = __float2bfloat16(v.w);
    H.x = (uint32_t)__bfloat16_as_ushort(hx) | ((uint32_t)__bfloat16_as_ushort(hy) << 16);
    H.y = (uint32_t)__bfloat16_as_ushort(hz) | ((uint32_t)__bfloat16_as_ushort(hw) << 16);
    bf16 lx = __float2bfloat16(v.x - __bfloat162float(hx));
    bf16 ly = __float2bfloat16(v.y - __bfloat162float(hy));
    bf16 lz = __float2bfloat16(v.z - __bfloat162float(hz));
    bf16 lw = __float2bfloat16(v.w - __bfloat162float(hw));
    L.x = (uint32_t)__bfloat16_as_ushort(lx) | ((uint32_t)__bfloat16_as_ushort(ly) << 16);
    L.y = (uint32_t)__bfloat16_as_ushort(lz) | ((uint32_t)__bfloat16_as_ushort(lw) << 16);
}

__device__ __forceinline__ uint32_t pack_hi_lo(float a, float b, uint32_t& outlo) {
    bf16 ha = __float2bfloat16(a), hb = __float2bfloat16(b);
    bf16 la = __float2bfloat16(a - __bfloat162float(ha));
    bf16 lb = __float2bfloat16(b - __bfloat162float(hb));
    outlo = (uint32_t)__bfloat16_as_ushort(la) | ((uint32_t)__bfloat16_as_ushort(lb) << 16);
    return (uint32_t)__bfloat16_as_ushort(ha) | ((uint32_t)__bfloat16_as_ushort(hb) << 16);
}

// ---------------- warp-MMA GEMM on pre-split bf16 pairs ----------------
// C[M,N] = (Ah+Al)[M,K] . (Bh+Bl)[N,K]^T  (3-term split product)
// BM=128 x BN=64 tile, 8 warps (4 m x 2 n), 3-stage cp.async pipeline,
// 2 CTAs per SM (launch_bounds min-blocks 2; smem 92160 B/CTA).
// EPI==0: +bias; EPI==1: dots epilogue.
template<int BN, int EPI>
__global__ __launch_bounds__(256, 2)
void mma_gemm(int M, int K,
              const bf16* __restrict__ Ah, const bf16* __restrict__ Al, int lda, size_t zsA,
              const bf16* __restrict__ Bh, const bf16* __restrict__ Bl, int ldb, size_t zsB,
              const float* __restrict__ bias,
              float* __restrict__ Cf, bf16* __restrict__ Coh, bf16* __restrict__ Col,
              int ldc, size_t zsC,
              float scale, const float* __restrict__ logc,
              const float* __restrict__ table,
              const int* __restrict__ dm, int dmld)
{
    constexpr int BM  = 128;
    constexpr int LDS = 40;                  // bf16 elems per smem row (80B stride)
    constexpr int NW_N = BN / 32;            // 2
    constexpr int NW_M = 8 / NW_N;           // 4
    constexpr int WM  = BM / NW_M;           // 32
    constexpr int MI  = WM / 16;             // 2
    constexpr int NBT = BN * 4 / 256;        // 1
    constexpr int ASZ = BM * LDS * 2;        // 10240 B
    constexpr int BSZ = BN * LDS * 2;        // 5120 B
    constexpr int STAGE = 2 * ASZ + 2 * BSZ; // 30720 B

    extern __shared__ char smem[];
    const uint32_t uS = smem_u32(smem);

    Ah += (size_t)blockIdx.z * zsA;  Al += (size_t)blockIdx.z * zsA;
    Bh += (size_t)blockIdx.z * zsB;  Bl += (size_t)blockIdx.z * zsB;
    const int m0 = blockIdx.y * BM, n0 = blockIdx.x * BN;
    const int tid = threadIdx.x, lane = tid & 31, wid = tid >> 5;
    const int wm = wid % NW_M, wn = wid / NW_M;
    const int mbase = wm * WM, nbase = wn * 32;
    const int lr = lane & 15, lc8 = (lane >> 4) * 8;

    const int nch = K >> 5;

    auto issue = [&](int s, int kc) {
        const uint32_t sb = uS + (uint32_t)(s * STAGE);
        const int k0 = kc << 5;
        #pragma unroll
        for (int t = 0; t < 2; ++t) {
            int j = tid + t * 256, row = j >> 2, ck = j & 3;
            uint32_t off = (uint32_t)(row * 80 + ck * 16);
            size_t so = (size_t)(m0 + row) * lda + k0 + ck * 8;
            cpa16(sb + off,       Ah + so);
            cpa16(sb + ASZ + off, Al + so);
        }
        #pragma unroll
        for (int t = 0; t < NBT; ++t) {
            int j = tid + t * 256, row = j >> 2, ck = j & 3;
            uint32_t off = (uint32_t)(row * 80 + ck * 16);
            size_t so = (size_t)(n0 + row) * ldb + k0 + ck * 8;
            cpa16(sb + 2 * ASZ + off,       Bh + so);
            cpa16(sb + 2 * ASZ + BSZ + off, Bl + so);
        }
    };

    float acc[MI][4][4];
    #pragma unroll
    for (int mi = 0; mi < MI; ++mi)
        #pragma unroll
        for (int ni = 0; ni < 4; ++ni)
            #pragma unroll
            for (int q = 0; q < 4; ++q) acc[mi][ni][q] = 0.f;

    // prologue: stages 0,1
    issue(0, 0); CP_COMMIT();
    if (nch > 1) issue(1, 1);
    CP_COMMIT();

    for (int ch = 0; ch < nch; ++ch) {
        CP_WAIT1();
        __syncthreads();

        // issue chunk ch+2 into stage (ch+2)%3 (that stage was consumed at iter ch-1)
        int nx = ch + 2;
        if (nx < nch) issue(nx % 3, nx);
        CP_COMMIT();

        const uint32_t sb = uS + (uint32_t)((ch % 3) * STAGE);
        const uint32_t uAh = sb, uAl = sb + ASZ, uBh = sb + 2 * ASZ, uBl = sb + 2 * ASZ + BSZ;
        #pragma unroll
        for (int ks = 0; ks < 2; ++ks) {
            uint32_t ah[MI][4], al[MI][4];
            #pragma unroll
            for (int mi = 0; mi < MI; ++mi) {
                uint32_t off = (uint32_t)((mbase + mi * 16 + lr) * LDS + ks * 16 + lc8) * 2;
                ldm4(ah[mi], uAh + off);
                ldm4(al[mi], uAl + off);
            }
            uint32_t bh[4][2], bl[4][2], r[4];
            uint32_t off0 = (uint32_t)((nbase + lr) * LDS + ks * 16 + lc8) * 2;
            uint32_t off1 = (uint32_t)((nbase + 16 + lr) * LDS + ks * 16 + lc8) * 2;
            ldm4(r, uBh + off0); bh[0][0] = r[0]; bh[0][1] = r[2]; bh[1][0] = r[1]; bh[1][1] = r[3];
            ldm4(r, uBh + off1); bh[2][0] = r[0]; bh[2][1] = r[2]; bh[3][0] = r[1]; bh[3][1] = r[3];
            ldm4(r, uBl + off0); bl[0][0] = r[0]; bl[0][1] = r[2]; bl[1][0] = r[1]; bl[1][1] = r[3];
            ldm4(r, uBl + off1); bl[2][0] = r[0]; bl[2][1] = r[2]; bl[3][0] = r[1]; bl[3][1] = r[3];
            #pragma unroll
            for (int mi = 0; mi < MI; ++mi)
                #pragma unroll
                for (int ni = 0; ni < 4; ++ni) {
                    mma_bf16(acc[mi][ni], ah[mi], bh[ni]);
                    mma_bf16(acc[mi][ni], ah[mi], bl[ni]);
                    mma_bf16(acc[mi][ni], al[mi], bh[ni]);
                }
        }
        __syncthreads();
    }

    // epilogue
    #pragma unroll
    for (int mi = 0; mi < MI; ++mi) {
        int r0 = m0 + mbase + mi * 16 + (lane >> 2);
        #pragma unroll
        for (int ni = 0; ni < 4; ++ni) {
            int cc = n0 + nbase + ni * 8 + (lane & 3) * 2;
            float d0 = acc[mi][ni][0], d1 = acc[mi][ni][1];
            float d2 = acc[mi][ni][2], d3 = acc[mi][ni][3];
            if (EPI == 0) {
                if (bias) {
                    float b0 = bias[cc], b1 = bias[cc + 1];
                    d0 += b0; d1 += b1; d2 += b0; d3 += b1;
                }
            } else {
                float lg0 = logc[cc], lg1 = logc[cc + 1];
                int e0 = dm[(size_t)r0 * dmld + cc],       e1 = dm[(size_t)r0 * dmld + cc + 1];
                int e2 = dm[(size_t)(r0 + 8) * dmld + cc], e3 = dm[(size_t)(r0 + 8) * dmld + cc + 1];
                d0 = d0 * scale + lg0 + table[e0];
                d1 = d1 * scale + lg1 + table[e1];
                d2 = d2 * scale + lg0 + table[e2];
                d3 = d3 * scale + lg1 + table[e3];
            }
            size_t o0 = (size_t)blockIdx.z * zsC + (size_t)r0 * ldc + cc;
            size_t o1 = (size_t)blockIdx.z * zsC + (size_t)(r0 + 8) * ldc + cc;
            if (Cf) {
                *reinterpret_cast<float2*>(Cf + o0) = make_float2(d0, d1);
                *reinterpret_cast<float2*>(Cf + o1) = make_float2(d2, d3);
            }
            if (Coh) {
                uint32_t lo0, lo1;
                uint32_t hi0 = pack_hi_lo(d0, d1, lo0);
                uint32_t hi1 = pack_hi_lo(d2, d3, lo1);
                *reinterpret_cast<uint32_t*>(Coh + o0) = hi0;
                *reinterpret_cast<uint32_t*>(Col + o0) = lo0;
                *reinterpret_cast<uint32_t*>(Coh + o1) = hi1;
                *reinterpret_cast<uint32_t*>(Col + o1) = lo1;
            }
        }
    }
}

// ---------------- split fp32 -> bf16 pair (elementwise) ----------------
__global__ void split_kernel(const float4* __restrict__ in, uint2* __restrict__ outH,
                             uint2* __restrict__ outL, int n4) {
    int i = blockIdx.x * blockDim.x + threadIdx.x;
    if (i < n4) {
        uint2 H, L; split4(in[i], H, L);
        outH[i] = H; outL[i] = L;
    }
}

// ---------------- transpose + split: out[C,R] (bf16 pair) = in[R,C]^T ----------------
__global__ void transpose_split_kernel(const float* __restrict__ in,
                                       bf16* __restrict__ outH, bf16* __restrict__ outL,
                                       int R, int Ccols) {
    __shared__ float tile[32][33];
    int c0 = blockIdx.x * 32, r0 = blockIdx.y * 32;
    int x = threadIdx.x, y = threadIdx.y;           // 32 x 8
    #pragma unroll
    for (int j = 0; j < 32; j += 8)
        tile[y + j][x] = in[(size_t)(r0 + y + j) * Ccols + c0 + x];
    __syncthreads();
    #pragma unroll
    for (int j = 0; j < 32; j += 8) {
        float v = tile[x][y + j];
        bf16 h = __float2bfloat16(v);
        bf16 l = __float2bfloat16(v - __bfloat162float(h));
        size_t o = (size_t)(c0 + y + j) * R + r0 + x;
        outH[o] = h; outL[o] = l;
    }
}

// ---------------- fused q bias ----------------
__global__ void fuse_bias_kernel(const float* __restrict__ bproj,
                                 const float* __restrict__ Wq,
                                 const float* __restrict__ bq,
                                 float* __restrict__ out) {
    int o = blockIdx.x * blockDim.x + threadIdx.x;
    float s = bq[o];
    for (int k = 0; k < HID; k++) s += bproj[k] * Wq[(size_t)k * HID + o];
    out[o] = s;
}

// ---------------- community preprocessing (deterministic, stable) ----------------
__global__ void hist_kernel(const int* __restrict__ ntc) {
    __shared__ int sh[C_COMM];
    int chunk = blockIdx.x;
    for (int i = threadIdx.x; i < C_COMM; i += blockDim.x) sh[i] = 0;
    __syncthreads();
    atomicAdd(&sh[ntc[chunk * CHUNK + threadIdx.x]], 1);
    __syncthreads();
    for (int i = threadIdx.x; i < C_COMM; i += blockDim.x)
        g_hist[chunk * C_COMM + i] = sh[i];
}

__global__ void chunk_scan_kernel() {
    int c = blockIdx.x;
    __shared__ int s[NCHUNK];
    int t = threadIdx.x;
    int own = g_hist[t * C_COMM + c];
    s[t] = own;
    __syncthreads();
    for (int off = 1; off < NCHUNK; off <<= 1) {
        int v = (t >= off) ? s[t - off] : 0;
        __syncthreads();
        s[t] += v;
        __syncthreads();
    }
    g_chunkbase[t * C_COMM + c] = s[t] - own;
    if (t == NCHUNK - 1) g_counts[c] = s[t];
}

__global__ void offsets_kernel() {
    __shared__ int s[C_COMM];
    int t = threadIdx.x;
    int own = g_counts[t];
    s[t] = own;
    __syncthreads();
    for (int off = 1; off < C_COMM; off <<= 1) {
        int v = (t >= off) ? s[t - off] : 0;
        __syncthreads();
        s[t] += v;
        __syncthreads();
    }
    g_offsets[t] = s[t] - own;
    g_logc[t]    = logf((float)own);
    g_inv[t]     = 1.0f / (float)(own > 0 ? own : 1);
}

__global__ void scatter_kernel(const int* __restrict__ ntc) {
    __shared__ int s[CHUNK];
    int chunk = blockIdx.x;
    int t = threadIdx.x;
    int node = chunk * CHUNK + t;
    int c = ntc[node];
    s[t] = c;
    __syncthreads();
    int lrank = 0;
    for (int j = 0; j < t; j++) lrank += (s[j] == c);
    g_members[g_offsets[c] + g_chunkbase[chunk * C_COMM + c] + lrank] = node;
}

// mean of member rows of g_h (deterministic order) -> split bf16 pair
__global__ void comm_avg_kernel() {
    int c = blockIdx.x;
    int t = threadIdx.x;                 // 256 threads, 2 cols each
    int off = g_offsets[c], cnt = g_counts[c];
    float a0 = 0.f, a1 = 0.f;
    for (int m = 0; m < cnt; m++) {
        const float* row = g_h + (size_t)g_members[off + m] * HID;
        a0 += row[t];
        a1 += row[t + 256];
    }
    float inv = g_inv[c];
    a0 *= inv; a1 *= inv;
    bf16 h0 = __float2bfloat16(a0), h1 = __float2bfloat16(a1);
    g_cmh[c * HID + t]       = h0;
    g_cmh[c * HID + t + 256] = h1;
    g_cml[c * HID + t]       = __float2bfloat16(a0 - __bfloat162float(h0));
    g_cml[c * HID + t + 256] = __float2bfloat16(a1 - __bfloat162float(h1));
}

__global__ void bias_table_kernel(const float* __restrict__ emb,
                                  const float* __restrict__ w,
                                  const float* __restrict__ bptr) {
    int i = blockIdx.x;
    int t = threadIdx.x;
    float s = emb[i * HID + t]       * w[t]
            + emb[i * HID + t + 128] * w[t + 128]
            + emb[i * HID + t + 256] * w[t + 256]
            + emb[i * HID + t + 384] * w[t + 384];
    for (int o = 16; o; o >>= 1) s += __shfl_xor_sync(0xFFFFFFFFu, s, o);
    __shared__ float r[4];
    if ((t & 31) == 0) r[t >> 5] = s;
    __syncthreads();
    if (t == 0) g_table[i] = r[0] + r[1] + r[2] + r[3] + bptr[0];
}

// LayerNorm + ReLU; writes fp32 (optional) + bf16 split pair
__global__ void ln_relu_kernel(const float* __restrict__ in, float* __restrict__ outF,
                               bf16* __restrict__ outH, bf16* __restrict__ outL,
                               const float* __restrict__ g, const float* __restrict__ b) {
    size_t row = blockIdx.x;
    int t = threadIdx.x;
    const float* x = in + row * HID;
    float v0 = x[t], v1 = x[t + 256];
    float s = v0 + v1, q = v0 * v0 + v1 * v1;
    for (int o = 16; o; o >>= 1) {
        s += __shfl_xor_sync(0xFFFFFFFFu, s, o);
        q += __shfl_xor_sync(0xFFFFFFFFu, q, o);
    }
    __shared__ float rs[8], rq[8];
    int w = t >> 5, lane = t & 31;
    if (lane == 0) { rs[w] = s; rq[w] = q; }
    __syncthreads();
    __shared__ float smean, srstd;
    if (t == 0) {
        float ts = 0.f, tq = 0.f;
        for (int i = 0; i < 8; i++) { ts += rs[i]; tq += rq[i]; }
        float mean = ts * (1.0f / HID);
        float var  = tq * (1.0f / HID) - mean * mean;
        smean = mean;
        srstd = rsqrtf(var + EPS);
    }
    __syncthreads();
    float mean = smean, rstd = srstd;
    float y0 = fmaxf((v0 - mean) * rstd * g[t]       + b[t],       0.f);
    float y1 = fmaxf((v1 - mean) * rstd * g[t + 256] + b[t + 256], 0.f);
    size_t o0 = row * HID + t, o1 = row * HID + t + 256;
    if (outF) { outF[o0] = y0; outF[o1] = y1; }
    bf16 h0 = __float2bfloat16(y0), h1 = __float2bfloat16(y1);
    outH[o0] = h0; outH[o1] = h1;
    outL[o0] = __float2bfloat16(y0 - __bfloat162float(h0));
    outL[o1] = __float2bfloat16(y1 - __bfloat162float(h1));
}

// softmax over C=512: reads fp32 dots, writes bf16 split probs
__global__ void softmax_kernel(const float* __restrict__ dots,
                               bf16* __restrict__ ph, bf16* __restrict__ pl) {
    size_t row = (size_t)blockIdx.x;
    const float* p = dots + row * C_COMM;
    int t = threadIdx.x;
    float v0 = p[t], v1 = p[t + 256];
    float m = fmaxf(v0, v1);
    for (int o = 16; o; o >>= 1) m = fmaxf(m, __shfl_xor_sync(0xFFFFFFFFu, m, o));
    __shared__ float rm[8];
    int w = t >> 5, lane = t & 31;
    if (lane == 0) rm[w] = m;
    __syncthreads();
    __shared__ float smax;
    if (t == 0) {
        float mm = rm[0];
        for (int i = 1; i < 8; i++) mm = fmaxf(mm, rm[i]);
        smax = mm;
    }
    __syncthreads();
    m = smax;
    float e0 = __expf(v0 - m), e1 = __expf(v1 - m);
    float s = e0 + e1;
    for (int o = 16; o; o >>= 1) s += __shfl_xor_sync(0xFFFFFFFFu, s, o);
    __shared__ float rsum[8];
    if (lane == 0) rsum[w] = s;
    __syncthreads();
    __shared__ float stot;
    if (t == 0) {
        float ts = 0.f;
        for (int i = 0; i < 8; i++) ts += rsum[i];
        stot = ts;
    }
    __syncthreads();
    float inv = 1.0f / stot;
    float q0 = e0 * inv, q1 = e1 * inv;
    size_t o0 = row * C_COMM + t, o1 = row * C_COMM + t + 256;
    bf16 h0 = __float2bfloat16(q0), h1 = __float2bfloat16(q1);
    ph[o0] = h0; ph[o1] = h1;
    pl[o0] = __float2bfloat16(q0 - __bfloat162float(h0));
    pl[o1] = __float2bfloat16(q1 - __bfloat162float(h1));
}

// ---------------- host-side helpers ----------------
static const int SMEM_G = 3 * (2 * 128 * 80 + 2 * 64 * 80);  // 92160 per CTA

static void tc_nn(int M, int Nc, int K,
                  const bf16* Ah, const bf16* Al, int lda,
                  const bf16* Bth, const bf16* Btl,
                  const float* bias,
                  float* Cf, bf16* Coh, bf16* Col, int ldc)
{
    dim3 g(Nc / 64, M / 128, 1);
    mma_gemm<64, 0><<<g, 256, SMEM_G>>>(M, K, Ah, Al, lda, 0, Bth, Btl, K, 0,
                                        bias, Cf, Coh, Col, ldc, 0,
                                        0.f, nullptr, nullptr, nullptr, 0);
}

static void do_transpose_split(const float* in, bf16* outH, bf16* outL, int R, int C) {
    dim3 g(C / 32, R / 32), b(32, 8);
    transpose_split_kernel<<<g, b>>>(in, outH, outL, R, C);
}

extern "C" void kernel_launch(void* const* d_in, const int* in_sizes, int n_in,
                              void* d_out, int out_size)
{
    // ---- input mapping (auto-detect metadata order) ----
    const float *x      = (const float*)d_in[0];
    const int   *dm     = (const int*)  d_in[1];
    const int   *ntc    = (const int*)  d_in[2];
    const float *W_in1  = (const float*)d_in[3];
    const float *b_in1  = (const float*)d_in[4];
    const float *ln_in_g= (const float*)d_in[5];
    const float *ln_in_b= (const float*)d_in[6];
    const float *W_in2  = (const float*)d_in[7];
    const float *b_in2  = (const float*)d_in[8];
    const float *Wproj, *Wq, *Wk, *Wv, *ffW1, *ffW2;
    const float *bproj, *bq, *bk, *bv, *ffb1, *ffb2;
    const float *dis_emb, *dis_w, *dis_b;
    const float *ffg1, *ffbeta1, *ffg2, *ffbeta2, *Wout, *bout;

    if (in_sizes[10] == NLAYER * HID * HID) {
        Wproj  = (const float*)d_in[9];  Wq     = (const float*)d_in[10];
        Wk     = (const float*)d_in[11]; Wv     = (const float*)d_in[12];
        ffW1   = (const float*)d_in[13]; ffW2   = (const float*)d_in[14];
        bproj  = (const float*)d_in[15]; bq     = (const float*)d_in[16];
        bk     = (const float*)d_in[17]; bv     = (const float*)d_in[18];
        ffb1   = (const float*)d_in[19]; ffb2   = (const float*)d_in[20];
        dis_emb= (const float*)d_in[21]; dis_w  = (const float*)d_in[22];
        dis_b  = (const float*)d_in[23];
        ffg1   = (const float*)d_in[24]; ffbeta1= (const float*)d_in[25];
        ffg2   = (const float*)d_in[26]; ffbeta2= (const float*)d_in[27];
        Wout   = (const float*)d_in[28]; bout   = (const float*)d_in[29];
    } else {
        Wproj  = (const float*)d_in[9];  bproj  = (const float*)d_in[10];
        Wq     = (const float*)d_in[11]; bq     = (const float*)d_in[12];
        Wk     = (const float*)d_in[13]; bk     = (const float*)d_in[14];
        Wv     = (const float*)d_in[15]; bv     = (const float*)d_in[16];
        dis_emb= (const float*)d_in[17]; dis_w  = (const float*)d_in[18];
        dis_b  = (const float*)d_in[19];
        ffW1   = (const float*)d_in[20]; ffb1   = (const float*)d_in[21];
        ffg1   = (const float*)d_in[22]; ffbeta1= (const float*)d_in[23];
        ffW2   = (const float*)d_in[24]; ffb2   = (const float*)d_in[25];
        ffg2   = (const float*)d_in[26]; ffbeta2= (const float*)d_in[27];
        Wout   = (const float*)d_in[28]; bout   = (const float*)d_in[29];
    }

    cudaFuncSetAttribute(mma_gemm<64, 0>, cudaFuncAttributeMaxDynamicSharedMemorySize, SMEM_G);
    cudaFuncSetAttribute(mma_gemm<64, 1>, cudaFuncAttributeMaxDynamicSharedMemorySize, SMEM_G);

    // ---- scratch pointers ----
    float *p_h, *p_t0, *p_t1, *p_dots, *p_v, *p_logc, *p_table, *p_bfq;
    bf16 *p_xh, *p_xl, *p_hh, *p_hl, *p_t0h, *p_t0l, *p_t1h, *p_t1l, *p_qh, *p_ql;
    bf16 *p_ph, *p_pl, *p_cmh, *p_cml, *p_kh, *p_kl, *p_vth, *p_vtl, *p_wh, *p_wl;
    cudaGetSymbolAddress((void**)&p_h,    g_h);
    cudaGetSymbolAddress((void**)&p_t0,   g_t0);
    cudaGetSymbolAddress((void**)&p_t1,   g_t1);
    cudaGetSymbolAddress((void**)&p_dots, g_dots);
    cudaGetSymbolAddress((void**)&p_v,    g_v);
    cudaGetSymbolAddress((void**)&p_logc, g_logc);
    cudaGetSymbolAddress((void**)&p_table,g_table);
    cudaGetSymbolAddress((void**)&p_bfq,  g_bfq);
    cudaGetSymbolAddress((void**)&p_xh,  g_xh);  cudaGetSymbolAddress((void**)&p_xl,  g_xl);
    cudaGetSymbolAddress((void**)&p_hh,  g_hh);  cudaGetSymbolAddress((void**)&p_hl,  g_hl);
    cudaGetSymbolAddress((void**)&p_t0h, g_t0h); cudaGetSymbolAddress((void**)&p_t0l, g_t0l);
    cudaGetSymbolAddress((void**)&p_t1h, g_t1h); cudaGetSymbolAddress((void**)&p_t1l, g_t1l);
    cudaGetSymbolAddress((void**)&p_qh,  g_qh);  cudaGetSymbolAddress((void**)&p_ql,  g_ql);
    cudaGetSymbolAddress((void**)&p_ph,  g_ph);  cudaGetSymbolAddress((void**)&p_pl,  g_pl);
    cudaGetSymbolAddress((void**)&p_cmh, g_cmh); cudaGetSymbolAddress((void**)&p_cml, g_cml);
    cudaGetSymbolAddress((void**)&p_kh,  g_kh);  cudaGetSymbolAddress((void**)&p_kl,  g_kl);
    cudaGetSymbolAddress((void**)&p_vth, g_vth); cudaGetSymbolAddress((void**)&p_vtl, g_vtl);
    cudaGetSymbolAddress((void**)&p_wh,  g_wh);  cudaGetSymbolAddress((void**)&p_wl,  g_wl);
    #define WH(i) (p_wh + (size_t)(i) * HID * HID)
    #define WL(i) (p_wl + (size_t)(i) * HID * HID)

    const float scale = 1.0f / sqrtf((float)DHEAD);

    // ---- weight preprocessing ----
    // slots: 0=W_in1T 1=W_in2T; per layer l: 2+l*5+{0:WfqT,1:WkT,2:WvT,3:ffW1T,4:ffW2T};
    // 12=WoutT; 13=tmp WqT; 14=tmp Wproj(raw split)
    do_transpose_split(W_in1, WH(0), WL(0), IN_DIM, HID);
    do_transpose_split(W_in2, WH(1), WL(1), HID, HID);
    split_kernel<<<N_NODES * IN_DIM / 1024, 256>>>((const float4*)x, (uint2*)p_xh, (uint2*)p_xl,
                                                   N_NODES * IN_DIM / 4);
    for (int l = 0; l < NLAYER; l++) {
        const size_t wo = (size_t)l * HID * HID;
        int s0 = 2 + l * 5;
        // fused q weight: WfqT[o,i] = sum_k WqT[o,k] * Wproj[i,k]
        do_transpose_split(Wq + wo, WH(13), WL(13), HID, HID);
        split_kernel<<<HID * HID / 1024, 256>>>((const float4*)(Wproj + wo),
                                                (uint2*)WH(14), (uint2*)WL(14), HID * HID / 4);
        {
            dim3 g(HID / 64, HID / 128, 1);
            mma_gemm<64, 0><<<g, 256, SMEM_G>>>(HID, HID,
                                                WH(13), WL(13), HID, 0,
                                                WH(14), WL(14), HID, 0,
                                                nullptr, nullptr, WH(s0), WL(s0), HID, 0,
                                                0.f, nullptr, nullptr, nullptr, 0);
        }
        fuse_bias_kernel<<<HID / 256, 256>>>(bproj + (size_t)l * HID, Wq + wo,
                                             bq + (size_t)l * HID, p_bfq + (size_t)l * HID);
        do_transpose_split(Wk   + wo, WH(s0 + 1), WL(s0 + 1), HID, HID);
        do_transpose_split(Wv   + wo, WH(s0 + 2), WL(s0 + 2), HID, HID);
        do_transpose_split(ffW1 + wo, WH(s0 + 3), WL(s0 + 3), HID, HID);
        do_transpose_split(ffW2 + wo, WH(s0 + 4), WL(s0 + 4), HID, HID);
    }
    do_transpose_split(Wout, WH(12), WL(12), HID, OUT_DIM);   // -> [64,512]

    // ---- community preprocessing (deterministic) ----
    hist_kernel      <<<NCHUNK, CHUNK>>>(ntc);
    chunk_scan_kernel<<<C_COMM, NCHUNK>>>();
    offsets_kernel   <<<1, C_COMM>>>();
    scatter_kernel   <<<NCHUNK, CHUNK>>>(ntc);

    // ---- fc_in ----
    tc_nn(N_NODES, HID, IN_DIM, p_xh, p_xl, IN_DIM, WH(0), WL(0), b_in1,
          p_t0, nullptr, nullptr, HID);
    ln_relu_kernel<<<N_NODES, 256>>>(p_t0, nullptr, p_t0h, p_t0l, ln_in_g, ln_in_b);
    tc_nn(N_NODES, HID, HID, p_t0h, p_t0l, HID, WH(1), WL(1), b_in2,
          p_h, p_hh, p_hl, HID);

    // ---- layers ----
    for (int l = 0; l < NLAYER; l++) {
        int s0 = 2 + l * 5;
        bias_table_kernel<<<NDIST, 128>>>(dis_emb + (size_t)l * NDIST * HID,
                                          dis_w + (size_t)l * HID, dis_b + l);
        comm_avg_kernel<<<C_COMM, 256>>>();

        // q = h @ WfqT^T + bfq  (split out only)
        tc_nn(N_NODES, HID, HID, p_hh, p_hl, HID, WH(s0), WL(s0),
              p_bfq + (size_t)l * HID, nullptr, p_qh, p_ql, HID);
        // k (split only), v (fp32, for transpose)
        tc_nn(C_COMM, HID, HID, p_cmh, p_cml, HID, WH(s0 + 1), WL(s0 + 1),
              bk + (size_t)l * HID, nullptr, p_kh, p_kl, HID);
        tc_nn(C_COMM, HID, HID, p_cmh, p_cml, HID, WH(s0 + 2), WL(s0 + 2),
              bv + (size_t)l * HID, p_v, nullptr, nullptr, HID);
        do_transpose_split(p_v, p_vth, p_vtl, C_COMM, HID);   // vT [HID, C] split

        // dots per head (z), fused epilogue -> fp32
        {
            dim3 g(C_COMM / 64, N_NODES / 128, NHEAD);
            mma_gemm<64, 1><<<g, 256, SMEM_G>>>(
                N_NODES, DHEAD,
                p_qh, p_ql, HID, (size_t)DHEAD,
                p_kh, p_kl, HID, (size_t)DHEAD,
                nullptr,
                p_dots, nullptr, nullptr, C_COMM, (size_t)N_NODES * C_COMM,
                scale, p_logc, p_table, dm, C_COMM);
        }
        softmax_kernel<<<NHEAD * N_NODES, 256>>>(p_dots, p_ph, p_pl);

        // AV per head -> t0 split only
        {
            dim3 g(DHEAD / 64, N_NODES / 128, NHEAD);
            mma_gemm<64, 0><<<g, 256, SMEM_G>>>(
                N_NODES, C_COMM,
                p_ph, p_pl, C_COMM, (size_t)N_NODES * C_COMM,
                p_vth, p_vtl, C_COMM, (size_t)DHEAD * C_COMM,
                nullptr,
                nullptr, p_t0h, p_t0l, HID, (size_t)DHEAD,
                0.f, nullptr, nullptr, nullptr, 0);
        }

        tc_nn(N_NODES, HID, HID, p_t0h, p_t0l, HID, WH(s0 + 3), WL(s0 + 3),
              ffb1 + (size_t)l * HID, p_t1, nullptr, nullptr, HID);
        ln_relu_kernel<<<N_NODES, 256>>>(p_t1, nullptr, p_t1h, p_t1l,
                                         ffg1 + (size_t)l * HID, ffbeta1 + (size_t)l * HID);
        tc_nn(N_NODES, HID, HID, p_t1h, p_t1l, HID, WH(s0 + 4), WL(s0 + 4),
              ffb2 + (size_t)l * HID, p_t0, nullptr, nullptr, HID);
        ln_relu_kernel<<<N_NODES, 256>>>(p_t0, p_h, p_hh, p_hl,
                                         ffg2 + (size_t)l * HID, ffbeta2 + (size_t)l * HID);
    }

    // ---- output projection ----
    tc_nn(N_NODES, OUT_DIM, HID, p_hh, p_hl, HID, WH(12), WL(12), bout,
          (float*)d_out, nullptr, nullptr, OUT_DIM);
}

// round 11
// speedup vs baseline: 2.5281x; 1.0891x over previous
#include <cuda_runtime.h>
#include <cuda_bf16.h>
#include <math.h>
#include <stdint.h>

// ---------------- problem constants ----------------
#define N_NODES 32768
#define C_COMM  512
#define IN_DIM  128
#define HID     512
#define NHEAD   4
#define DHEAD   128
#define NLAYER  2
#define OUT_DIM 64
#define NDIST   31
#define EPS     1e-5f

#define CHUNK   256
#define NCHUNK  (N_NODES / CHUNK)   // 128

typedef __nv_bfloat16 bf16;

// ---------------- scratch (device globals; no allocation allowed) ----------------
__device__ float g_h   [N_NODES * HID];
__device__ float g_t0  [N_NODES * HID];
__device__ float g_t1  [N_NODES * HID];
__device__ float g_v   [C_COMM * HID];
__device__ float g_bfq [NLAYER * HID];
__device__ float g_rsp [(size_t)NHEAD * N_NODES * 8];   // per-(row, n-tile) exp partial sums
__device__ float g_rinv[(size_t)NHEAD * N_NODES];       // 1 / row sum

__device__ bf16 g_xh [N_NODES * IN_DIM], g_xl [N_NODES * IN_DIM];
__device__ bf16 g_hh [N_NODES * HID],    g_hl [N_NODES * HID];
__device__ bf16 g_t0h[N_NODES * HID],    g_t0l[N_NODES * HID];
__device__ bf16 g_t1h[N_NODES * HID],    g_t1l[N_NODES * HID];
__device__ bf16 g_qh [N_NODES * HID],    g_ql [N_NODES * HID];
__device__ bf16 g_ph [(size_t)NHEAD * N_NODES * C_COMM];   // unnormalized exp pairs
__device__ bf16 g_pl [(size_t)NHEAD * N_NODES * C_COMM];
__device__ bf16 g_cmh[C_COMM * HID],     g_cml[C_COMM * HID];
__device__ bf16 g_kh [C_COMM * HID],     g_kl [C_COMM * HID];
__device__ bf16 g_vth[HID * C_COMM],     g_vtl[HID * C_COMM];
__device__ bf16 g_wh [15][HID * HID],    g_wl [15][HID * HID];

__device__ int   g_hist     [NCHUNK * C_COMM];
__device__ int   g_chunkbase[NCHUNK * C_COMM];
__device__ int   g_counts [C_COMM];
__device__ int   g_offsets[C_COMM];
__device__ int   g_members[N_NODES];
__device__ float g_logc[C_COMM];
__device__ float g_inv [C_COMM];
__device__ float g_table[NDIST];

// ---------------- small PTX helpers (all sm_80-compatible) ----------------
__device__ __forceinline__ uint32_t smem_u32(const void* p) {
    uint32_t a;
    asm("{ .reg .u64 t; cvta.to.shared.u64 t, %1; cvt.u32.u64 %0, t; }" : "=r"(a) : "l"(p));
    return a;
}

__device__ __forceinline__ void cpa16(uint32_t dst, const void* src) {
    asm volatile("{ .reg .u64 g; cvta.to.global.u64 g, %1; cp.async.cg.shared.global [%0], [g], 16; }"
                 :: "r"(dst), "l"(src));
}
#define CP_COMMIT() asm volatile("cp.async.commit_group;" ::: "memory")
#define CP_WAIT1()  asm volatile("cp.async.wait_group 1;" ::: "memory")

__device__ __forceinline__ void ldm4(uint32_t* r, uint32_t addr) {
    asm volatile("ldmatrix.sync.aligned.m8n8.x4.shared.b16 {%0,%1,%2,%3}, [%4];"
                 : "=r"(r[0]), "=r"(r[1]), "=r"(r[2]), "=r"(r[3]) : "r"(addr));
}

__device__ __forceinline__ void mma_bf16(float* d, const uint32_t* a, const uint32_t* b) {
    asm volatile(
        "mma.sync.aligned.m16n8k16.row.col.f32.bf16.bf16.f32 "
        "{%0,%1,%2,%3}, {%4,%5,%6,%7}, {%8,%9}, {%0,%1,%2,%3};"
        : "+f"(d[0]), "+f"(d[1]), "+f"(d[2]), "+f"(d[3])
        : "r"(a[0]), "r"(a[1]), "r"(a[2]), "r"(a[3]), "r"(b[0]), "r"(b[1]));
}

// split fp32x4 -> bf16 hi quad + bf16 lo quad
__device__ __forceinline__ void split4(float4 v, uint2& H, uint2& L) {
    bf16 hx = __float2bfloat16(v.x), hy = __float2bfloat16(v.y);
    bf16 hz = __float2bfloat16(v.z), hw = __float2bfloat16(v.w);
    H.x = (uint32_t)__bfloat16_as_ushort(hx) | ((uint32_t)__bfloat16_as_ushort(hy) << 16);
    H.y = (uint32_t)__bfloat16_as_ushort(hz) | ((uint32_t)__bfloat16_as_ushort(hw) << 16);
    bf16 lx = __float2bfloat16(v.x - __bfloat162float(hx));
    bf16 ly = __float2bfloat16(v.y - __bfloat162float(hy));
    bf16 lz = __float2bfloat16(v.z - __bfloat162float(hz));
    bf16 lw = __float2bfloat16(v.w - __bfloat162float(hw));
    L.x = (uint32_t)__bfloat16_as_ushort(lx) | ((uint32_t)__bfloat16_as_ushort(ly) << 16);
    L.y = (uint32_t)__bfloat16_as_ushort(lz) | ((uint32_t)__bfloat16_as_ushort(lw) << 16);
}

__device__ __forceinline__ uint32_t pack_hi_lo(float a, float b, uint32_t& outlo) {
    bf16 ha = __float2bfloat16(a), hb = __float2bfloat16(b);
    bf16 la = __float2bfloat16(a - __bfloat162float(ha));
    bf16 lb = __float2bfloat16(b - __bfloat162float(hb));
    outlo = (uint32_t)__bfloat16_as_ushort(la) | ((uint32_t)__bfloat16_as_ushort(lb) << 16);
    return (uint32_t)__bfloat16_as_ushort(ha) | ((uint32_t)__bfloat16_as_ushort(hb) << 16);
}

// ---------------- warp-MMA GEMM on pre-split bf16 pairs ----------------
// C[M,N] = (Ah+Al)[M,K] . (Bh+Bl)[N,K]^T  (3-term split product)
// BM=128 x BN=64 tile, 8 warps (4 m x 2 n), 3-stage cp.async pipeline, 2 CTAs/SM.
// EPI==0: +bias, optional rowinv scaling, fp32 and/or pair output.
// EPI==1: dots epilogue -> e = exp(d*scale + logc + table[dm]); writes e pairs
//         + deterministic per-row partial sums to rsp[row*8 + blockIdx.x].
template<int BN, int EPI>
__global__ __launch_bounds__(256, 2)
void mma_gemm(int M, int K,
              const bf16* __restrict__ Ah, const bf16* __restrict__ Al, int lda, size_t zsA,
              const bf16* __restrict__ Bh, const bf16* __restrict__ Bl, int ldb, size_t zsB,
              const float* __restrict__ bias,
              float* __restrict__ Cf, bf16* __restrict__ Coh, bf16* __restrict__ Col,
              int ldc, size_t zsC,
              float scale, const float* __restrict__ logc,
              const float* __restrict__ table,
              const int* __restrict__ dm, int dmld,
              float* __restrict__ rsp, const float* __restrict__ rowinv)
{
    constexpr int BM  = 128;
    constexpr int LDS = 40;                  // bf16 elems per smem row (80B stride)
    constexpr int NW_N = BN / 32;            // 2
    constexpr int NW_M = 8 / NW_N;           // 4
    constexpr int WM  = BM / NW_M;           // 32
    constexpr int MI  = WM / 16;             // 2
    constexpr int NBT = BN * 4 / 256;        // 1
    constexpr int ASZ = BM * LDS * 2;        // 10240 B
    constexpr int BSZ = BN * LDS * 2;        // 5120 B
    constexpr int STAGE = 2 * ASZ + 2 * BSZ; // 30720 B

    extern __shared__ char smem[];
    const uint32_t uS = smem_u32(smem);

    Ah += (size_t)blockIdx.z * zsA;  Al += (size_t)blockIdx.z * zsA;
    Bh += (size_t)blockIdx.z * zsB;  Bl += (size_t)blockIdx.z * zsB;
    const int m0 = blockIdx.y * BM, n0 = blockIdx.x * BN;
    const int tid = threadIdx.x, lane = tid & 31, wid = tid >> 5;
    const int wm = wid % NW_M, wn = wid / NW_M;
    const int mbase = wm * WM, nbase = wn * 32;
    const int lr = lane & 15, lc8 = (lane >> 4) * 8;

    const int nch = K >> 5;

    auto issue = [&](int s, int kc) {
        const uint32_t sb = uS + (uint32_t)(s * STAGE);
        const int k0 = kc << 5;
        #pragma unroll
        for (int t = 0; t < 2; ++t) {
            int j = tid + t * 256, row = j >> 2, ck = j & 3;
            uint32_t off = (uint32_t)(row * 80 + ck * 16);
            size_t so = (size_t)(m0 + row) * lda + k0 + ck * 8;
            cpa16(sb + off,       Ah + so);
            cpa16(sb + ASZ + off, Al + so);
        }
        #pragma unroll
        for (int t = 0; t < NBT; ++t) {
            int j = tid + t * 256, row = j >> 2, ck = j & 3;
            uint32_t off = (uint32_t)(row * 80 + ck * 16);
            size_t so = (size_t)(n0 + row) * ldb + k0 + ck * 8;
            cpa16(sb + 2 * ASZ + off,       Bh + so);
            cpa16(sb + 2 * ASZ + BSZ + off, Bl + so);
        }
    };

    float acc[MI][4][4];
    #pragma unroll
    for (int mi = 0; mi < MI; ++mi)
        #pragma unroll
        for (int ni = 0; ni < 4; ++ni)
            #pragma unroll
            for (int q = 0; q < 4; ++q) acc[mi][ni][q] = 0.f;

    // prologue: stages 0,1
    issue(0, 0); CP_COMMIT();
    if (nch > 1) issue(1, 1);
    CP_COMMIT();

    for (int ch = 0; ch < nch; ++ch) {
        CP_WAIT1();
        __syncthreads();   // single barrier per chunk: publishes chunk ch's data AND
                           // guarantees all warps finished reading stage (ch+2)%3 at iter ch-1

        int nx = ch + 2;
        if (nx < nch) issue(nx % 3, nx);
        CP_COMMIT();

        const uint32_t sb = uS + (uint32_t)((ch % 3) * STAGE);
        const uint32_t uAh = sb, uAl = sb + ASZ, uBh = sb + 2 * ASZ, uBl = sb + 2 * ASZ + BSZ;
        #pragma unroll
        for (int ks = 0; ks < 2; ++ks) {
            uint32_t ah[MI][4], al[MI][4];
            #pragma unroll
            for (int mi = 0; mi < MI; ++mi) {
                uint32_t off = (uint32_t)((mbase + mi * 16 + lr) * LDS + ks * 16 + lc8) * 2;
                ldm4(ah[mi], uAh + off);
                ldm4(al[mi], uAl + off);
            }
            uint32_t bh[4][2], bl[4][2], r[4];
            uint32_t off0 = (uint32_t)((nbase + lr) * LDS + ks * 16 + lc8) * 2;
            uint32_t off1 = (uint32_t)((nbase + 16 + lr) * LDS + ks * 16 + lc8) * 2;
            ldm4(r, uBh + off0); bh[0][0] = r[0]; bh[0][1] = r[2]; bh[1][0] = r[1]; bh[1][1] = r[3];
            ldm4(r, uBh + off1); bh[2][0] = r[0]; bh[2][1] = r[2]; bh[3][0] = r[1]; bh[3][1] = r[3];
            ldm4(r, uBl + off0); bl[0][0] = r[0]; bl[0][1] = r[2]; bl[1][0] = r[1]; bl[1][1] = r[3];
            ldm4(r, uBl + off1); bl[2][0] = r[0]; bl[2][1] = r[2]; bl[3][0] = r[1]; bl[3][1] = r[3];
            #pragma unroll
            for (int mi = 0; mi < MI; ++mi)
                #pragma unroll
                for (int ni = 0; ni < 4; ++ni) {
                    mma_bf16(acc[mi][ni], ah[mi], bh[ni]);
                    mma_bf16(acc[mi][ni], ah[mi], bl[ni]);
                    mma_bf16(acc[mi][ni], al[mi], bh[ni]);
                }
        }
    }

    if (EPI == 0) {
        #pragma unroll
        for (int mi = 0; mi < MI; ++mi) {
            int r0 = m0 + mbase + mi * 16 + (lane >> 2);
            float s0 = 1.f, s1 = 1.f;
            if (rowinv) {
                s0 = rowinv[(size_t)blockIdx.z * M + r0];
                s1 = rowinv[(size_t)blockIdx.z * M + r0 + 8];
            }
            #pragma unroll
            for (int ni = 0; ni < 4; ++ni) {
                int cc = n0 + nbase + ni * 8 + (lane & 3) * 2;
                float d0 = acc[mi][ni][0], d1 = acc[mi][ni][1];
                float d2 = acc[mi][ni][2], d3 = acc[mi][ni][3];
                if (bias) {
                    float b0 = bias[cc], b1 = bias[cc + 1];
                    d0 += b0; d1 += b1; d2 += b0; d3 += b1;
                }
                d0 *= s0; d1 *= s0; d2 *= s1; d3 *= s1;
                size_t o0 = (size_t)blockIdx.z * zsC + (size_t)r0 * ldc + cc;
                size_t o1 = (size_t)blockIdx.z * zsC + (size_t)(r0 + 8) * ldc + cc;
                if (Cf) {
                    *reinterpret_cast<float2*>(Cf + o0) = make_float2(d0, d1);
                    *reinterpret_cast<float2*>(Cf + o1) = make_float2(d2, d3);
                }
                if (Coh) {
                    uint32_t lo0, lo1;
                    uint32_t hi0 = pack_hi_lo(d0, d1, lo0);
                    uint32_t hi1 = pack_hi_lo(d2, d3, lo1);
                    *reinterpret_cast<uint32_t*>(Coh + o0) = hi0;
                    *reinterpret_cast<uint32_t*>(Col + o0) = lo0;
                    *reinterpret_cast<uint32_t*>(Coh + o1) = hi1;
                    *reinterpret_cast<uint32_t*>(Col + o1) = lo1;
                }
            }
        }
    } else {
        // dots epilogue: e = exp(dots); write pairs + deterministic row partial sums
        float rs0[MI], rs1[MI];
        #pragma unroll
        for (int mi = 0; mi < MI; ++mi) { rs0[mi] = 0.f; rs1[mi] = 0.f; }
        #pragma unroll
        for (int mi = 0; mi < MI; ++mi) {
            int r0 = m0 + mbase + mi * 16 + (lane >> 2);
            #pragma unroll
            for (int ni = 0; ni < 4; ++ni) {
                int cc = n0 + nbase + ni * 8 + (lane & 3) * 2;
                float lg0 = logc[cc], lg1 = logc[cc + 1];
                int e0i = dm[(size_t)r0 * dmld + cc],       e1i = dm[(size_t)r0 * dmld + cc + 1];
                int e2i = dm[(size_t)(r0 + 8) * dmld + cc], e3i = dm[(size_t)(r0 + 8) * dmld + cc + 1];
                float e0 = __expf(acc[mi][ni][0] * scale + lg0 + table[e0i]);
                float e1 = __expf(acc[mi][ni][1] * scale + lg1 + table[e1i]);
                float e2 = __expf(acc[mi][ni][2] * scale + lg0 + table[e2i]);
                float e3 = __expf(acc[mi][ni][3] * scale + lg1 + table[e3i]);
                size_t o0 = (size_t)blockIdx.z * zsC + (size_t)r0 * ldc + cc;
                size_t o1 = (size_t)blockIdx.z * zsC + (size_t)(r0 + 8) * ldc + cc;
                uint32_t lo0, lo1;
                uint32_t hi0 = pack_hi_lo(e0, e1, lo0);
                uint32_t hi1 = pack_hi_lo(e2, e3, lo1);
                *reinterpret_cast<uint32_t*>(Coh + o0) = hi0;
                *reinterpret_cast<uint32_t*>(Col + o0) = lo0;
                *reinterpret_cast<uint32_t*>(Coh + o1) = hi1;
                *reinterpret_cast<uint32_t*>(Col + o1) = lo1;
                rs0[mi] += e0 + e1;
                rs1[mi] += e2 + e3;
            }
        }
        __syncthreads();                       // smem pipeline no longer needed; reuse
        float* srs = reinterpret_cast<float*>(smem);   // [NW_N][BM]
        #pragma unroll
        for (int mi = 0; mi < MI; ++mi) {
            float a = rs0[mi];
            a += __shfl_xor_sync(0xFFFFFFFFu, a, 1);
            a += __shfl_xor_sync(0xFFFFFFFFu, a, 2);
            float b = rs1[mi];
            b += __shfl_xor_sync(0xFFFFFFFFu, b, 1);
            b += __shfl_xor_sync(0xFFFFFFFFu, b, 2);
            if ((lane & 3) == 0) {
                int rr = mbase + mi * 16 + (lane >> 2);
                srs[wn * BM + rr]     = a;
                srs[wn * BM + rr + 8] = b;
            }
        }
        __syncthreads();
        if (tid < BM) {
            float part = srs[tid] + srs[BM + tid];
            rsp[((size_t)blockIdx.z * (size_t)M + m0 + tid) * 8 + blockIdx.x] = part;
        }
    }
}

// ---------------- 1/rowsum from 8 deterministic partials ----------------
__global__ void rowsum_reduce_kernel(const float* __restrict__ rsp,
                                     float* __restrict__ rinv, int n) {
    int i = blockIdx.x * blockDim.x + threadIdx.x;
    if (i < n) {
        const float* p = rsp + (size_t)i * 8;
        float s = 0.f;
        #pragma unroll
        for (int j = 0; j < 8; ++j) s += p[j];
        rinv[i] = 1.0f / s;
    }
}

// ---------------- split fp32 -> bf16 pair (elementwise) ----------------
__global__ void split_kernel(const float4* __restrict__ in, uint2* __restrict__ outH,
                             uint2* __restrict__ outL, int n4) {
    int i = blockIdx.x * blockDim.x + threadIdx.x;
    if (i < n4) {
        uint2 H, L; split4(in[i], H, L);
        outH[i] = H; outL[i] = L;
    }
}

// ---------------- transpose + split: out[C,R] (bf16 pair) = in[R,C]^T ----------------
__global__ void transpose_split_kernel(const float* __restrict__ in,
                                       bf16* __restrict__ outH, bf16* __restrict__ outL,
                                       int R, int Ccols) {
    __shared__ float tile[32][33];
    int c0 = blockIdx.x * 32, r0 = blockIdx.y * 32;
    int x = threadIdx.x, y = threadIdx.y;           // 32 x 8
    #pragma unroll
    for (int j = 0; j < 32; j += 8)
        tile[y + j][x] = in[(size_t)(r0 + y + j) * Ccols + c0 + x];
    __syncthreads();
    #pragma unroll
    for (int j = 0; j < 32; j += 8) {
        float v = tile[x][y + j];
        bf16 h = __float2bfloat16(v);
        bf16 l = __float2bfloat16(v - __bfloat162float(h));
        size_t o = (size_t)(c0 + y + j) * R + r0 + x;
        outH[o] = h; outL[o] = l;
    }
}

// ---------------- fused q bias ----------------
__global__ void fuse_bias_kernel(const float* __restrict__ bproj,
                                 const float* __restrict__ Wq,
                                 const float* __restrict__ bq,
                                 float* __restrict__ out) {
    int o = blockIdx.x * blockDim.x + threadIdx.x;
    float s = bq[o];
    for (int k = 0; k < HID; k++) s += bproj[k] * Wq[(size_t)k * HID + o];
    out[o] = s;
}

// ---------------- community preprocessing (deterministic, stable) ----------------
__global__ void hist_kernel(const int* __restrict__ ntc) {
    __shared__ int sh[C_COMM];
    int chunk = blockIdx.x;
    for (int i = threadIdx.x; i < C_COMM; i += blockDim.x) sh[i] = 0;
    __syncthreads();
    atomicAdd(&sh[ntc[chunk * CHUNK + threadIdx.x]], 1);
    __syncthreads();
    for (int i = threadIdx.x; i < C_COMM; i += blockDim.x)
        g_hist[chunk * C_COMM + i] = sh[i];
}

__global__ void chunk_scan_kernel() {
    int c = blockIdx.x;
    __shared__ int s[NCHUNK];
    int t = threadIdx.x;
    int own = g_hist[t * C_COMM + c];
    s[t] = own;
    __syncthreads();
    for (int off = 1; off < NCHUNK; off <<= 1) {
        int v = (t >= off) ? s[t - off] : 0;
        __syncthreads();
        s[t] += v;
        __syncthreads();
    }
    g_chunkbase[t * C_COMM + c] = s[t] - own;
    if (t == NCHUNK - 1) g_counts[c] = s[t];
}

__global__ void offsets_kernel() {
    __shared__ int s[C_COMM];
    int t = threadIdx.x;
    int own = g_counts[t];
    s[t] = own;
    __syncthreads();
    for (int off = 1; off < C_COMM; off <<= 1) {
        int v = (t >= off) ? s[t - off] : 0;
        __syncthreads();
        s[t] += v;
        __syncthreads();
    }
    g_offsets[t] = s[t] - own;
    g_logc[t]    = logf((float)own);
    g_inv[t]     = 1.0f / (float)(own > 0 ? own : 1);
}

__global__ void scatter_kernel(const int* __restrict__ ntc) {
    __shared__ int s[CHUNK];
    int chunk = blockIdx.x;
    int t = threadIdx.x;
    int node = chunk * CHUNK + t;
    int c = ntc[node];
    s[t] = c;
    __syncthreads();
    int lrank = 0;
    for (int j = 0; j < t; j++) lrank += (s[j] == c);
    g_members[g_offsets[c] + g_chunkbase[chunk * C_COMM + c] + lrank] = node;
}

// mean of member rows of g_h (deterministic order) -> split bf16 pair
__global__ void comm_avg_kernel() {
    int c = blockIdx.x;
    int t = threadIdx.x;                 // 256 threads, 2 cols each
    int off = g_offsets[c], cnt = g_counts[c];
    float a0 = 0.f, a1 = 0.f;
    for (int m = 0; m < cnt; m++) {
        const float* row = g_h + (size_t)g_members[off + m] * HID;
        a0 += row[t];
        a1 += row[t + 256];
    }
    float inv = g_inv[c];
    a0 *= inv; a1 *= inv;
    bf16 h0 = __float2bfloat16(a0), h1 = __float2bfloat16(a1);
    g_cmh[c * HID + t]       = h0;
    g_cmh[c * HID + t + 256] = h1;
    g_cml[c * HID + t]       = __float2bfloat16(a0 - __bfloat162float(h0));
    g_cml[c * HID + t + 256] = __float2bfloat16(a1 - __bfloat162float(h1));
}

__global__ void bias_table_kernel(const float* __restrict__ emb,
                                  const float* __restrict__ w,
                                  const float* __restrict__ bptr) {
    int i = blockIdx.x;
    int t = threadIdx.x;
    float s = emb[i * HID + t]       * w[t]
            + emb[i * HID + t + 128] * w[t + 128]
            + emb[i * HID + t + 256] * w[t + 256]
            + emb[i * HID + t + 384] * w[t + 384];
    for (int o = 16; o; o >>= 1) s += __shfl_xor_sync(0xFFFFFFFFu, s, o);
    __shared__ float r[4];
    if ((t & 31) == 0) r[t >> 5] = s;
    __syncthreads();
    if (t == 0) g_table[i] = r[0] + r[1] + r[2] + r[3] + bptr[0];
}

// LayerNorm + ReLU; writes fp32 (optional) + bf16 split pair
__global__ void ln_relu_kernel(const float* __restrict__ in, float* __restrict__ outF,
                               bf16* __restrict__ outH, bf16* __restrict__ outL,
                               const float* __restrict__ g, const float* __restrict__ b) {
    size_t row = blockIdx.x;
    int t = threadIdx.x;
    const float* x = in + row * HID;
    float v0 = x[t], v1 = x[t + 256];
    float s = v0 + v1, q = v0 * v0 + v1 * v1;
    for (int o = 16; o; o >>= 1) {
        s += __shfl_xor_sync(0xFFFFFFFFu, s, o);
        q += __shfl_xor_sync(0xFFFFFFFFu, q, o);
    }
    __shared__ float rs[8], rq[8];
    int w = t >> 5, lane = t & 31;
    if (lane == 0) { rs[w] = s; rq[w] = q; }
    __syncthreads();
    __shared__ float smean, srstd;
    if (t == 0) {
        float ts = 0.f, tq = 0.f;
        for (int i = 0; i < 8; i++) { ts += rs[i]; tq += rq[i]; }
        float mean = ts * (1.0f / HID);
        float var  = tq * (1.0f / HID) - mean * mean;
        smean = mean;
        srstd = rsqrtf(var + EPS);
    }
    __syncthreads();
    float mean = smean, rstd = srstd;
    float y0 = fmaxf((v0 - mean) * rstd * g[t]       + b[t],       0.f);
    float y1 = fmaxf((v1 - mean) * rstd * g[t + 256] + b[t + 256], 0.f);
    size_t o0 = row * HID + t, o1 = row * HID + t + 256;
    if (outF) { outF[o0] = y0; outF[o1] = y1; }
    bf16 h0 = __float2bfloat16(y0), h1 = __float2bfloat16(y1);
    outH[o0] = h0; outH[o1] = h1;
    outL[o0] = __float2bfloat16(y0 - __bfloat162float(h0));
    outL[o1] = __float2bfloat16(y1 - __bfloat162float(h1));
}

// ---------------- host-side helpers ----------------
static const int SMEM_G = 3 * (2 * 128 * 80 + 2 * 64 * 80);  // 92160 per CTA

static void tc_nn(int M, int Nc, int K,
                  const bf16* Ah, const bf16* Al, int lda,
                  const bf16* Bth, const bf16* Btl,
                  const float* bias,
                  float* Cf, bf16* Coh, bf16* Col, int ldc)
{
    dim3 g(Nc / 64, M / 128, 1);
    mma_gemm<64, 0><<<g, 256, SMEM_G>>>(M, K, Ah, Al, lda, 0, Bth, Btl, K, 0,
                                        bias, Cf, Coh, Col, ldc, 0,
                                        0.f, nullptr, nullptr, nullptr, 0,
                                        nullptr, nullptr);
}

static void do_transpose_split(const float* in, bf16* outH, bf16* outL, int R, int C) {
    dim3 g(C / 32, R / 32), b(32, 8);
    transpose_split_kernel<<<g, b>>>(in, outH, outL, R, C);
}

extern "C" void kernel_launch(void* const* d_in, const int* in_sizes, int n_in,
                              void* d_out, int out_size)
{
    // ---- input mapping (auto-detect metadata order) ----
    const float *x      = (const float*)d_in[0];
    const int   *dm     = (const int*)  d_in[1];
    const int   *ntc    = (const int*)  d_in[2];
    const float *W_in1  = (const float*)d_in[3];
    const float *b_in1  = (const float*)d_in[4];
    const float *ln_in_g= (const float*)d_in[5];
    const float *ln_in_b= (const float*)d_in[6];
    const float *W_in2  = (const float*)d_in[7];
    const float *b_in2  = (const float*)d_in[8];
    const float *Wproj, *Wq, *Wk, *Wv, *ffW1, *ffW2;
    const float *bproj, *bq, *bk, *bv, *ffb1, *ffb2;
    const float *dis_emb, *dis_w, *dis_b;
    const float *ffg1, *ffbeta1, *ffg2, *ffbeta2, *Wout, *bout;

    if (in_sizes[10] == NLAYER * HID * HID) {
        Wproj  = (const float*)d_in[9];  Wq     = (const float*)d_in[10];
        Wk     = (const float*)d_in[11]; Wv     = (const float*)d_in[12];
        ffW1   = (const float*)d_in[13]; ffW2   = (const float*)d_in[14];
        bproj  = (const float*)d_in[15]; bq     = (const float*)d_in[16];
        bk     = (const float*)d_in[17]; bv     = (const float*)d_in[18];
        ffb1   = (const float*)d_in[19]; ffb2   = (const float*)d_in[20];
        dis_emb= (const float*)d_in[21]; dis_w  = (const float*)d_in[22];
        dis_b  = (const float*)d_in[23];
        ffg1   = (const float*)d_in[24]; ffbeta1= (const float*)d_in[25];
        ffg2   = (const float*)d_in[26]; ffbeta2= (const float*)d_in[27];
        Wout   = (const float*)d_in[28]; bout   = (const float*)d_in[29];
    } else {
        Wproj  = (const float*)d_in[9];  bproj  = (const float*)d_in[10];
        Wq     = (const float*)d_in[11]; bq     = (const float*)d_in[12];
        Wk     = (const float*)d_in[13]; bk     = (const float*)d_in[14];
        Wv     = (const float*)d_in[15]; bv     = (const float*)d_in[16];
        dis_emb= (const float*)d_in[17]; dis_w  = (const float*)d_in[18];
        dis_b  = (const float*)d_in[19];
        ffW1   = (const float*)d_in[20]; ffb1   = (const float*)d_in[21];
        ffg1   = (const float*)d_in[22]; ffbeta1= (const float*)d_in[23];
        ffW2   = (const float*)d_in[24]; ffb2   = (const float*)d_in[25];
        ffg2   = (const float*)d_in[26]; ffbeta2= (const float*)d_in[27];
        Wout   = (const float*)d_in[28]; bout   = (const float*)d_in[29];
    }

    cudaFuncSetAttribute(mma_gemm<64, 0>, cudaFuncAttributeMaxDynamicSharedMemorySize, SMEM_G);
    cudaFuncSetAttribute(mma_gemm<64, 1>, cudaFuncAttributeMaxDynamicSharedMemorySize, SMEM_G);

    // ---- scratch pointers ----
    float *p_h, *p_t0, *p_t1, *p_v, *p_logc, *p_table, *p_bfq, *p_rsp, *p_rinv;
    bf16 *p_xh, *p_xl, *p_hh, *p_hl, *p_t0h, *p_t0l, *p_t1h, *p_t1l, *p_qh, *p_ql;
    bf16 *p_ph, *p_pl, *p_cmh, *p_cml, *p_kh, *p_kl, *p_vth, *p_vtl, *p_wh, *p_wl;
    cudaGetSymbolAddress((void**)&p_h,    g_h);
    cudaGetSymbolAddress((void**)&p_t0,   g_t0);
    cudaGetSymbolAddress((void**)&p_t1,   g_t1);
    cudaGetSymbolAddress((void**)&p_v,    g_v);
    cudaGetSymbolAddress((void**)&p_logc, g_logc);
    cudaGetSymbolAddress((void**)&p_table,g_table);
    cudaGetSymbolAddress((void**)&p_bfq,  g_bfq);
    cudaGetSymbolAddress((void**)&p_rsp,  g_rsp);
    cudaGetSymbolAddress((void**)&p_rinv, g_rinv);
    cudaGetSymbolAddress((void**)&p_xh,  g_xh);  cudaGetSymbolAddress((void**)&p_xl,  g_xl);
    cudaGetSymbolAddress((void**)&p_hh,  g_hh);  cudaGetSymbolAddress((void**)&p_hl,  g_hl);
    cudaGetSymbolAddress((void**)&p_t0h, g_t0h); cudaGetSymbolAddress((void**)&p_t0l, g_t0l);
    cudaGetSymbolAddress((void**)&p_t1h, g_t1h); cudaGetSymbolAddress((void**)&p_t1l, g_t1l);
    cudaGetSymbolAddress((void**)&p_qh,  g_qh);  cudaGetSymbolAddress((void**)&p_ql,  g_ql);
    cudaGetSymbolAddress((void**)&p_ph,  g_ph);  cudaGetSymbolAddress((void**)&p_pl,  g_pl);
    cudaGetSymbolAddress((void**)&p_cmh, g_cmh); cudaGetSymbolAddress((void**)&p_cml, g_cml);
    cudaGetSymbolAddress((void**)&p_kh,  g_kh);  cudaGetSymbolAddress((void**)&p_kl,  g_kl);
    cudaGetSymbolAddress((void**)&p_vth, g_vth); cudaGetSymbolAddress((void**)&p_vtl, g_vtl);
    cudaGetSymbolAddress((void**)&p_wh,  g_wh);  cudaGetSymbolAddress((void**)&p_wl,  g_wl);
    #define WH(i) (p_wh + (size_t)(i) * HID * HID)
    #define WL(i) (p_wl + (size_t)(i) * HID * HID)

    const float scale = 1.0f / sqrtf((float)DHEAD);

    // ---- weight preprocessing ----
    do_transpose_split(W_in1, WH(0), WL(0), IN_DIM, HID);
    do_transpose_split(W_in2, WH(1), WL(1), HID, HID);
    split_kernel<<<N_NODES * IN_DIM / 1024, 256>>>((const float4*)x, (uint2*)p_xh, (uint2*)p_xl,
                                                   N_NODES * IN_DIM / 4);
    for (int l = 0; l < NLAYER; l++) {
        const size_t wo = (size_t)l * HID * HID;
        int s0 = 2 + l * 5;
        do_transpose_split(Wq + wo, WH(13), WL(13), HID, HID);
        split_kernel<<<HID * HID / 1024, 256>>>((const float4*)(Wproj + wo),
                                                (uint2*)WH(14), (uint2*)WL(14), HID * HID / 4);
        {
            dim3 g(HID / 64, HID / 128, 1);
            mma_gemm<64, 0><<<g, 256, SMEM_G>>>(HID, HID,
                                                WH(13), WL(13), HID, 0,
                                                WH(14), WL(14), HID, 0,
                                                nullptr, nullptr, WH(s0), WL(s0), HID, 0,
                                                0.f, nullptr, nullptr, nullptr, 0,
                                                nullptr, nullptr);
        }
        fuse_bias_kernel<<<HID / 256, 256>>>(bproj + (size_t)l * HID, Wq + wo,
                                             bq + (size_t)l * HID, p_bfq + (size_t)l * HID);
        do_transpose_split(Wk   + wo, WH(s0 + 1), WL(s0 + 1), HID, HID);
        do_transpose_split(Wv   + wo, WH(s0 + 2), WL(s0 + 2), HID, HID);
        do_transpose_split(ffW1 + wo, WH(s0 + 3), WL(s0 + 3), HID, HID);
        do_transpose_split(ffW2 + wo, WH(s0 + 4), WL(s0 + 4), HID, HID);
    }
    do_transpose_split(Wout, WH(12), WL(12), HID, OUT_DIM);

    // ---- community preprocessing (deterministic) ----
    hist_kernel      <<<NCHUNK, CHUNK>>>(ntc);
    chunk_scan_kernel<<<C_COMM, NCHUNK>>>();
    offsets_kernel   <<<1, C_COMM>>>();
    scatter_kernel   <<<NCHUNK, CHUNK>>>(ntc);

    // ---- fc_in ----
    tc_nn(N_NODES, HID, IN_DIM, p_xh, p_xl, IN_DIM, WH(0), WL(0), b_in1,
          p_t0, nullptr, nullptr, HID);
    ln_relu_kernel<<<N_NODES, 256>>>(p_t0, nullptr, p_t0h, p_t0l, ln_in_g, ln_in_b);
    tc_nn(N_NODES, HID, HID, p_t0h, p_t0l, HID, WH(1), WL(1), b_in2,
          p_h, p_hh, p_hl, HID);

    // ---- layers ----
    for (int l = 0; l < NLAYER; l++) {
        int s0 = 2 + l * 5;
        bias_table_kernel<<<NDIST, 128>>>(dis_emb + (size_t)l * NDIST * HID,
                                          dis_w + (size_t)l * HID, dis_b + l);
        comm_avg_kernel<<<C_COMM, 256>>>();

        tc_nn(N_NODES, HID, HID, p_hh, p_hl, HID, WH(s0), WL(s0),
              p_bfq + (size_t)l * HID, nullptr, p_qh, p_ql, HID);
        tc_nn(C_COMM, HID, HID, p_cmh, p_cml, HID, WH(s0 + 1), WL(s0 + 1),
              bk + (size_t)l * HID, nullptr, p_kh, p_kl, HID);
        tc_nn(C_COMM, HID, HID, p_cmh, p_cml, HID, WH(s0 + 2), WL(s0 + 2),
              bv + (size_t)l * HID, p_v, nullptr, nullptr, HID);
        do_transpose_split(p_v, p_vth, p_vtl, C_COMM, HID);

        // dots per head: fused exp epilogue -> unnormalized e pairs + row partial sums
        {
            dim3 g(C_COMM / 64, N_NODES / 128, NHEAD);
            mma_gemm<64, 1><<<g, 256, SMEM_G>>>(
                N_NODES, DHEAD,
                p_qh, p_ql, HID, (size_t)DHEAD,
                p_kh, p_kl, HID, (size_t)DHEAD,
                nullptr,
                nullptr, p_ph, p_pl, C_COMM, (size_t)N_NODES * C_COMM,
                scale, p_logc, p_table, dm, C_COMM,
                p_rsp, nullptr);
        }
        rowsum_reduce_kernel<<<NHEAD * N_NODES / 256, 256>>>(p_rsp, p_rinv, NHEAD * N_NODES);

        // AV per head: multiply by 1/rowsum in epilogue -> t0 split
        {
            dim3 g(DHEAD / 64, N_NODES / 128, NHEAD);
            mma_gemm<64, 0><<<g, 256, SMEM_G>>>(
                N_NODES, C_COMM,
                p_ph, p_pl, C_COMM, (size_t)N_NODES * C_COMM,
                p_vth, p_vtl, C_COMM, (size_t)DHEAD * C_COMM,
                nullptr,
                nullptr, p_t0h, p_t0l, HID, (size_t)DHEAD,
                0.f, nullptr, nullptr, nullptr, 0,
                nullptr, p_rinv);
        }

        tc_nn(N_NODES, HID, HID, p_t0h, p_t0l, HID, WH(s0 + 3), WL(s0 + 3),
              ffb1 + (size_t)l * HID, p_t1, nullptr, nullptr, HID);
        ln_relu_kernel<<<N_NODES, 256>>>(p_t1, nullptr, p_t1h, p_t1l,
                                         ffg1 + (size_t)l * HID, ffbeta1 + (size_t)l * HID);
        tc_nn(N_NODES, HID, HID, p_t1h, p_t1l, HID, WH(s0 + 4), WL(s0 + 4),
              ffb2 + (size_t)l * HID, p_t0, nullptr, nullptr, HID);
        ln_relu_kernel<<<N_NODES, 256>>>(p_t0, p_h, p_hh, p_hl,
                                         ffg2 + (size_t)l * HID, ffbeta2 + (size_t)l * HID);
    }

    // ---- output projection ----
    tc_nn(N_NODES, OUT_DIM, HID, p_hh, p_hl, HID, WH(12), WL(12), bout,
          (float*)d_out, nullptr, nullptr, OUT_DIM);
}

// round 13
// speedup vs baseline: 2.7100x; 1.0720x over previous
#include <cuda_runtime.h>
#include <cuda_bf16.h>
#include <math.h>
#include <stdint.h>

// ---------------- problem constants ----------------
#define N_NODES 32768
#define C_COMM  512
#define IN_DIM  128
#define HID     512
#define NHEAD   4
#define DHEAD   128
#define NLAYER  2
#define OUT_DIM 64
#define NDIST   31
#define EPS     1e-5f

#define CHUNK   256
#define NCHUNK  (N_NODES / CHUNK)   // 128

typedef __nv_bfloat16 bf16;

// ---------------- scratch (device globals; no allocation allowed) ----------------
__device__ float g_h   [N_NODES * HID];
__device__ float g_t0  [N_NODES * HID];
__device__ float g_t1  [N_NODES * HID];
__device__ float g_bfq [NLAYER * HID];
__device__ float g_bkv [NLAYER * 2 * HID];
__device__ float g_rsp [(size_t)NHEAD * N_NODES * 8];
__device__ float g_rinv[(size_t)NHEAD * N_NODES];

__device__ bf16 g_xh [N_NODES * IN_DIM], g_xl [N_NODES * IN_DIM];
__device__ bf16 g_hh [N_NODES * HID],    g_hl [N_NODES * HID];
__device__ bf16 g_t0h[N_NODES * HID],    g_t0l[N_NODES * HID];
__device__ bf16 g_t1h[N_NODES * HID],    g_t1l[N_NODES * HID];
__device__ bf16 g_qh [N_NODES * HID],    g_ql [N_NODES * HID];
__device__ bf16 g_ph [(size_t)NHEAD * N_NODES * C_COMM];
__device__ bf16 g_pl [(size_t)NHEAD * N_NODES * C_COMM];
__device__ bf16 g_cmh[C_COMM * HID],     g_cml[C_COMM * HID];
__device__ bf16 g_kvh[2 * C_COMM * HID], g_kvl[2 * C_COMM * HID];   // [k; v]
__device__ bf16 g_vth[HID * C_COMM],     g_vtl[HID * C_COMM];
__device__ bf16 g_wh [17][HID * HID],    g_wl [17][HID * HID];
__device__ uint8_t g_dm8[(size_t)N_NODES * C_COMM];

__device__ int   g_hist     [NCHUNK * C_COMM];
__device__ int   g_chunkbase[NCHUNK * C_COMM];
__device__ int   g_counts [C_COMM];
__device__ int   g_offsets[C_COMM];
__device__ int   g_members[N_NODES];
__device__ float g_logc[C_COMM];
__device__ float g_inv [C_COMM];
__device__ float g_table[NDIST];

// ---------------- small PTX helpers (all sm_80-compatible) ----------------
__device__ __forceinline__ uint32_t smem_u32(const void* p) {
    uint32_t a;
    asm("{ .reg .u64 t; cvta.to.shared.u64 t, %1; cvt.u32.u64 %0, t; }" : "=r"(a) : "l"(p));
    return a;
}

__device__ __forceinline__ void cpa16(uint32_t dst, const void* src) {
    asm volatile("{ .reg .u64 g; cvta.to.global.u64 g, %1; cp.async.cg.shared.global [%0], [g], 16; }"
                 :: "r"(dst), "l"(src));
}
#define CP_COMMIT() asm volatile("cp.async.commit_group;" ::: "memory")
#define CP_WAIT1()  asm volatile("cp.async.wait_group 1;" ::: "memory")

__device__ __forceinline__ void ldm4(uint32_t* r, uint32_t addr) {
    asm volatile("ldmatrix.sync.aligned.m8n8.x4.shared.b16 {%0,%1,%2,%3}, [%4];"
                 : "=r"(r[0]), "=r"(r[1]), "=r"(r[2]), "=r"(r[3]) : "r"(addr));
}

__device__ __forceinline__ void mma_bf16(float* d, const uint32_t* a, const uint32_t* b) {
    asm volatile(
        "mma.sync.aligned.m16n8k16.row.col.f32.bf16.bf16.f32 "
        "{%0,%1,%2,%3}, {%4,%5,%6,%7}, {%8,%9}, {%0,%1,%2,%3};"
        : "+f"(d[0]), "+f"(d[1]), "+f"(d[2]), "+f"(d[3])
        : "r"(a[0]), "r"(a[1]), "r"(a[2]), "r"(a[3]), "r"(b[0]), "r"(b[1]));
}

// split fp32x4 -> bf16 hi quad + bf16 lo quad
__device__ __forceinline__ void split4(float4 v, uint2& H, uint2& L) {
    bf16 hx = __float2bfloat16(v.x), hy = __float2bfloat16(v.y);
    bf16 hz = __float2bfloat16(v.z), hw = __float2bfloat16(v.w);
    H.x = (uint32_t)__bfloat16_as_ushort(hx) | ((uint32_t)__bfloat16_as_ushort(hy) << 16);
    H.y = (uint32_t)__bfloat16_as_ushort(hz) | ((uint32_t)__bfloat16_as_ushort(hw) << 16);
    bf16 lx = __float2bfloat16(v.x - __bfloat162float(hx));
    bf16 ly = __float2bfloat16(v.y - __bfloat162float(hy));
    bf16 lz = __float2bfloat16(v.z - __bfloat162float(hz));
    bf16 lw = __float2bfloat16(v.w - __bfloat162float(hw));
    L.x = (uint32_t)__bfloat16_as_ushort(lx) | ((uint32_t)__bfloat16_as_ushort(ly) << 16);
    L.y = (uint32_t)__bfloat16_as_ushort(lz) | ((uint32_t)__bfloat16_as_ushort(lw) << 16);
}

__device__ __forceinline__ uint32_t pack_hi_lo(float a, float b, uint32_t& outlo) {
    bf16 ha = __float2bfloat16(a), hb = __float2bfloat16(b);
    bf16 la = __float2bfloat16(a - __bfloat162float(ha));
    bf16 lb = __float2bfloat16(b - __bfloat162float(hb));
    outlo = (uint32_t)__bfloat16_as_ushort(la) | ((uint32_t)__bfloat16_as_ushort(lb) << 16);
    return (uint32_t)__bfloat16_as_ushort(ha) | ((uint32_t)__bfloat16_as_ushort(hb) << 16);
}

// ---------------- warp-MMA GEMM on pre-split bf16 pairs ----------------
// C[M,N] = (Ah+Al)[M,K] . (Bh+Bl)[N,K]^T  (3-term split product)
// BM=128 x BN=64, 8 warps (4m x 2n), 3-stage cp.async pipeline, 2 CTAs/SM.
// EPI==0: +bias[z*bstride + col], optional rowinv scaling, fp32 and/or pair out.
// EPI==1: dots epilogue -> e = exp(d*scale + logc + table[dm8]); e pairs
//         + deterministic per-row partial sums to rsp[row*8 + blockIdx.x].
template<int BN, int EPI>
__global__ __launch_bounds__(256, 2)
void mma_gemm(int M, int K,
              const bf16* __restrict__ Ah, const bf16* __restrict__ Al, int lda, size_t zsA,
              const bf16* __restrict__ Bh, const bf16* __restrict__ Bl, int ldb, size_t zsB,
              const float* __restrict__ bias, int bstride,
              float* __restrict__ Cf, bf16* __restrict__ Coh, bf16* __restrict__ Col,
              int ldc, size_t zsC,
              float scale, const float* __restrict__ logc,
              const float* __restrict__ table,
              const uint8_t* __restrict__ dm, int dmld,
              float* __restrict__ rsp, const float* __restrict__ rowinv)
{
    constexpr int BM  = 128;
    constexpr int LDS = 40;
    constexpr int NW_N = BN / 32;            // 2
    constexpr int NW_M = 8 / NW_N;           // 4
    constexpr int WM  = BM / NW_M;           // 32
    constexpr int MI  = WM / 16;             // 2
    constexpr int NBT = BN * 4 / 256;        // 1
    constexpr int ASZ = BM * LDS * 2;
    constexpr int BSZ = BN * LDS * 2;
    constexpr int STAGE = 2 * ASZ + 2 * BSZ;

    extern __shared__ char smem[];
    const uint32_t uS = smem_u32(smem);

    Ah += (size_t)blockIdx.z * zsA;  Al += (size_t)blockIdx.z * zsA;
    Bh += (size_t)blockIdx.z * zsB;  Bl += (size_t)blockIdx.z * zsB;
    const int m0 = blockIdx.y * BM, n0 = blockIdx.x * BN;
    const int tid = threadIdx.x, lane = tid & 31, wid = tid >> 5;
    const int wm = wid % NW_M, wn = wid / NW_M;
    const int mbase = wm * WM, nbase = wn * 32;
    const int lr = lane & 15, lc8 = (lane >> 4) * 8;

    const int nch = K >> 5;

    auto issue = [&](int s, int kc) {
        const uint32_t sb = uS + (uint32_t)(s * STAGE);
        const int k0 = kc << 5;
        #pragma unroll
        for (int t = 0; t < 2; ++t) {
            int j = tid + t * 256, row = j >> 2, ck = j & 3;
            uint32_t off = (uint32_t)(row * 80 + ck * 16);
            size_t so = (size_t)(m0 + row) * lda + k0 + ck * 8;
            cpa16(sb + off,       Ah + so);
            cpa16(sb + ASZ + off, Al + so);
        }
        #pragma unroll
        for (int t = 0; t < NBT; ++t) {
            int j = tid + t * 256, row = j >> 2, ck = j & 3;
            uint32_t off = (uint32_t)(row * 80 + ck * 16);
            size_t so = (size_t)(n0 + row) * ldb + k0 + ck * 8;
            cpa16(sb + 2 * ASZ + off,       Bh + so);
            cpa16(sb + 2 * ASZ + BSZ + off, Bl + so);
        }
    };

    float acc[MI][4][4];
    #pragma unroll
    for (int mi = 0; mi < MI; ++mi)
        #pragma unroll
        for (int ni = 0; ni < 4; ++ni)
            #pragma unroll
            for (int q = 0; q < 4; ++q) acc[mi][ni][q] = 0.f;

    issue(0, 0); CP_COMMIT();
    if (nch > 1) issue(1, 1);
    CP_COMMIT();

    for (int ch = 0; ch < nch; ++ch) {
        CP_WAIT1();
        __syncthreads();   // publishes chunk ch AND closes stage (ch+2)%3's readers

        int nx = ch + 2;
        if (nx < nch) issue(nx % 3, nx);
        CP_COMMIT();

        const uint32_t sb = uS + (uint32_t)((ch % 3) * STAGE);
        const uint32_t uAh = sb, uAl = sb + ASZ, uBh = sb + 2 * ASZ, uBl = sb + 2 * ASZ + BSZ;
        #pragma unroll
        for (int ks = 0; ks < 2; ++ks) {
            uint32_t ah[MI][4], al[MI][4];
            #pragma unroll
            for (int mi = 0; mi < MI; ++mi) {
                uint32_t off = (uint32_t)((mbase + mi * 16 + lr) * LDS + ks * 16 + lc8) * 2;
                ldm4(ah[mi], uAh + off);
                ldm4(al[mi], uAl + off);
            }
            uint32_t bh[4][2], bl[4][2], r[4];
            uint32_t off0 = (uint32_t)((nbase + lr) * LDS + ks * 16 + lc8) * 2;
            uint32_t off1 = (uint32_t)((nbase + 16 + lr) * LDS + ks * 16 + lc8) * 2;
            ldm4(r, uBh + off0); bh[0][0] = r[0]; bh[0][1] = r[2]; bh[1][0] = r[1]; bh[1][1] = r[3];
            ldm4(r, uBh + off1); bh[2][0] = r[0]; bh[2][1] = r[2]; bh[3][0] = r[1]; bh[3][1] = r[3];
            ldm4(r, uBl + off0); bl[0][0] = r[0]; bl[0][1] = r[2]; bl[1][0] = r[1]; bl[1][1] = r[3];
            ldm4(r, uBl + off1); bl[2][0] = r[0]; bl[2][1] = r[2]; bl[3][0] = r[1]; bl[3][1] = r[3];
            #pragma unroll
            for (int mi = 0; mi < MI; ++mi)
                #pragma unroll
                for (int ni = 0; ni < 4; ++ni) {
                    mma_bf16(acc[mi][ni], ah[mi], bh[ni]);
                    mma_bf16(acc[mi][ni], ah[mi], bl[ni]);
                    mma_bf16(acc[mi][ni], al[mi], bh[ni]);
                }
        }
    }

    if (EPI == 0) {
        #pragma unroll
        for (int mi = 0; mi < MI; ++mi) {
            int r0 = m0 + mbase + mi * 16 + (lane >> 2);
            float s0 = 1.f, s1 = 1.f;
            if (rowinv) {
                s0 = rowinv[(size_t)blockIdx.z * M + r0];
                s1 = rowinv[(size_t)blockIdx.z * M + r0 + 8];
            }
            #pragma unroll
            for (int ni = 0; ni < 4; ++ni) {
                int cc = n0 + nbase + ni * 8 + (lane & 3) * 2;
                float d0 = acc[mi][ni][0], d1 = acc[mi][ni][1];
                float d2 = acc[mi][ni][2], d3 = acc[mi][ni][3];
                if (bias) {
                    const float* bz = bias + (size_t)blockIdx.z * bstride;
                    float b0 = bz[cc], b1 = bz[cc + 1];
                    d0 += b0; d1 += b1; d2 += b0; d3 += b1;
                }
                d0 *= s0; d1 *= s0; d2 *= s1; d3 *= s1;
                size_t o0 = (size_t)blockIdx.z * zsC + (size_t)r0 * ldc + cc;
                size_t o1 = (size_t)blockIdx.z * zsC + (size_t)(r0 + 8) * ldc + cc;
                if (Cf) {
                    *reinterpret_cast<float2*>(Cf + o0) = make_float2(d0, d1);
                    *reinterpret_cast<float2*>(Cf + o1) = make_float2(d2, d3);
                }
                if (Coh) {
                    uint32_t lo0, lo1;
                    uint32_t hi0 = pack_hi_lo(d0, d1, lo0);
                    uint32_t hi1 = pack_hi_lo(d2, d3, lo1);
                    *reinterpret_cast<uint32_t*>(Coh + o0) = hi0;
                    *reinterpret_cast<uint32_t*>(Col + o0) = lo0;
                    *reinterpret_cast<uint32_t*>(Coh + o1) = hi1;
                    *reinterpret_cast<uint32_t*>(Col + o1) = lo1;
                }
            }
        }
    } else {
        float rs0[MI], rs1[MI];
        #pragma unroll
        for (int mi = 0; mi < MI; ++mi) { rs0[mi] = 0.f; rs1[mi] = 0.f; }
        #pragma unroll
        for (int mi = 0; mi < MI; ++mi) {
            int r0 = m0 + mbase + mi * 16 + (lane >> 2);
            #pragma unroll
            for (int ni = 0; ni < 4; ++ni) {
                int cc = n0 + nbase + ni * 8 + (lane & 3) * 2;
                float lg0 = logc[cc], lg1 = logc[cc + 1];
                uchar2 dd0 = *reinterpret_cast<const uchar2*>(dm + (size_t)r0 * dmld + cc);
                uchar2 dd1 = *reinterpret_cast<const uchar2*>(dm + (size_t)(r0 + 8) * dmld + cc);
                float e0 = __expf(acc[mi][ni][0] * scale + lg0 + table[dd0.x]);
                float e1 = __expf(acc[mi][ni][1] * scale + lg1 + table[dd0.y]);
                float e2 = __expf(acc[mi][ni][2] * scale + lg0 + table[dd1.x]);
                float e3 = __expf(acc[mi][ni][3] * scale + lg1 + table[dd1.y]);
                size_t o0 = (size_t)blockIdx.z * zsC + (size_t)r0 * ldc + cc;
                size_t o1 = (size_t)blockIdx.z * zsC + (size_t)(r0 + 8) * ldc + cc;
                uint32_t lo0, lo1;
                uint32_t hi0 = pack_hi_lo(e0, e1, lo0);
                uint32_t hi1 = pack_hi_lo(e2, e3, lo1);
                *reinterpret_cast<uint32_t*>(Coh + o0) = hi0;
                *reinterpret_cast<uint32_t*>(Col + o0) = lo0;
                *reinterpret_cast<uint32_t*>(Coh + o1) = hi1;
                *reinterpret_cast<uint32_t*>(Col + o1) = lo1;
                rs0[mi] += e0 + e1;
                rs1[mi] += e2 + e3;
            }
        }
        __syncthreads();
        float* srs = reinterpret_cast<float*>(smem);
        #pragma unroll
        for (int mi = 0; mi < MI; ++mi) {
            float a = rs0[mi];
            a += __shfl_xor_sync(0xFFFFFFFFu, a, 1);
            a += __shfl_xor_sync(0xFFFFFFFFu, a, 2);
            float b = rs1[mi];
            b += __shfl_xor_sync(0xFFFFFFFFu, b, 1);
            b += __shfl_xor_sync(0xFFFFFFFFu, b, 2);
            if ((lane & 3) == 0) {
                int rr = mbase + mi * 16 + (lane >> 2);
                srs[wn * BM + rr]     = a;
                srs[wn * BM + rr + 8] = b;
            }
        }
        __syncthreads();
        if (tid < BM) {
            float part = srs[tid] + srs[BM + tid];
            rsp[((size_t)blockIdx.z * (size_t)M + m0 + tid) * 8 + blockIdx.x] = part;
        }
    }
}

// ---------------- 1/rowsum from 8 deterministic partials ----------------
__global__ void rowsum_reduce_kernel(const float* __restrict__ rsp,
                                     float* __restrict__ rinv, int n) {
    int i = blockIdx.x * blockDim.x + threadIdx.x;
    if (i < n) {
        const float* p = rsp + (size_t)i * 8;
        float s = 0.f;
        #pragma unroll
        for (int j = 0; j < 8; ++j) s += p[j];
        rinv[i] = 1.0f / s;
    }
}

// ---------------- split fp32 -> bf16 pair (elementwise) ----------------
__global__ void split_kernel(const float4* __restrict__ in, uint2* __restrict__ outH,
                             uint2* __restrict__ outL, int n4) {
    int i = blockIdx.x * blockDim.x + threadIdx.x;
    if (i < n4) {
        uint2 H, L; split4(in[i], H, L);
        outH[i] = H; outL[i] = L;
    }
}

// ---------------- dm int32 -> uint8 ----------------
__global__ void dm8_kernel(const int4* __restrict__ in, uchar4* __restrict__ out, int n4) {
    int i = blockIdx.x * blockDim.x + threadIdx.x;
    if (i < n4) {
        int4 v = in[i];
        out[i] = make_uchar4((uint8_t)v.x, (uint8_t)v.y, (uint8_t)v.z, (uint8_t)v.w);
    }
}

// ---------------- batched transpose + split: out[z][C,R] = in[z][R,C]^T ----------------
__global__ void transpose_split_kernel(const float* __restrict__ in, size_t zsIn,
                                       bf16* __restrict__ outH, bf16* __restrict__ outL,
                                       size_t zsOut, int R, int Ccols) {
    __shared__ float tile[32][33];
    in   += (size_t)blockIdx.z * zsIn;
    outH += (size_t)blockIdx.z * zsOut;
    outL += (size_t)blockIdx.z * zsOut;
    int c0 = blockIdx.x * 32, r0 = blockIdx.y * 32;
    int x = threadIdx.x, y = threadIdx.y;           // 32 x 8
    #pragma unroll
    for (int j = 0; j < 32; j += 8)
        tile[y + j][x] = in[(size_t)(r0 + y + j) * Ccols + c0 + x];
    __syncthreads();
    #pragma unroll
    for (int j = 0; j < 32; j += 8) {
        float v = tile[x][y + j];
        bf16 h = __float2bfloat16(v);
        bf16 l = __float2bfloat16(v - __bfloat162float(h));
        size_t o = (size_t)(c0 + y + j) * R + r0 + x;
        outH[o] = h; outL[o] = l;
    }
}

// ---------------- transpose pair input (recombine) + re-split ----------------
__global__ void transpose_resplit_kernel(const bf16* __restrict__ inH,
                                         const bf16* __restrict__ inL,
                                         bf16* __restrict__ outH, bf16* __restrict__ outL,
                                         int R, int Ccols) {
    __shared__ float tile[32][33];
    int c0 = blockIdx.x * 32, r0 = blockIdx.y * 32;
    int x = threadIdx.x, y = threadIdx.y;
    #pragma unroll
    for (int j = 0; j < 32; j += 8) {
        size_t o = (size_t)(r0 + y + j) * Ccols + c0 + x;
        tile[y + j][x] = __bfloat162float(inH[o]) + __bfloat162float(inL[o]);
    }
    __syncthreads();
    #pragma unroll
    for (int j = 0; j < 32; j += 8) {
        float v = tile[x][y + j];
        bf16 h = __float2bfloat16(v);
        bf16 l = __float2bfloat16(v - __bfloat162float(h));
        size_t o = (size_t)(c0 + y + j) * R + r0 + x;
        outH[o] = h; outL[o] = l;
    }
}

// ---------------- fused q bias ----------------
__global__ void fuse_bias_kernel(const float* __restrict__ bproj,
                                 const float* __restrict__ Wq,
                                 const float* __restrict__ bq,
                                 float* __restrict__ out) {
    int o = blockIdx.x * blockDim.x + threadIdx.x;
    float s = bq[o];
    for (int k = 0; k < HID; k++) s += bproj[k] * Wq[(size_t)k * HID + o];
    out[o] = s;
}

// ---------------- copy bk/bv into adjacent scratch [l][2][HID] ----------------
__global__ void copy_bkv_kernel(const float* __restrict__ bk, const float* __restrict__ bv,
                                float* __restrict__ out) {
    int i = blockIdx.x * blockDim.x + threadIdx.x;      // NLAYER*HID
    int l = i / HID, c = i % HID;
    out[(l * 2) * HID + c]     = bk[i];
    out[(l * 2 + 1) * HID + c] = bv[i];
}

// ---------------- community preprocessing (deterministic, stable) ----------------
__global__ void hist_kernel(const int* __restrict__ ntc) {
    __shared__ int sh[C_COMM];
    int chunk = blockIdx.x;
    for (int i = threadIdx.x; i < C_COMM; i += blockDim.x) sh[i] = 0;
    __syncthreads();
    atomicAdd(&sh[ntc[chunk * CHUNK + threadIdx.x]], 1);
    __syncthreads();
    for (int i = threadIdx.x; i < C_COMM; i += blockDim.x)
        g_hist[chunk * C_COMM + i] = sh[i];
}

__global__ void chunk_scan_kernel() {
    int c = blockIdx.x;
    __shared__ int s[NCHUNK];
    int t = threadIdx.x;
    int own = g_hist[t * C_COMM + c];
    s[t] = own;
    __syncthreads();
    for (int off = 1; off < NCHUNK; off <<= 1) {
        int v = (t >= off) ? s[t - off] : 0;
        __syncthreads();
        s[t] += v;
        __syncthreads();
    }
    g_chunkbase[t * C_COMM + c] = s[t] - own;
    if (t == NCHUNK - 1) g_counts[c] = s[t];
}

__global__ void offsets_kernel() {
    __shared__ int s[C_COMM];
    int t = threadIdx.x;
    int own = g_counts[t];
    s[t] = own;
    __syncthreads();
    for (int off = 1; off < C_COMM; off <<= 1) {
        int v = (t >= off) ? s[t - off] : 0;
        __syncthreads();
        s[t] += v;
        __syncthreads();
    }
    g_offsets[t] = s[t] - own;
    g_logc[t]    = logf((float)own);
    g_inv[t]     = 1.0f / (float)(own > 0 ? own : 1);
}

__global__ void scatter_kernel(const int* __restrict__ ntc) {
    __shared__ int s[CHUNK];
    int chunk = blockIdx.x;
    int t = threadIdx.x;
    int node = chunk * CHUNK + t;
    int c = ntc[node];
    s[t] = c;
    __syncthreads();
    int lrank = 0;
    for (int j = 0; j < t; j++) lrank += (s[j] == c);
    g_members[g_offsets[c] + g_chunkbase[chunk * C_COMM + c] + lrank] = node;
}

__global__ void comm_avg_kernel() {
    int c = blockIdx.x;
    int t = threadIdx.x;
    int off = g_offsets[c], cnt = g_counts[c];
    float a0 = 0.f, a1 = 0.f;
    for (int m = 0; m < cnt; m++) {
        const float* row = g_h + (size_t)g_members[off + m] * HID;
        a0 += row[t];
        a1 += row[t + 256];
    }
    float inv = g_inv[c];
    a0 *= inv; a1 *= inv;
    bf16 h0 = __float2bfloat16(a0), h1 = __float2bfloat16(a1);
    g_cmh[c * HID + t]       = h0;
    g_cmh[c * HID + t + 256] = h1;
    g_cml[c * HID + t]       = __float2bfloat16(a0 - __bfloat162float(h0));
    g_cml[c * HID + t + 256] = __float2bfloat16(a1 - __bfloat162float(h1));
}

__global__ void bias_table_kernel(const float* __restrict__ emb,
                                  const float* __restrict__ w,
                                  const float* __restrict__ bptr) {
    int i = blockIdx.x;
    int t = threadIdx.x;
    float s = emb[i * HID + t]       * w[t]
            + emb[i * HID + t + 128] * w[t + 128]
            + emb[i * HID + t + 256] * w[t + 256]
            + emb[i * HID + t + 384] * w[t + 384];
    for (int o = 16; o; o >>= 1) s += __shfl_xor_sync(0xFFFFFFFFu, s, o);
    __shared__ float r[4];
    if ((t & 31) == 0) r[t >> 5] = s;
    __syncthreads();
    if (t == 0) g_table[i] = r[0] + r[1] + r[2] + r[3] + bptr[0];
}

// warp-per-row LayerNorm + ReLU; fp32 (optional) + bf16 pair outputs
__global__ void ln_relu_kernel(const float* __restrict__ in, float* __restrict__ outF,
                               bf16* __restrict__ outH, bf16* __restrict__ outL,
                               const float* __restrict__ g, const float* __restrict__ b) {
    int w = threadIdx.x >> 5, lane = threadIdx.x & 31;
    size_t row = (size_t)blockIdx.x * 8 + w;
    const float* x = in + row * HID;
    float4 v[4];
    float s = 0.f, q = 0.f;
    #pragma unroll
    for (int k = 0; k < 4; k++) {
        v[k] = *reinterpret_cast<const float4*>(x + k * 128 + lane * 4);
        s += v[k].x + v[k].y + v[k].z + v[k].w;
        q += v[k].x * v[k].x + v[k].y * v[k].y + v[k].z * v[k].z + v[k].w * v[k].w;
    }
    #pragma unroll
    for (int o = 16; o; o >>= 1) {
        s += __shfl_xor_sync(0xFFFFFFFFu, s, o);
        q += __shfl_xor_sync(0xFFFFFFFFu, q, o);
    }
    float mean = s * (1.0f / HID);
    float var  = q * (1.0f / HID) - mean * mean;
    float rstd = rsqrtf(var + EPS);
    #pragma unroll
    for (int k = 0; k < 4; k++) {
        int c = k * 128 + lane * 4;
        float4 gg = *reinterpret_cast<const float4*>(g + c);
        float4 bb = *reinterpret_cast<const float4*>(b + c);
        float4 y;
        y.x = fmaxf((v[k].x - mean) * rstd * gg.x + bb.x, 0.f);
        y.y = fmaxf((v[k].y - mean) * rstd * gg.y + bb.y, 0.f);
        y.z = fmaxf((v[k].z - mean) * rstd * gg.z + bb.z, 0.f);
        y.w = fmaxf((v[k].w - mean) * rstd * gg.w + bb.w, 0.f);
        if (outF) *reinterpret_cast<float4*>(outF + row * HID + c) = y;
        uint2 H, L; split4(y, H, L);
        *reinterpret_cast<uint2*>(outH + row * HID + c) = H;
        *reinterpret_cast<uint2*>(outL + row * HID + c) = L;
    }
}

// ---------------- host-side helpers ----------------
static const int SMEM_G = 3 * (2 * 128 * 80 + 2 * 64 * 80);  // 92160 per CTA

static void tc_nn(int M, int Nc, int K,
                  const bf16* Ah, const bf16* Al, int lda,
                  const bf16* Bth, const bf16* Btl,
                  const float* bias,
                  float* Cf, bf16* Coh, bf16* Col, int ldc)
{
    dim3 g(Nc / 64, M / 128, 1);
    mma_gemm<64, 0><<<g, 256, SMEM_G>>>(M, K, Ah, Al, lda, 0, Bth, Btl, K, 0,
                                        bias, 0, Cf, Coh, Col, ldc, 0,
                                        0.f, nullptr, nullptr, nullptr, 0,
                                        nullptr, nullptr);
}

extern "C" void kernel_launch(void* const* d_in, const int* in_sizes, int n_in,
                              void* d_out, int out_size)
{
    // ---- input mapping (auto-detect metadata order) ----
    const float *x      = (const float*)d_in[0];
    const int   *dm     = (const int*)  d_in[1];
    const int   *ntc    = (const int*)  d_in[2];
    const float *W_in1  = (const float*)d_in[3];
    const float *b_in1  = (const float*)d_in[4];
    const float *ln_in_g= (const float*)d_in[5];
    const float *ln_in_b= (const float*)d_in[6];
    const float *W_in2  = (const float*)d_in[7];
    const float *b_in2  = (const float*)d_in[8];
    const float *Wproj, *Wq, *Wk, *Wv, *ffW1, *ffW2;
    const float *bproj, *bq, *bk, *bv, *ffb1, *ffb2;
    const float *dis_emb, *dis_w, *dis_b;
    const float *ffg1, *ffbeta1, *ffg2, *ffbeta2, *Wout, *bout;

    if (in_sizes[10] == NLAYER * HID * HID) {
        Wproj  = (const float*)d_in[9];  Wq     = (const float*)d_in[10];
        Wk     = (const float*)d_in[11]; Wv     = (const float*)d_in[12];
        ffW1   = (const float*)d_in[13]; ffW2   = (const float*)d_in[14];
        bproj  = (const float*)d_in[15]; bq     = (const float*)d_in[16];
        bk     = (const float*)d_in[17]; bv     = (const float*)d_in[18];
        ffb1   = (const float*)d_in[19]; ffb2   = (const float*)d_in[20];
        dis_emb= (const float*)d_in[21]; dis_w  = (const float*)d_in[22];
        dis_b  = (const float*)d_in[23];
        ffg1   = (const float*)d_in[24]; ffbeta1= (const float*)d_in[25];
        ffg2   = (const float*)d_in[26]; ffbeta2= (const float*)d_in[27];
        Wout   = (const float*)d_in[28]; bout   = (const float*)d_in[29];
    } else {
        Wproj  = (const float*)d_in[9];  bproj  = (const float*)d_in[10];
        Wq     = (const float*)d_in[11]; bq     = (const float*)d_in[12];
        Wk     = (const float*)d_in[13]; bk     = (const float*)d_in[14];
        Wv     = (const float*)d_in[15]; bv     = (const float*)d_in[16];
        dis_emb= (const float*)d_in[17]; dis_w  = (const float*)d_in[18];
        dis_b  = (const float*)d_in[19];
        ffW1   = (const float*)d_in[20]; ffb1   = (const float*)d_in[21];
        ffg1   = (const float*)d_in[22]; ffbeta1= (const float*)d_in[23];
        ffW2   = (const float*)d_in[24]; ffb2   = (const float*)d_in[25];
        ffg2   = (const float*)d_in[26]; ffbeta2= (const float*)d_in[27];
        Wout   = (const float*)d_in[28]; bout   = (const float*)d_in[29];
    }

    cudaFuncSetAttribute(mma_gemm<64, 0>, cudaFuncAttributeMaxDynamicSharedMemorySize, SMEM_G);
    cudaFuncSetAttribute(mma_gemm<64, 1>, cudaFuncAttributeMaxDynamicSharedMemorySize, SMEM_G);

    // ---- scratch pointers ----
    float *p_h, *p_t0, *p_t1, *p_logc, *p_table, *p_bfq, *p_bkv, *p_rsp, *p_rinv;
    bf16 *p_xh, *p_xl, *p_hh, *p_hl, *p_t0h, *p_t0l, *p_t1h, *p_t1l, *p_qh, *p_ql;
    bf16 *p_ph, *p_pl, *p_cmh, *p_cml, *p_kvh, *p_kvl, *p_vth, *p_vtl, *p_wh, *p_wl;
    uint8_t *p_dm8;
    cudaGetSymbolAddress((void**)&p_h,    g_h);
    cudaGetSymbolAddress((void**)&p_t0,   g_t0);
    cudaGetSymbolAddress((void**)&p_t1,   g_t1);
    cudaGetSymbolAddress((void**)&p_logc, g_logc);
    cudaGetSymbolAddress((void**)&p_table,g_table);
    cudaGetSymbolAddress((void**)&p_bfq,  g_bfq);
    cudaGetSymbolAddress((void**)&p_bkv,  g_bkv);
    cudaGetSymbolAddress((void**)&p_rsp,  g_rsp);
    cudaGetSymbolAddress((void**)&p_rinv, g_rinv);
    cudaGetSymbolAddress((void**)&p_dm8,  g_dm8);
    cudaGetSymbolAddress((void**)&p_xh,  g_xh);  cudaGetSymbolAddress((void**)&p_xl,  g_xl);
    cudaGetSymbolAddress((void**)&p_hh,  g_hh);  cudaGetSymbolAddress((void**)&p_hl,  g_hl);
    cudaGetSymbolAddress((void**)&p_t0h, g_t0h); cudaGetSymbolAddress((void**)&p_t0l, g_t0l);
    cudaGetSymbolAddress((void**)&p_t1h, g_t1h); cudaGetSymbolAddress((void**)&p_t1l, g_t1l);
    cudaGetSymbolAddress((void**)&p_qh,  g_qh);  cudaGetSymbolAddress((void**)&p_ql,  g_ql);
    cudaGetSymbolAddress((void**)&p_ph,  g_ph);  cudaGetSymbolAddress((void**)&p_pl,  g_pl);
    cudaGetSymbolAddress((void**)&p_cmh, g_cmh); cudaGetSymbolAddress((void**)&p_cml, g_cml);
    cudaGetSymbolAddress((void**)&p_kvh, g_kvh); cudaGetSymbolAddress((void**)&p_kvl, g_kvl);
    cudaGetSymbolAddress((void**)&p_vth, g_vth); cudaGetSymbolAddress((void**)&p_vtl, g_vtl);
    cudaGetSymbolAddress((void**)&p_wh,  g_wh);  cudaGetSymbolAddress((void**)&p_wl,  g_wl);
    #define WH(i) (p_wh + (size_t)(i) * HID * HID)
    #define WL(i) (p_wl + (size_t)(i) * HID * HID)

    const float scale = 1.0f / sqrtf((float)DHEAD);
    const size_t W2 = (size_t)HID * HID;

    // ---- weight preprocessing (batched) ----
    // slots: 0=W_in1T 1=W_in2T; layer l: s0=2+l*5 {0:WfqT,1:WkT,2:WvT,3:ffW1T,4:ffW2T};
    // 12=WoutT; 13,14=WqT l0,l1; 15,16=Wproj split l0,l1
    {
        dim3 b(32, 8);
        transpose_split_kernel<<<dim3(HID / 32, IN_DIM / 32, 1), b>>>(
            W_in1, 0, WH(0), WL(0), 0, IN_DIM, HID);
        transpose_split_kernel<<<dim3(HID / 32, HID / 32, 1), b>>>(
            W_in2, 0, WH(1), WL(1), 0, HID, HID);
        transpose_split_kernel<<<dim3(OUT_DIM / 32, HID / 32, 1), b>>>(
            Wout, 0, WH(12), WL(12), 0, HID, OUT_DIM);
        transpose_split_kernel<<<dim3(HID / 32, HID / 32, NLAYER), b>>>(
            Wq, W2, WH(13), WL(13), W2, HID, HID);
        transpose_split_kernel<<<dim3(HID / 32, HID / 32, NLAYER), b>>>(
            Wk, W2, WH(3), WL(3), 5 * W2, HID, HID);
        transpose_split_kernel<<<dim3(HID / 32, HID / 32, NLAYER), b>>>(
            Wv, W2, WH(4), WL(4), 5 * W2, HID, HID);
        transpose_split_kernel<<<dim3(HID / 32, HID / 32, NLAYER), b>>>(
            ffW1, W2, WH(5), WL(5), 5 * W2, HID, HID);
        transpose_split_kernel<<<dim3(HID / 32, HID / 32, NLAYER), b>>>(
            ffW2, W2, WH(6), WL(6), 5 * W2, HID, HID);
    }
    split_kernel<<<N_NODES * IN_DIM / 1024, 256>>>((const float4*)x, (uint2*)p_xh, (uint2*)p_xl,
                                                   N_NODES * IN_DIM / 4);
    split_kernel<<<NLAYER * HID * HID / 1024, 256>>>((const float4*)Wproj,
                                                     (uint2*)WH(15), (uint2*)WL(15),
                                                     NLAYER * HID * HID / 4);
    // fused q weight (both layers): WfqT[o,i] = sum_k WqT[o,k] * Wproj[i,k]
    {
        dim3 g(HID / 64, HID / 128, NLAYER);
        mma_gemm<64, 0><<<g, 256, SMEM_G>>>(HID, HID,
                                            WH(13), WL(13), HID, W2,
                                            WH(15), WL(15), HID, W2,
                                            nullptr, 0, nullptr, WH(2), WL(2), HID, 5 * W2,
                                            0.f, nullptr, nullptr, nullptr, 0,
                                            nullptr, nullptr);
    }
    for (int l = 0; l < NLAYER; l++)
        fuse_bias_kernel<<<HID / 256, 256>>>(bproj + (size_t)l * HID,
                                             Wq + (size_t)l * W2,
                                             bq + (size_t)l * HID, p_bfq + (size_t)l * HID);
    copy_bkv_kernel<<<NLAYER * HID / 256, 256>>>(bk, bv, p_bkv);
    dm8_kernel<<<(int)((size_t)N_NODES * C_COMM / 1024), 256>>>(
        (const int4*)dm, (uchar4*)p_dm8, (int)((size_t)N_NODES * C_COMM / 4));

    // ---- community preprocessing (deterministic) ----
    hist_kernel      <<<NCHUNK, CHUNK>>>(ntc);
    chunk_scan_kernel<<<C_COMM, NCHUNK>>>();
    offsets_kernel   <<<1, C_COMM>>>();
    scatter_kernel   <<<NCHUNK, CHUNK>>>(ntc);

    // ---- fc_in ----
    tc_nn(N_NODES, HID, IN_DIM, p_xh, p_xl, IN_DIM, WH(0), WL(0), b_in1,
          p_t0, nullptr, nullptr, HID);
    ln_relu_kernel<<<N_NODES / 8, 256>>>(p_t0, nullptr, p_t0h, p_t0l, ln_in_g, ln_in_b);
    tc_nn(N_NODES, HID, HID, p_t0h, p_t0l, HID, WH(1), WL(1), b_in2,
          p_h, p_hh, p_hl, HID);

    // ---- layers ----
    for (int l = 0; l < NLAYER; l++) {
        int s0 = 2 + l * 5;
        bias_table_kernel<<<NDIST, 128>>>(dis_emb + (size_t)l * NDIST * HID,
                                          dis_w + (size_t)l * HID, dis_b + l);
        comm_avg_kernel<<<C_COMM, 256>>>();

        // q = h @ WfqT^T + bfq
        tc_nn(N_NODES, HID, HID, p_hh, p_hl, HID, WH(s0), WL(s0),
              p_bfq + (size_t)l * HID, nullptr, p_qh, p_ql, HID);
        // k and v in one launch (z: 0=k, 1=v), pair outputs adjacent
        {
            dim3 g(HID / 64, C_COMM / 128, 2);
            mma_gemm<64, 0><<<g, 256, SMEM_G>>>(
                C_COMM, HID,
                p_cmh, p_cml, HID, 0,
                WH(s0 + 1), WL(s0 + 1), HID, W2,
                p_bkv + (size_t)l * 2 * HID, HID,
                nullptr, p_kvh, p_kvl, HID, (size_t)C_COMM * HID,
                0.f, nullptr, nullptr, nullptr, 0,
                nullptr, nullptr);
        }
        transpose_resplit_kernel<<<dim3(HID / 32, C_COMM / 32), dim3(32, 8)>>>(
            p_kvh + (size_t)C_COMM * HID, p_kvl + (size_t)C_COMM * HID,
            p_vth, p_vtl, C_COMM, HID);

        // dots per head: fused exp epilogue -> unnormalized e pairs + row partial sums
        {
            dim3 g(C_COMM / 64, N_NODES / 128, NHEAD);
            mma_gemm<64, 1><<<g, 256, SMEM_G>>>(
                N_NODES, DHEAD,
                p_qh, p_ql, HID, (size_t)DHEAD,
                p_kvh, p_kvl, HID, (size_t)DHEAD,
                nullptr, 0,
                nullptr, p_ph, p_pl, C_COMM, (size_t)N_NODES * C_COMM,
                scale, p_logc, p_table, p_dm8, C_COMM,
                p_rsp, nullptr);
        }
        rowsum_reduce_kernel<<<NHEAD * N_NODES / 256, 256>>>(p_rsp, p_rinv, NHEAD * N_NODES);

        // AV per head: multiply by 1/rowsum in epilogue -> t0 split
        {
            dim3 g(DHEAD / 64, N_NODES / 128, NHEAD);
            mma_gemm<64, 0><<<g, 256, SMEM_G>>>(
                N_NODES, C_COMM,
                p_ph, p_pl, C_COMM, (size_t)N_NODES * C_COMM,
                p_vth, p_vtl, C_COMM, (size_t)DHEAD * C_COMM,
                nullptr, 0,
                nullptr, p_t0h, p_t0l, HID, (size_t)DHEAD,
                0.f, nullptr, nullptr, nullptr, 0,
                nullptr, p_rinv);
        }

        tc_nn(N_NODES, HID, HID, p_t0h, p_t0l, HID, WH(s0 + 3), WL(s0 + 3),
              ffb1 + (size_t)l * HID, p_t1, nullptr, nullptr, HID);
        ln_relu_kernel<<<N_NODES / 8, 256>>>(p_t1, nullptr, p_t1h, p_t1l,
                                             ffg1 + (size_t)l * HID, ffbeta1 + (size_t)l * HID);
        tc_nn(N_NODES, HID, HID, p_t1h, p_t1l, HID, WH(s0 + 4), WL(s0 + 4),
              ffb2 + (size_t)l * HID, p_t0, nullptr, nullptr, HID);
        ln_relu_kernel<<<N_NODES / 8, 256>>>(p_t0, p_h, p_hh, p_hl,
                                             ffg2 + (size_t)l * HID, ffbeta2 + (size_t)l * HID);
    }

    // ---- output projection ----
    tc_nn(N_NODES, OUT_DIM, HID, p_hh, p_hl, HID, WH(12), WL(12), bout,
          (float*)d_out, nullptr, nullptr, OUT_DIM);
}

// round 14
// speedup vs baseline: 3.2756x; 1.2087x over previous
#include <cuda_runtime.h>
#include <cuda_fp16.h>
#include <math.h>
#include <stdint.h>

// ---------------- problem constants ----------------
#define N_NODES 32768
#define C_COMM  512
#define IN_DIM  128
#define HID     512
#define NHEAD   4
#define DHEAD   128
#define NLAYER  2
#define OUT_DIM 64
#define NDIST   31
#define EPS     1e-5f

#define CHUNK   256
#define NCHUNK  (N_NODES / CHUNK)   // 128

typedef __half f16;

// ---------------- scratch (device globals; no allocation allowed) ----------------
__device__ float g_h   [N_NODES * HID];
__device__ float g_t0  [N_NODES * HID];
__device__ float g_t1  [N_NODES * HID];
__device__ float g_bfq [NLAYER * HID];
__device__ float g_bkv [NLAYER * 2 * HID];
__device__ float g_rsp [(size_t)NHEAD * N_NODES * 8];
__device__ float g_rinv[(size_t)NHEAD * N_NODES];

__device__ f16 g_xh [N_NODES * IN_DIM], g_xl [N_NODES * IN_DIM];
__device__ f16 g_hh [N_NODES * HID],    g_hl [N_NODES * HID];
__device__ f16 g_t0h[N_NODES * HID],    g_t0l[N_NODES * HID];
__device__ f16 g_t1h[N_NODES * HID],    g_t1l[N_NODES * HID];
__device__ f16 g_qh [N_NODES * HID],    g_ql [N_NODES * HID];
__device__ f16 g_ph [(size_t)NHEAD * N_NODES * C_COMM];
__device__ f16 g_pl [(size_t)NHEAD * N_NODES * C_COMM];
__device__ f16 g_cmh[C_COMM * HID],     g_cml[C_COMM * HID];
__device__ f16 g_kvh[2 * C_COMM * HID], g_kvl[2 * C_COMM * HID];   // [k; v]
__device__ f16 g_vth[HID * C_COMM],     g_vtl[HID * C_COMM];
__device__ f16 g_wh [17][HID * HID],    g_wl [17][HID * HID];
__device__ uint8_t g_dm8[(size_t)N_NODES * C_COMM];

__device__ int   g_hist     [NCHUNK * C_COMM];
__device__ int   g_chunkbase[NCHUNK * C_COMM];
__device__ int   g_counts [C_COMM];
__device__ int   g_offsets[C_COMM];
__device__ int   g_members[N_NODES];
__device__ float g_logc[C_COMM];
__device__ float g_inv [C_COMM];
__device__ float g_table[NDIST];

// ---------------- small PTX helpers (all sm_80-compatible) ----------------
__device__ __forceinline__ uint32_t smem_u32(const void* p) {
    uint32_t a;
    asm("{ .reg .u64 t; cvta.to.shared.u64 t, %1; cvt.u32.u64 %0, t; }" : "=r"(a) : "l"(p));
    return a;
}

__device__ __forceinline__ void cpa16(uint32_t dst, const void* src) {
    asm volatile("{ .reg .u64 g; cvta.to.global.u64 g, %1; cp.async.cg.shared.global [%0], [g], 16; }"
                 :: "r"(dst), "l"(src));
}
#define CP_COMMIT() asm volatile("cp.async.commit_group;" ::: "memory")
#define CP_WAIT1()  asm volatile("cp.async.wait_group 1;" ::: "memory")

__device__ __forceinline__ void ldm4(uint32_t* r, uint32_t addr) {
    asm volatile("ldmatrix.sync.aligned.m8n8.x4.shared.b16 {%0,%1,%2,%3}, [%4];"
                 : "=r"(r[0]), "=r"(r[1]), "=r"(r[2]), "=r"(r[3]) : "r"(addr));
}

__device__ __forceinline__ void mma_f16(float* d, const uint32_t* a, const uint32_t* b) {
    asm volatile(
        "mma.sync.aligned.m16n8k16.row.col.f32.f16.f16.f32 "
        "{%0,%1,%2,%3}, {%4,%5,%6,%7}, {%8,%9}, {%0,%1,%2,%3};"
        : "+f"(d[0]), "+f"(d[1]), "+f"(d[2]), "+f"(d[3])
        : "r"(a[0]), "r"(a[1]), "r"(a[2]), "r"(a[3]), "r"(b[0]), "r"(b[1]));
}

// split fp32x4 -> fp16 hi quad + fp16 lo quad
__device__ __forceinline__ void split4(float4 v, uint2& H, uint2& L) {
    f16 hx = __float2half(v.x), hy = __float2half(v.y);
    f16 hz = __float2half(v.z), hw = __float2half(v.w);
    H.x = (uint32_t)__half_as_ushort(hx) | ((uint32_t)__half_as_ushort(hy) << 16);
    H.y = (uint32_t)__half_as_ushort(hz) | ((uint32_t)__half_as_ushort(hw) << 16);
    f16 lx = __float2half(v.x - __half2float(hx));
    f16 ly = __float2half(v.y - __half2float(hy));
    f16 lz = __float2half(v.z - __half2float(hz));
    f16 lw = __float2half(v.w - __half2float(hw));
    L.x = (uint32_t)__half_as_ushort(lx) | ((uint32_t)__half_as_ushort(ly) << 16);
    L.y = (uint32_t)__half_as_ushort(lz) | ((uint32_t)__half_as_ushort(lw) << 16);
}

__device__ __forceinline__ uint32_t pack_hi_lo(float a, float b, uint32_t& outlo) {
    f16 ha = __float2half(a), hb = __float2half(b);
    f16 la = __float2half(a - __half2float(ha));
    f16 lb = __float2half(b - __half2float(hb));
    outlo = (uint32_t)__half_as_ushort(la) | ((uint32_t)__half_as_ushort(lb) << 16);
    return (uint32_t)__half_as_ushort(ha) | ((uint32_t)__half_as_ushort(hb) << 16);
}

// ---------------- warp-MMA GEMM on pre-split fp16 pairs ----------------
// TERMS==3: C = (Ah+Al)(Bh+Bl)^T 3-term.  TERMS==2: C = (Ah+Al)Bh^T (Bl unused).
// BM=128 x BN=64, 8 warps (4m x 2n), 3-stage cp.async pipeline, 2 CTAs/SM.
// EPI==0: +bias[z*bstride + col], optional rowinv scaling, fp32 and/or pair out.
// EPI==1: dots epilogue -> e = exp(d*scale + logc + table[dm8]); e pairs
//         + deterministic per-row partial sums to rsp[row*8 + blockIdx.x].
template<int BN, int EPI, int TERMS>
__global__ __launch_bounds__(256, 2)
void mma_gemm(int M, int K,
              const f16* __restrict__ Ah, const f16* __restrict__ Al, int lda, size_t zsA,
              const f16* __restrict__ Bh, const f16* __restrict__ Bl, int ldb, size_t zsB,
              const float* __restrict__ bias, int bstride,
              float* __restrict__ Cf, f16* __restrict__ Coh, f16* __restrict__ Col,
              int ldc, size_t zsC,
              float scale, const float* __restrict__ logc,
              const float* __restrict__ table,
              const uint8_t* __restrict__ dm, int dmld,
              float* __restrict__ rsp, const float* __restrict__ rowinv)
{
    constexpr int BM  = 128;
    constexpr int LDS = 40;
    constexpr int NW_N = BN / 32;            // 2
    constexpr int NW_M = 8 / NW_N;           // 4
    constexpr int WM  = BM / NW_M;           // 32
    constexpr int MI  = WM / 16;             // 2
    constexpr int NBT = BN * 4 / 256;        // 1
    constexpr int ASZ = BM * LDS * 2;
    constexpr int BSZ = BN * LDS * 2;
    constexpr int STAGE = 2 * ASZ + 2 * BSZ;

    extern __shared__ char smem[];
    const uint32_t uS = smem_u32(smem);

    Ah += (size_t)blockIdx.z * zsA;  Al += (size_t)blockIdx.z * zsA;
    Bh += (size_t)blockIdx.z * zsB;
    if (TERMS == 3) Bl += (size_t)blockIdx.z * zsB;
    const int m0 = blockIdx.y * BM, n0 = blockIdx.x * BN;
    const int tid = threadIdx.x, lane = tid & 31, wid = tid >> 5;
    const int wm = wid % NW_M, wn = wid / NW_M;
    const int mbase = wm * WM, nbase = wn * 32;
    const int lr = lane & 15, lc8 = (lane >> 4) * 8;

    const int nch = K >> 5;

    auto issue = [&](int s, int kc) {
        const uint32_t sb = uS + (uint32_t)(s * STAGE);
        const int k0 = kc << 5;
        #pragma unroll
        for (int t = 0; t < 2; ++t) {
            int j = tid + t * 256, row = j >> 2, ck = j & 3;
            uint32_t off = (uint32_t)(row * 80 + ck * 16);
            size_t so = (size_t)(m0 + row) * lda + k0 + ck * 8;
            cpa16(sb + off,       Ah + so);
            cpa16(sb + ASZ + off, Al + so);
        }
        #pragma unroll
        for (int t = 0; t < NBT; ++t) {
            int j = tid + t * 256, row = j >> 2, ck = j & 3;
            uint32_t off = (uint32_t)(row * 80 + ck * 16);
            size_t so = (size_t)(n0 + row) * ldb + k0 + ck * 8;
            cpa16(sb + 2 * ASZ + off, Bh + so);
            if (TERMS == 3) cpa16(sb + 2 * ASZ + BSZ + off, Bl + so);
        }
    };

    float acc[MI][4][4];
    #pragma unroll
    for (int mi = 0; mi < MI; ++mi)
        #pragma unroll
        for (int ni = 0; ni < 4; ++ni)
            #pragma unroll
            for (int q = 0; q < 4; ++q) acc[mi][ni][q] = 0.f;

    issue(0, 0); CP_COMMIT();
    if (nch > 1) issue(1, 1);
    CP_COMMIT();

    for (int ch = 0; ch < nch; ++ch) {
        CP_WAIT1();
        __syncthreads();   // publishes chunk ch AND closes stage (ch+2)%3's readers

        int nx = ch + 2;
        if (nx < nch) issue(nx % 3, nx);
        CP_COMMIT();

        const uint32_t sb = uS + (uint32_t)((ch % 3) * STAGE);
        const uint32_t uAh = sb, uAl = sb + ASZ, uBh = sb + 2 * ASZ, uBl = sb + 2 * ASZ + BSZ;
        #pragma unroll
        for (int ks = 0; ks < 2; ++ks) {
            uint32_t ah[MI][4], al[MI][4];
            #pragma unroll
            for (int mi = 0; mi < MI; ++mi) {
                uint32_t off = (uint32_t)((mbase + mi * 16 + lr) * LDS + ks * 16 + lc8) * 2;
                ldm4(ah[mi], uAh + off);
                ldm4(al[mi], uAl + off);
            }
            uint32_t bh[4][2], bl[4][2], r[4];
            uint32_t off0 = (uint32_t)((nbase + lr) * LDS + ks * 16 + lc8) * 2;
            uint32_t off1 = (uint32_t)((nbase + 16 + lr) * LDS + ks * 16 + lc8) * 2;
            ldm4(r, uBh + off0); bh[0][0] = r[0]; bh[0][1] = r[2]; bh[1][0] = r[1]; bh[1][1] = r[3];
            ldm4(r, uBh + off1); bh[2][0] = r[0]; bh[2][1] = r[2]; bh[3][0] = r[1]; bh[3][1] = r[3];
            if (TERMS == 3) {
                ldm4(r, uBl + off0); bl[0][0] = r[0]; bl[0][1] = r[2]; bl[1][0] = r[1]; bl[1][1] = r[3];
                ldm4(r, uBl + off1); bl[2][0] = r[0]; bl[2][1] = r[2]; bl[3][0] = r[1]; bl[3][1] = r[3];
            }
            #pragma unroll
            for (int mi = 0; mi < MI; ++mi)
                #pragma unroll
                for (int ni = 0; ni < 4; ++ni) {
                    mma_f16(acc[mi][ni], ah[mi], bh[ni]);
                    mma_f16(acc[mi][ni], al[mi], bh[ni]);
                    if (TERMS == 3) mma_f16(acc[mi][ni], ah[mi], bl[ni]);
                }
        }
    }

    if (EPI == 0) {
        #pragma unroll
        for (int mi = 0; mi < MI; ++mi) {
            int r0 = m0 + mbase + mi * 16 + (lane >> 2);
            float s0 = 1.f, s1 = 1.f;
            if (rowinv) {
                s0 = rowinv[(size_t)blockIdx.z * M + r0];
                s1 = rowinv[(size_t)blockIdx.z * M + r0 + 8];
            }
            #pragma unroll
            for (int ni = 0; ni < 4; ++ni) {
                int cc = n0 + nbase + ni * 8 + (lane & 3) * 2;
                float d0 = acc[mi][ni][0], d1 = acc[mi][ni][1];
                float d2 = acc[mi][ni][2], d3 = acc[mi][ni][3];
                if (bias) {
                    const float* bz = bias + (size_t)blockIdx.z * bstride;
                    float b0 = bz[cc], b1 = bz[cc + 1];
                    d0 += b0; d1 += b1; d2 += b0; d3 += b1;
                }
                d0 *= s0; d1 *= s0; d2 *= s1; d3 *= s1;
                size_t o0 = (size_t)blockIdx.z * zsC + (size_t)r0 * ldc + cc;
                size_t o1 = (size_t)blockIdx.z * zsC + (size_t)(r0 + 8) * ldc + cc;
                if (Cf) {
                    *reinterpret_cast<float2*>(Cf + o0) = make_float2(d0, d1);
                    *reinterpret_cast<float2*>(Cf + o1) = make_float2(d2, d3);
                }
                if (Coh) {
                    uint32_t lo0, lo1;
                    uint32_t hi0 = pack_hi_lo(d0, d1, lo0);
                    uint32_t hi1 = pack_hi_lo(d2, d3, lo1);
                    *reinterpret_cast<uint32_t*>(Coh + o0) = hi0;
                    *reinterpret_cast<uint32_t*>(Col + o0) = lo0;
                    *reinterpret_cast<uint32_t*>(Coh + o1) = hi1;
                    *reinterpret_cast<uint32_t*>(Col + o1) = lo1;
                }
            }
        }
    } else {
        float rs0[MI], rs1[MI];
        #pragma unroll
        for (int mi = 0; mi < MI; ++mi) { rs0[mi] = 0.f; rs1[mi] = 0.f; }
        #pragma unroll
        for (int mi = 0; mi < MI; ++mi) {
            int r0 = m0 + mbase + mi * 16 + (lane >> 2);
            #pragma unroll
            for (int ni = 0; ni < 4; ++ni) {
                int cc = n0 + nbase + ni * 8 + (lane & 3) * 2;
                float lg0 = logc[cc], lg1 = logc[cc + 1];
                uchar2 dd0 = *reinterpret_cast<const uchar2*>(dm + (size_t)r0 * dmld + cc);
                uchar2 dd1 = *reinterpret_cast<const uchar2*>(dm + (size_t)(r0 + 8) * dmld + cc);
                float e0 = __expf(acc[mi][ni][0] * scale + lg0 + table[dd0.x]);
                float e1 = __expf(acc[mi][ni][1] * scale + lg1 + table[dd0.y]);
                float e2 = __expf(acc[mi][ni][2] * scale + lg0 + table[dd1.x]);
                float e3 = __expf(acc[mi][ni][3] * scale + lg1 + table[dd1.y]);
                size_t o0 = (size_t)blockIdx.z * zsC + (size_t)r0 * ldc + cc;
                size_t o1 = (size_t)blockIdx.z * zsC + (size_t)(r0 + 8) * ldc + cc;
                uint32_t lo0, lo1;
                uint32_t hi0 = pack_hi_lo(e0, e1, lo0);
                uint32_t hi1 = pack_hi_lo(e2, e3, lo1);
                *reinterpret_cast<uint32_t*>(Coh + o0) = hi0;
                *reinterpret_cast<uint32_t*>(Col + o0) = lo0;
                *reinterpret_cast<uint32_t*>(Coh + o1) = hi1;
                *reinterpret_cast<uint32_t*>(Col + o1) = lo1;
                rs0[mi] += e0 + e1;
                rs1[mi] += e2 + e3;
            }
        }
        __syncthreads();
        float* srs = reinterpret_cast<float*>(smem);
        #pragma unroll
        for (int mi = 0; mi < MI; ++mi) {
            float a = rs0[mi];
            a += __shfl_xor_sync(0xFFFFFFFFu, a, 1);
            a += __shfl_xor_sync(0xFFFFFFFFu, a, 2);
            float b = rs1[mi];
            b += __shfl_xor_sync(0xFFFFFFFFu, b, 1);
            b += __shfl_xor_sync(0xFFFFFFFFu, b, 2);
            if ((lane & 3) == 0) {
                int rr = mbase + mi * 16 + (lane >> 2);
                srs[wn * BM + rr]     = a;
                srs[wn * BM + rr + 8] = b;
            }
        }
        __syncthreads();
        if (tid < BM) {
            float part = srs[tid] + srs[BM + tid];
            rsp[((size_t)blockIdx.z * (size_t)M + m0 + tid) * 8 + blockIdx.x] = part;
        }
    }
}

// ---------------- 1/rowsum from 8 deterministic partials ----------------
__global__ void rowsum_reduce_kernel(const float* __restrict__ rsp,
                                     float* __restrict__ rinv, int n) {
    int i = blockIdx.x * blockDim.x + threadIdx.x;
    if (i < n) {
        const float* p = rsp + (size_t)i * 8;
        float s = 0.f;
        #pragma unroll
        for (int j = 0; j < 8; ++j) s += p[j];
        rinv[i] = 1.0f / s;
    }
}

// ---------------- split fp32 -> fp16 pair (elementwise) ----------------
__global__ void split_kernel(const float4* __restrict__ in, uint2* __restrict__ outH,
                             uint2* __restrict__ outL, int n4) {
    int i = blockIdx.x * blockDim.x + threadIdx.x;
    if (i < n4) {
        uint2 H, L; split4(in[i], H, L);
        outH[i] = H; outL[i] = L;
    }
}

// ---------------- dm int32 -> uint8 ----------------
__global__ void dm8_kernel(const int4* __restrict__ in, uchar4* __restrict__ out, int n4) {
    int i = blockIdx.x * blockDim.x + threadIdx.x;
    if (i < n4) {
        int4 v = in[i];
        out[i] = make_uchar4((uint8_t)v.x, (uint8_t)v.y, (uint8_t)v.z, (uint8_t)v.w);
    }
}

// ---------------- batched transpose + split: out[z][C,R] = in[z][R,C]^T ----------------
__global__ void transpose_split_kernel(const float* __restrict__ in, size_t zsIn,
                                       f16* __restrict__ outH, f16* __restrict__ outL,
                                       size_t zsOut, int R, int Ccols) {
    __shared__ float tile[32][33];
    in   += (size_t)blockIdx.z * zsIn;
    outH += (size_t)blockIdx.z * zsOut;
    outL += (size_t)blockIdx.z * zsOut;
    int c0 = blockIdx.x * 32, r0 = blockIdx.y * 32;
    int x = threadIdx.x, y = threadIdx.y;           // 32 x 8
    #pragma unroll
    for (int j = 0; j < 32; j += 8)
        tile[y + j][x] = in[(size_t)(r0 + y + j) * Ccols + c0 + x];
    __syncthreads();
    #pragma unroll
    for (int j = 0; j < 32; j += 8) {
        float v = tile[x][y + j];
        f16 h = __float2half(v);
        f16 l = __float2half(v - __half2float(h));
        size_t o = (size_t)(c0 + y + j) * R + r0 + x;
        outH[o] = h; outL[o] = l;
    }
}

// ---------------- transpose pair input (recombine) + re-split ----------------
__global__ void transpose_resplit_kernel(const f16* __restrict__ inH,
                                         const f16* __restrict__ inL,
                                         f16* __restrict__ outH, f16* __restrict__ outL,
                                         int R, int Ccols) {
    __shared__ float tile[32][33];
    int c0 = blockIdx.x * 32, r0 = blockIdx.y * 32;
    int x = threadIdx.x, y = threadIdx.y;
    #pragma unroll
    for (int j = 0; j < 32; j += 8) {
        size_t o = (size_t)(r0 + y + j) * Ccols + c0 + x;
        tile[y + j][x] = __half2float(inH[o]) + __half2float(inL[o]);
    }
    __syncthreads();
    #pragma unroll
    for (int j = 0; j < 32; j += 8) {
        float v = tile[x][y + j];
        f16 h = __float2half(v);
        f16 l = __float2half(v - __half2float(h));
        size_t o = (size_t)(c0 + y + j) * R + r0 + x;
        outH[o] = h; outL[o] = l;
    }
}

// ---------------- fused q bias ----------------
__global__ void fuse_bias_kernel(const float* __restrict__ bproj,
                                 const float* __restrict__ Wq,
                                 const float* __restrict__ bq,
                                 float* __restrict__ out) {
    int o = blockIdx.x * blockDim.x + threadIdx.x;
    float s = bq[o];
    for (int k = 0; k < HID; k++) s += bproj[k] * Wq[(size_t)k * HID + o];
    out[o] = s;
}

// ---------------- copy bk/bv into adjacent scratch [l][2][HID] ----------------
__global__ void copy_bkv_kernel(const float* __restrict__ bk, const float* __restrict__ bv,
                                float* __restrict__ out) {
    int i = blockIdx.x * blockDim.x + threadIdx.x;      // NLAYER*HID
    int l = i / HID, c = i % HID;
    out[(l * 2) * HID + c]     = bk[i];
    out[(l * 2 + 1) * HID + c] = bv[i];
}

// ---------------- community preprocessing (deterministic, stable) ----------------
__global__ void hist_kernel(const int* __restrict__ ntc) {
    __shared__ int sh[C_COMM];
    int chunk = blockIdx.x;
    for (int i = threadIdx.x; i < C_COMM; i += blockDim.x) sh[i] = 0;
    __syncthreads();
    atomicAdd(&sh[ntc[chunk * CHUNK + threadIdx.x]], 1);
    __syncthreads();
    for (int i = threadIdx.x; i < C_COMM; i += blockDim.x)
        g_hist[chunk * C_COMM + i] = sh[i];
}

__global__ void chunk_scan_kernel() {
    int c = blockIdx.x;
    __shared__ int s[NCHUNK];
    int t = threadIdx.x;
    int own = g_hist[t * C_COMM + c];
    s[t] = own;
    __syncthreads();
    for (int off = 1; off < NCHUNK; off <<= 1) {
        int v = (t >= off) ? s[t - off] : 0;
        __syncthreads();
        s[t] += v;
        __syncthreads();
    }
    g_chunkbase[t * C_COMM + c] = s[t] - own;
    if (t == NCHUNK - 1) g_counts[c] = s[t];
}

__global__ void offsets_kernel() {
    __shared__ int s[C_COMM];
    int t = threadIdx.x;
    int own = g_counts[t];
    s[t] = own;
    __syncthreads();
    for (int off = 1; off < C_COMM; off <<= 1) {
        int v = (t >= off) ? s[t - off] : 0;
        __syncthreads();
        s[t] += v;
        __syncthreads();
    }
    g_offsets[t] = s[t] - own;
    g_logc[t]    = logf((float)own);
    g_inv[t]     = 1.0f / (float)(own > 0 ? own : 1);
}

__global__ void scatter_kernel(const int* __restrict__ ntc) {
    __shared__ int s[CHUNK];
    int chunk = blockIdx.x;
    int t = threadIdx.x;
    int node = chunk * CHUNK + t;
    int c = ntc[node];
    s[t] = c;
    __syncthreads();
    int lrank = 0;
    for (int j = 0; j < t; j++) lrank += (s[j] == c);
    g_members[g_offsets[c] + g_chunkbase[chunk * C_COMM + c] + lrank] = node;
}

__global__ void comm_avg_kernel() {
    int c = blockIdx.x;
    int t = threadIdx.x;
    int off = g_offsets[c], cnt = g_counts[c];
    float a0 = 0.f, a1 = 0.f;
    for (int m = 0; m < cnt; m++) {
        const float* row = g_h + (size_t)g_members[off + m] * HID;
        a0 += row[t];
        a1 += row[t + 256];
    }
    float inv = g_inv[c];
    a0 *= inv; a1 *= inv;
    f16 h0 = __float2half(a0), h1 = __float2half(a1);
    g_cmh[c * HID + t]       = h0;
    g_cmh[c * HID + t + 256] = h1;
    g_cml[c * HID + t]       = __float2half(a0 - __half2float(h0));
    g_cml[c * HID + t + 256] = __float2half(a1 - __half2float(h1));
}

__global__ void bias_table_kernel(const float* __restrict__ emb,
                                  const float* __restrict__ w,
                                  const float* __restrict__ bptr) {
    int i = blockIdx.x;
    int t = threadIdx.x;
    float s = emb[i * HID + t]       * w[t]
            + emb[i * HID + t + 128] * w[t + 128]
            + emb[i * HID + t + 256] * w[t + 256]
            + emb[i * HID + t + 384] * w[t + 384];
    for (int o = 16; o; o >>= 1) s += __shfl_xor_sync(0xFFFFFFFFu, s, o);
    __shared__ float r[4];
    if ((t & 31) == 0) r[t >> 5] = s;
    __syncthreads();
    if (t == 0) g_table[i] = r[0] + r[1] + r[2] + r[3] + bptr[0];
}

// warp-per-row LayerNorm + ReLU; fp32 (optional) + fp16 pair outputs
__global__ void ln_relu_kernel(const float* __restrict__ in, float* __restrict__ outF,
                               f16* __restrict__ outH, f16* __restrict__ outL,
                               const float* __restrict__ g, const float* __restrict__ b) {
    int w = threadIdx.x >> 5, lane = threadIdx.x & 31;
    size_t row = (size_t)blockIdx.x * 8 + w;
    const float* x = in + row * HID;
    float4 v[4];
    float s = 0.f, q = 0.f;
    #pragma unroll
    for (int k = 0; k < 4; k++) {
        v[k] = *reinterpret_cast<const float4*>(x + k * 128 + lane * 4);
        s += v[k].x + v[k].y + v[k].z + v[k].w;
        q += v[k].x * v[k].x + v[k].y * v[k].y + v[k].z * v[k].z + v[k].w * v[k].w;
    }
    #pragma unroll
    for (int o = 16; o; o >>= 1) {
        s += __shfl_xor_sync(0xFFFFFFFFu, s, o);
        q += __shfl_xor_sync(0xFFFFFFFFu, q, o);
    }
    float mean = s * (1.0f / HID);
    float var  = q * (1.0f / HID) - mean * mean;
    float rstd = rsqrtf(var + EPS);
    #pragma unroll
    for (int k = 0; k < 4; k++) {
        int c = k * 128 + lane * 4;
        float4 gg = *reinterpret_cast<const float4*>(g + c);
        float4 bb = *reinterpret_cast<const float4*>(b + c);
        float4 y;
        y.x = fmaxf((v[k].x - mean) * rstd * gg.x + bb.x, 0.f);
        y.y = fmaxf((v[k].y - mean) * rstd * gg.y + bb.y, 0.f);
        y.z = fmaxf((v[k].z - mean) * rstd * gg.z + bb.z, 0.f);
        y.w = fmaxf((v[k].w - mean) * rstd * gg.w + bb.w, 0.f);
        if (outF) *reinterpret_cast<float4*>(outF + row * HID + c) = y;
        uint2 H, L; split4(y, H, L);
        *reinterpret_cast<uint2*>(outH + row * HID + c) = H;
        *reinterpret_cast<uint2*>(outL + row * HID + c) = L;
    }
}

// ---------------- host-side helpers ----------------
static const int SMEM_G = 3 * (2 * 128 * 80 + 2 * 64 * 80);  // 92160 per CTA

static void tc_nn(int M, int Nc, int K,
                  const f16* Ah, const f16* Al, int lda,
                  const f16* Bth, const f16* Btl,
                  const float* bias,
                  float* Cf, f16* Coh, f16* Col, int ldc)
{
    dim3 g(Nc / 64, M / 128, 1);
    mma_gemm<64, 0, 2><<<g, 256, SMEM_G>>>(M, K, Ah, Al, lda, 0, Bth, Btl, K, 0,
                                           bias, 0, Cf, Coh, Col, ldc, 0,
                                           0.f, nullptr, nullptr, nullptr, 0,
                                           nullptr, nullptr);
}

extern "C" void kernel_launch(void* const* d_in, const int* in_sizes, int n_in,
                              void* d_out, int out_size)
{
    // ---- input mapping (auto-detect metadata order) ----
    const float *x      = (const float*)d_in[0];
    const int   *dm     = (const int*)  d_in[1];
    const int   *ntc    = (const int*)  d_in[2];
    const float *W_in1  = (const float*)d_in[3];
    const float *b_in1  = (const float*)d_in[4];
    const float *ln_in_g= (const float*)d_in[5];
    const float *ln_in_b= (const float*)d_in[6];
    const float *W_in2  = (const float*)d_in[7];
    const float *b_in2  = (const float*)d_in[8];
    const float *Wproj, *Wq, *Wk, *Wv, *ffW1, *ffW2;
    const float *bproj, *bq, *bk, *bv, *ffb1, *ffb2;
    const float *dis_emb, *dis_w, *dis_b;
    const float *ffg1, *ffbeta1, *ffg2, *ffbeta2, *Wout, *bout;

    if (in_sizes[10] == NLAYER * HID * HID) {
        Wproj  = (const float*)d_in[9];  Wq     = (const float*)d_in[10];
        Wk     = (const float*)d_in[11]; Wv     = (const float*)d_in[12];
        ffW1   = (const float*)d_in[13]; ffW2   = (const float*)d_in[14];
        bproj  = (const float*)d_in[15]; bq     = (const float*)d_in[16];
        bk     = (const float*)d_in[17]; bv     = (const float*)d_in[18];
        ffb1   = (const float*)d_in[19]; ffb2   = (const float*)d_in[20];
        dis_emb= (const float*)d_in[21]; dis_w  = (const float*)d_in[22];
        dis_b  = (const float*)d_in[23];
        ffg1   = (const float*)d_in[24]; ffbeta1= (const float*)d_in[25];
        ffg2   = (const float*)d_in[26]; ffbeta2= (const float*)d_in[27];
        Wout   = (const float*)d_in[28]; bout   = (const float*)d_in[29];
    } else {
        Wproj  = (const float*)d_in[9];  bproj  = (const float*)d_in[10];
        Wq     = (const float*)d_in[11]; bq     = (const float*)d_in[12];
        Wk     = (const float*)d_in[13]; bk     = (const float*)d_in[14];
        Wv     = (const float*)d_in[15]; bv     = (const float*)d_in[16];
        dis_emb= (const float*)d_in[17]; dis_w  = (const float*)d_in[18];
        dis_b  = (const float*)d_in[19];
        ffW1   = (const float*)d_in[20]; ffb1   = (const float*)d_in[21];
        ffg1   = (const float*)d_in[22]; ffbeta1= (const float*)d_in[23];
        ffW2   = (const float*)d_in[24]; ffb2   = (const float*)d_in[25];
        ffg2   = (const float*)d_in[26]; ffbeta2= (const float*)d_in[27];
        Wout   = (const float*)d_in[28]; bout   = (const float*)d_in[29];
    }

    cudaFuncSetAttribute(mma_gemm<64, 0, 2>, cudaFuncAttributeMaxDynamicSharedMemorySize, SMEM_G);
    cudaFuncSetAttribute(mma_gemm<64, 1, 2>, cudaFuncAttributeMaxDynamicSharedMemorySize, SMEM_G);
    cudaFuncSetAttribute(mma_gemm<64, 0, 3>, cudaFuncAttributeMaxDynamicSharedMemorySize, SMEM_G);

    // ---- scratch pointers ----
    float *p_h, *p_t0, *p_t1, *p_logc, *p_table, *p_bfq, *p_bkv, *p_rsp, *p_rinv;
    f16 *p_xh, *p_xl, *p_hh, *p_hl, *p_t0h, *p_t0l, *p_t1h, *p_t1l, *p_qh, *p_ql;
    f16 *p_ph, *p_pl, *p_cmh, *p_cml, *p_kvh, *p_kvl, *p_vth, *p_vtl, *p_wh, *p_wl;
    uint8_t *p_dm8;
    cudaGetSymbolAddress((void**)&p_h,    g_h);
    cudaGetSymbolAddress((void**)&p_t0,   g_t0);
    cudaGetSymbolAddress((void**)&p_t1,   g_t1);
    cudaGetSymbolAddress((void**)&p_logc, g_logc);
    cudaGetSymbolAddress((void**)&p_table,g_table);
    cudaGetSymbolAddress((void**)&p_bfq,  g_bfq);
    cudaGetSymbolAddress((void**)&p_bkv,  g_bkv);
    cudaGetSymbolAddress((void**)&p_rsp,  g_rsp);
    cudaGetSymbolAddress((void**)&p_rinv, g_rinv);
    cudaGetSymbolAddress((void**)&p_dm8,  g_dm8);
    cudaGetSymbolAddress((void**)&p_xh,  g_xh);  cudaGetSymbolAddress((void**)&p_xl,  g_xl);
    cudaGetSymbolAddress((void**)&p_hh,  g_hh);  cudaGetSymbolAddress((void**)&p_hl,  g_hl);
    cudaGetSymbolAddress((void**)&p_t0h, g_t0h); cudaGetSymbolAddress((void**)&p_t0l, g_t0l);
    cudaGetSymbolAddress((void**)&p_t1h, g_t1h); cudaGetSymbolAddress((void**)&p_t1l, g_t1l);
    cudaGetSymbolAddress((void**)&p_qh,  g_qh);  cudaGetSymbolAddress((void**)&p_ql,  g_ql);
    cudaGetSymbolAddress((void**)&p_ph,  g_ph);  cudaGetSymbolAddress((void**)&p_pl,  g_pl);
    cudaGetSymbolAddress((void**)&p_cmh, g_cmh); cudaGetSymbolAddress((void**)&p_cml, g_cml);
    cudaGetSymbolAddress((void**)&p_kvh, g_kvh); cudaGetSymbolAddress((void**)&p_kvl, g_kvl);
    cudaGetSymbolAddress((void**)&p_vth, g_vth); cudaGetSymbolAddress((void**)&p_vtl, g_vtl);
    cudaGetSymbolAddress((void**)&p_wh,  g_wh);  cudaGetSymbolAddress((void**)&p_wl,  g_wl);
    #define WH(i) (p_wh + (size_t)(i) * HID * HID)
    #define WL(i) (p_wl + (size_t)(i) * HID * HID)

    const float scale = 1.0f / sqrtf((float)DHEAD);
    const size_t W2 = (size_t)HID * HID;

    // ---- weight preprocessing (batched) ----
    // slots: 0=W_in1T 1=W_in2T; layer l: s0=2+l*5 {0:WfqT,1:WkT,2:WvT,3:ffW1T,4:ffW2T};
    // 12=WoutT; 13,14=WqT l0,l1; 15,16=Wproj split l0,l1
    {
        dim3 b(32, 8);
        transpose_split_kernel<<<dim3(HID / 32, IN_DIM / 32, 1), b>>>(
            W_in1, 0, WH(0), WL(0), 0, IN_DIM, HID);
        transpose_split_kernel<<<dim3(HID / 32, HID / 32, 1), b>>>(
            W_in2, 0, WH(1), WL(1), 0, HID, HID);
        transpose_split_kernel<<<dim3(OUT_DIM / 32, HID / 32, 1), b>>>(
            Wout, 0, WH(12), WL(12), 0, HID, OUT_DIM);
        transpose_split_kernel<<<dim3(HID / 32, HID / 32, NLAYER), b>>>(
            Wq, W2, WH(13), WL(13), W2, HID, HID);
        transpose_split_kernel<<<dim3(HID / 32, HID / 32, NLAYER), b>>>(
            Wk, W2, WH(3), WL(3), 5 * W2, HID, HID);
        transpose_split_kernel<<<dim3(HID / 32, HID / 32, NLAYER), b>>>(
            Wv, W2, WH(4), WL(4), 5 * W2, HID, HID);
        transpose_split_kernel<<<dim3(HID / 32, HID / 32, NLAYER), b>>>(
            ffW1, W2, WH(5), WL(5), 5 * W2, HID, HID);
        transpose_split_kernel<<<dim3(HID / 32, HID / 32, NLAYER), b>>>(
            ffW2, W2, WH(6), WL(6), 5 * W2, HID, HID);
    }
    split_kernel<<<N_NODES * IN_DIM / 1024, 256>>>((const float4*)x, (uint2*)p_xh, (uint2*)p_xl,
                                                   N_NODES * IN_DIM / 4);
    split_kernel<<<NLAYER * HID * HID / 1024, 256>>>((const float4*)Wproj,
                                                     (uint2*)WH(15), (uint2*)WL(15),
                                                     NLAYER * HID * HID / 4);
    // fused q weight (both layers, 3-term for precision): WfqT = WqT . Wproj^T-form
    {
        dim3 g(HID / 64, HID / 128, NLAYER);
        mma_gemm<64, 0, 3><<<g, 256, SMEM_G>>>(HID, HID,
                                               WH(13), WL(13), HID, W2,
                                               WH(15), WL(15), HID, W2,
                                               nullptr, 0, nullptr, WH(2), WL(2), HID, 5 * W2,
                                               0.f, nullptr, nullptr, nullptr, 0,
                                               nullptr, nullptr);
    }
    for (int l = 0; l < NLAYER; l++)
        fuse_bias_kernel<<<HID / 256, 256>>>(bproj + (size_t)l * HID,
                                             Wq + (size_t)l * W2,
                                             bq + (size_t)l * HID, p_bfq + (size_t)l * HID);
    copy_bkv_kernel<<<NLAYER * HID / 256, 256>>>(bk, bv, p_bkv);
    dm8_kernel<<<(int)((size_t)N_NODES * C_COMM / 1024), 256>>>(
        (const int4*)dm, (uchar4*)p_dm8, (int)((size_t)N_NODES * C_COMM / 4));

    // ---- community preprocessing (deterministic) ----
    hist_kernel      <<<NCHUNK, CHUNK>>>(ntc);
    chunk_scan_kernel<<<C_COMM, NCHUNK>>>();
    offsets_kernel   <<<1, C_COMM>>>();
    scatter_kernel   <<<NCHUNK, CHUNK>>>(ntc);

    // ---- fc_in ----
    tc_nn(N_NODES, HID, IN_DIM, p_xh, p_xl, IN_DIM, WH(0), WL(0), b_in1,
          p_t0, nullptr, nullptr, HID);
    ln_relu_kernel<<<N_NODES / 8, 256>>>(p_t0, nullptr, p_t0h, p_t0l, ln_in_g, ln_in_b);
    tc_nn(N_NODES, HID, HID, p_t0h, p_t0l, HID, WH(1), WL(1), b_in2,
          p_h, p_hh, p_hl, HID);

    // ---- layers ----
    for (int l = 0; l < NLAYER; l++) {
        int s0 = 2 + l * 5;
        bias_table_kernel<<<NDIST, 128>>>(dis_emb + (size_t)l * NDIST * HID,
                                          dis_w + (size_t)l * HID, dis_b + l);
        comm_avg_kernel<<<C_COMM, 256>>>();

        // q = h @ WfqT^T + bfq
        tc_nn(N_NODES, HID, HID, p_hh, p_hl, HID, WH(s0), WL(s0),
              p_bfq + (size_t)l * HID, nullptr, p_qh, p_ql, HID);
        // k and v in one launch (z: 0=k, 1=v), pair outputs adjacent
        {
            dim3 g(HID / 64, C_COMM / 128, 2);
            mma_gemm<64, 0, 2><<<g, 256, SMEM_G>>>(
                C_COMM, HID,
                p_cmh, p_cml, HID, 0,
                WH(s0 + 1), WL(s0 + 1), HID, W2,
                p_bkv + (size_t)l * 2 * HID, HID,
                nullptr, p_kvh, p_kvl, HID, (size_t)C_COMM * HID,
                0.f, nullptr, nullptr, nullptr, 0,
                nullptr, nullptr);
        }
        transpose_resplit_kernel<<<dim3(HID / 32, C_COMM / 32), dim3(32, 8)>>>(
            p_kvh + (size_t)C_COMM * HID, p_kvl + (size_t)C_COMM * HID,
            p_vth, p_vtl, C_COMM, HID);

        // dots per head: fused exp epilogue -> unnormalized e pairs + row partial sums
        {
            dim3 g(C_COMM / 64, N_NODES / 128, NHEAD);
            mma_gemm<64, 1, 2><<<g, 256, SMEM_G>>>(
                N_NODES, DHEAD,
                p_qh, p_ql, HID, (size_t)DHEAD,
                p_kvh, p_kvl, HID, (size_t)DHEAD,
                nullptr, 0,
                nullptr, p_ph, p_pl, C_COMM, (size_t)N_NODES * C_COMM,
                scale, p_logc, p_table, p_dm8, C_COMM,
                p_rsp, nullptr);
        }
        rowsum_reduce_kernel<<<NHEAD * N_NODES / 256, 256>>>(p_rsp, p_rinv, NHEAD * N_NODES);

        // AV per head: multiply by 1/rowsum in epilogue -> t0 split
        {
            dim3 g(DHEAD / 64, N_NODES / 128, NHEAD);
            mma_gemm<64, 0, 2><<<g, 256, SMEM_G>>>(
                N_NODES, C_COMM,
                p_ph, p_pl, C_COMM, (size_t)N_NODES * C_COMM,
                p_vth, p_vtl, C_COMM, (size_t)DHEAD * C_COMM,
                nullptr, 0,
                nullptr, p_t0h, p_t0l, HID, (size_t)DHEAD,
                0.f, nullptr, nullptr, nullptr, 0,
                nullptr, p_rinv);
        }

        tc_nn(N_NODES, HID, HID, p_t0h, p_t0l, HID, WH(s0 + 3), WL(s0 + 3),
              ffb1 + (size_t)l * HID, p_t1, nullptr, nullptr, HID);
        ln_relu_kernel<<<N_NODES / 8, 256>>>(p_t1, nullptr, p_t1h, p_t1l,
                                             ffg1 + (size_t)l * HID, ffbeta1 + (size_t)l * HID);
        tc_nn(N_NODES, HID, HID, p_t1h, p_t1l, HID, WH(s0 + 4), WL(s0 + 4),
              ffb2 + (size_t)l * HID, p_t0, nullptr, nullptr, HID);
        ln_relu_kernel<<<N_NODES / 8, 256>>>(p_t0, p_h, p_hh, p_hl,
                                             ffg2 + (size_t)l * HID, ffbeta2 + (size_t)l * HID);
    }

    // ---- output projection ----
    tc_nn(N_NODES, OUT_DIM, HID, p_hh, p_hl, HID, WH(12), WL(12), bout,
          (float*)d_out, nullptr, nullptr, OUT_DIM);
}

// round 15
// speedup vs baseline: 3.7933x; 1.1581x over previous
#include <cuda_runtime.h>
#include <cuda_fp16.h>
#include <math.h>
#include <stdint.h>

// ---------------- problem constants ----------------
#define N_NODES 32768
#define C_COMM  512
#define IN_DIM  128
#define HID     512
#define NHEAD   4
#define DHEAD   128
#define NLAYER  2
#define OUT_DIM 64
#define NDIST   31
#define EPS     1e-5f

#define CHUNK   256
#define NCHUNK  (N_NODES / CHUNK)   // 128

typedef __half f16;

// ---------------- scratch (device globals; no allocation allowed) ----------------
__device__ float g_h   [N_NODES * HID];
__device__ float g_t0  [N_NODES * HID];
__device__ float g_t1  [N_NODES * HID];
__device__ float g_bfq [NLAYER * HID];
__device__ float g_bkv [NLAYER * 2 * HID];
__device__ float g_rsp [(size_t)NHEAD * N_NODES * 8];
__device__ float g_rinv[(size_t)NHEAD * N_NODES];

__device__ f16 g_xh [N_NODES * IN_DIM], g_xl [N_NODES * IN_DIM];
__device__ f16 g_hh [N_NODES * HID],    g_hl [N_NODES * HID];
__device__ f16 g_t0h[N_NODES * HID],    g_t0l[N_NODES * HID];
__device__ f16 g_t1h[N_NODES * HID],    g_t1l[N_NODES * HID];
__device__ f16 g_qh [N_NODES * HID],    g_ql [N_NODES * HID];
__device__ f16 g_ph [(size_t)NHEAD * N_NODES * C_COMM];
__device__ f16 g_pl [(size_t)NHEAD * N_NODES * C_COMM];
__device__ f16 g_cmh[C_COMM * HID],     g_cml[C_COMM * HID];
__device__ f16 g_kvh[2 * C_COMM * HID], g_kvl[2 * C_COMM * HID];   // [k; v]
__device__ f16 g_vth[HID * C_COMM],     g_vtl[HID * C_COMM];
__device__ f16 g_wh [17][HID * HID],    g_wl [17][HID * HID];
__device__ uint8_t g_dm8[(size_t)N_NODES * C_COMM];

__device__ int   g_hist     [NCHUNK * C_COMM];
__device__ int   g_chunkbase[NCHUNK * C_COMM];
__device__ int   g_counts [C_COMM];
__device__ int   g_offsets[C_COMM];
__device__ int   g_members[N_NODES];
__device__ float g_logc[C_COMM];
__device__ float g_inv [C_COMM];
__device__ float g_table[NDIST];

// ---------------- small PTX helpers (all sm_80-compatible) ----------------
__device__ __forceinline__ uint32_t smem_u32(const void* p) {
    uint32_t a;
    asm("{ .reg .u64 t; cvta.to.shared.u64 t, %1; cvt.u32.u64 %0, t; }" : "=r"(a) : "l"(p));
    return a;
}

__device__ __forceinline__ void cpa16(uint32_t dst, const void* src) {
    asm volatile("{ .reg .u64 g; cvta.to.global.u64 g, %1; cp.async.cg.shared.global [%0], [g], 16; }"
                 :: "r"(dst), "l"(src));
}
#define CP_COMMIT() asm volatile("cp.async.commit_group;" ::: "memory")
#define CP_WAIT1()  asm volatile("cp.async.wait_group 1;" ::: "memory")

__device__ __forceinline__ void ldm4(uint32_t* r, uint32_t addr) {
    asm volatile("ldmatrix.sync.aligned.m8n8.x4.shared.b16 {%0,%1,%2,%3}, [%4];"
                 : "=r"(r[0]), "=r"(r[1]), "=r"(r[2]), "=r"(r[3]) : "r"(addr));
}

__device__ __forceinline__ void mma_f16(float* d, const uint32_t* a, const uint32_t* b) {
    asm volatile(
        "mma.sync.aligned.m16n8k16.row.col.f32.f16.f16.f32 "
        "{%0,%1,%2,%3}, {%4,%5,%6,%7}, {%8,%9}, {%0,%1,%2,%3};"
        : "+f"(d[0]), "+f"(d[1]), "+f"(d[2]), "+f"(d[3])
        : "r"(a[0]), "r"(a[1]), "r"(a[2]), "r"(a[3]), "r"(b[0]), "r"(b[1]));
}

// split fp32x4 -> fp16 hi quad + fp16 lo quad
__device__ __forceinline__ void split4(float4 v, uint2& H, uint2& L) {
    f16 hx = __float2half(v.x), hy = __float2half(v.y);
    f16 hz = __float2half(v.z), hw = __float2half(v.w);
    H.x = (uint32_t)__half_as_ushort(hx) | ((uint32_t)__half_as_ushort(hy) << 16);
    H.y = (uint32_t)__half_as_ushort(hz) | ((uint32_t)__half_as_ushort(hw) << 16);
    f16 lx = __float2half(v.x - __half2float(hx));
    f16 ly = __float2half(v.y - __half2float(hy));
    f16 lz = __float2half(v.z - __half2float(hz));
    f16 lw = __float2half(v.w - __half2float(hw));
    L.x = (uint32_t)__half_as_ushort(lx) | ((uint32_t)__half_as_ushort(ly) << 16);
    L.y = (uint32_t)__half_as_ushort(lz) | ((uint32_t)__half_as_ushort(lw) << 16);
}

__device__ __forceinline__ uint32_t pack_hi_lo(float a, float b, uint32_t& outlo) {
    f16 ha = __float2half(a), hb = __float2half(b);
    f16 la = __float2half(a - __half2float(ha));
    f16 lb = __float2half(b - __half2float(hb));
    outlo = (uint32_t)__half_as_ushort(la) | ((uint32_t)__half_as_ushort(lb) << 16);
    return (uint32_t)__half_as_ushort(ha) | ((uint32_t)__half_as_ushort(hb) << 16);
}

// ---------------- warp-MMA GEMM on pre-split fp16 pairs ----------------
// TERMS==3: C = (Ah+Al)(Bh+Bl)^T.  TERMS==2: C = (Ah+Al)Bh^T (no Bl smem slot).
// BM=128 x BN tile, 8 warps (4m x 2n), 3-stage cp.async pipeline, 2 CTAs/SM.
// EPI==0: +bias[z*bstride + col], optional rowinv scaling, fp32 and/or pair out.
// EPI==1: dots epilogue -> e = exp(d*scale + logc + table[dm8]); e pairs
//         + deterministic per-row partial sums to rsp[row*8 + blockIdx.x].
template<int BN, int EPI, int TERMS>
__global__ __launch_bounds__(256, 2)
void mma_gemm(int M, int K,
              const f16* __restrict__ Ah, const f16* __restrict__ Al, int lda, size_t zsA,
              const f16* __restrict__ Bh, const f16* __restrict__ Bl, int ldb, size_t zsB,
              const float* __restrict__ bias, int bstride,
              float* __restrict__ Cf, f16* __restrict__ Coh, f16* __restrict__ Col,
              int ldc, size_t zsC,
              float scale, const float* __restrict__ logc,
              const float* __restrict__ table,
              const uint8_t* __restrict__ dm, int dmld,
              float* __restrict__ rsp, const float* __restrict__ rowinv)
{
    constexpr int BM  = 128;
    constexpr int LDS = 40;                  // f16 elems per smem row (80B stride)
    constexpr int NW_N = 2;                  // warps along n
    constexpr int NW_M = 4;                  // warps along m
    constexpr int WM  = BM / NW_M;           // 32
    constexpr int MI  = WM / 16;             // 2
    constexpr int WN  = BN / NW_N;           // 32 or 64
    constexpr int NI  = WN / 8;              // 4 or 8 (n8 tiles per warp)
    constexpr int NG  = NI / 2;              // ldsm.x4 groups for B
    constexpr int NBT = BN * 4 / 256;        // B cp.async tasks per thread
    constexpr int ASZ = BM * LDS * 2;        // 10240 B per A matrix
    constexpr int BSZ = BN * LDS * 2;
    constexpr int STAGE = 2 * ASZ + (TERMS == 3 ? 2 : 1) * BSZ;

    extern __shared__ char smem[];
    const uint32_t uS = smem_u32(smem);

    Ah += (size_t)blockIdx.z * zsA;  Al += (size_t)blockIdx.z * zsA;
    Bh += (size_t)blockIdx.z * zsB;
    if (TERMS == 3) Bl += (size_t)blockIdx.z * zsB;
    const int m0 = blockIdx.y * BM, n0 = blockIdx.x * BN;
    const int tid = threadIdx.x, lane = tid & 31, wid = tid >> 5;
    const int wm = wid % NW_M, wn = wid / NW_M;
    const int mbase = wm * WM, nbase = wn * WN;
    const int lr = lane & 15, lc8 = (lane >> 4) * 8;

    const int nch = K >> 5;

    auto issue = [&](int s, int kc) {
        const uint32_t sb = uS + (uint32_t)(s * STAGE);
        const int k0 = kc << 5;
        #pragma unroll
        for (int t = 0; t < 2; ++t) {
            int j = tid + t * 256, row = j >> 2, ck = j & 3;
            uint32_t off = (uint32_t)(row * 80 + ck * 16);
            size_t so = (size_t)(m0 + row) * lda + k0 + ck * 8;
            cpa16(sb + off,       Ah + so);
            cpa16(sb + ASZ + off, Al + so);
        }
        #pragma unroll
        for (int t = 0; t < NBT; ++t) {
            int j = tid + t * 256, row = j >> 2, ck = j & 3;
            uint32_t off = (uint32_t)(row * 80 + ck * 16);
            size_t so = (size_t)(n0 + row) * ldb + k0 + ck * 8;
            cpa16(sb + 2 * ASZ + off, Bh + so);
            if (TERMS == 3) cpa16(sb + 2 * ASZ + BSZ + off, Bl + so);
        }
    };

    float acc[MI][NI][4];
    #pragma unroll
    for (int mi = 0; mi < MI; ++mi)
        #pragma unroll
        for (int ni = 0; ni < NI; ++ni)
            #pragma unroll
            for (int q = 0; q < 4; ++q) acc[mi][ni][q] = 0.f;

    issue(0, 0); CP_COMMIT();
    if (nch > 1) issue(1, 1);
    CP_COMMIT();

    for (int ch = 0; ch < nch; ++ch) {
        CP_WAIT1();
        __syncthreads();   // publishes chunk ch AND closes stage (ch+2)%3's readers

        int nx = ch + 2;
        if (nx < nch) issue(nx % 3, nx);
        CP_COMMIT();

        const uint32_t sb = uS + (uint32_t)((ch % 3) * STAGE);
        const uint32_t uAh = sb, uAl = sb + ASZ, uBh = sb + 2 * ASZ, uBl = sb + 2 * ASZ + BSZ;
        #pragma unroll
        for (int ks = 0; ks < 2; ++ks) {
            uint32_t ah[MI][4], al[MI][4];
            #pragma unroll
            for (int mi = 0; mi < MI; ++mi) {
                uint32_t off = (uint32_t)((mbase + mi * 16 + lr) * LDS + ks * 16 + lc8) * 2;
                ldm4(ah[mi], uAh + off);
                ldm4(al[mi], uAl + off);
            }
            uint32_t bh[NI][2], bl[NI][2], r[4];
            #pragma unroll
            for (int g = 0; g < NG; ++g) {
                uint32_t offg = (uint32_t)((nbase + g * 16 + lr) * LDS + ks * 16 + lc8) * 2;
                ldm4(r, uBh + offg);
                bh[2 * g][0] = r[0]; bh[2 * g][1] = r[2];
                bh[2 * g + 1][0] = r[1]; bh[2 * g + 1][1] = r[3];
                if (TERMS == 3) {
                    ldm4(r, uBl + offg);
                    bl[2 * g][0] = r[0]; bl[2 * g][1] = r[2];
                    bl[2 * g + 1][0] = r[1]; bl[2 * g + 1][1] = r[3];
                }
            }
            #pragma unroll
            for (int mi = 0; mi < MI; ++mi)
                #pragma unroll
                for (int ni = 0; ni < NI; ++ni) {
                    mma_f16(acc[mi][ni], ah[mi], bh[ni]);
                    mma_f16(acc[mi][ni], al[mi], bh[ni]);
                    if (TERMS == 3) mma_f16(acc[mi][ni], ah[mi], bl[ni]);
                }
        }
    }

    if (EPI == 0) {
        #pragma unroll
        for (int mi = 0; mi < MI; ++mi) {
            int r0 = m0 + mbase + mi * 16 + (lane >> 2);
            float s0 = 1.f, s1 = 1.f;
            if (rowinv) {
                s0 = rowinv[(size_t)blockIdx.z * M + r0];
                s1 = rowinv[(size_t)blockIdx.z * M + r0 + 8];
            }
            #pragma unroll
            for (int ni = 0; ni < NI; ++ni) {
                int cc = n0 + nbase + ni * 8 + (lane & 3) * 2;
                float d0 = acc[mi][ni][0], d1 = acc[mi][ni][1];
                float d2 = acc[mi][ni][2], d3 = acc[mi][ni][3];
                if (bias) {
                    const float* bz = bias + (size_t)blockIdx.z * bstride;
                    float b0 = bz[cc], b1 = bz[cc + 1];
                    d0 += b0; d1 += b1; d2 += b0; d3 += b1;
                }
                d0 *= s0; d1 *= s0; d2 *= s1; d3 *= s1;
                size_t o0 = (size_t)blockIdx.z * zsC + (size_t)r0 * ldc + cc;
                size_t o1 = (size_t)blockIdx.z * zsC + (size_t)(r0 + 8) * ldc + cc;
                if (Cf) {
                    *reinterpret_cast<float2*>(Cf + o0) = make_float2(d0, d1);
                    *reinterpret_cast<float2*>(Cf + o1) = make_float2(d2, d3);
                }
                if (Coh) {
                    uint32_t lo0, lo1;
                    uint32_t hi0 = pack_hi_lo(d0, d1, lo0);
                    uint32_t hi1 = pack_hi_lo(d2, d3, lo1);
                    *reinterpret_cast<uint32_t*>(Coh + o0) = hi0;
                    *reinterpret_cast<uint32_t*>(Col + o0) = lo0;
                    *reinterpret_cast<uint32_t*>(Coh + o1) = hi1;
                    *reinterpret_cast<uint32_t*>(Col + o1) = lo1;
                }
            }
        }
    } else {
        float rs0[MI], rs1[MI];
        #pragma unroll
        for (int mi = 0; mi < MI; ++mi) { rs0[mi] = 0.f; rs1[mi] = 0.f; }
        #pragma unroll
        for (int mi = 0; mi < MI; ++mi) {
            int r0 = m0 + mbase + mi * 16 + (lane >> 2);
            #pragma unroll
            for (int ni = 0; ni < NI; ++ni) {
                int cc = n0 + nbase + ni * 8 + (lane & 3) * 2;
                float lg0 = logc[cc], lg1 = logc[cc + 1];
                uchar2 dd0 = *reinterpret_cast<const uchar2*>(dm + (size_t)r0 * dmld + cc);
                uchar2 dd1 = *reinterpret_cast<const uchar2*>(dm + (size_t)(r0 + 8) * dmld + cc);
                float e0 = __expf(acc[mi][ni][0] * scale + lg0 + table[dd0.x]);
                float e1 = __expf(acc[mi][ni][1] * scale + lg1 + table[dd0.y]);
                float e2 = __expf(acc[mi][ni][2] * scale + lg0 + table[dd1.x]);
                float e3 = __expf(acc[mi][ni][3] * scale + lg1 + table[dd1.y]);
                size_t o0 = (size_t)blockIdx.z * zsC + (size_t)r0 * ldc + cc;
                size_t o1 = (size_t)blockIdx.z * zsC + (size_t)(r0 + 8) * ldc + cc;
                uint32_t lo0, lo1;
                uint32_t hi0 = pack_hi_lo(e0, e1, lo0);
                uint32_t hi1 = pack_hi_lo(e2, e3, lo1);
                *reinterpret_cast<uint32_t*>(Coh + o0) = hi0;
                *reinterpret_cast<uint32_t*>(Col + o0) = lo0;
                *reinterpret_cast<uint32_t*>(Coh + o1) = hi1;
                *reinterpret_cast<uint32_t*>(Col + o1) = lo1;
                rs0[mi] += e0 + e1;
                rs1[mi] += e2 + e3;
            }
        }
        __syncthreads();
        float* srs = reinterpret_cast<float*>(smem);
        #pragma unroll
        for (int mi = 0; mi < MI; ++mi) {
            float a = rs0[mi];
            a += __shfl_xor_sync(0xFFFFFFFFu, a, 1);
            a += __shfl_xor_sync(0xFFFFFFFFu, a, 2);
            float b = rs1[mi];
            b += __shfl_xor_sync(0xFFFFFFFFu, b, 1);
            b += __shfl_xor_sync(0xFFFFFFFFu, b, 2);
            if ((lane & 3) == 0) {
                int rr = mbase + mi * 16 + (lane >> 2);
                srs[wn * BM + rr]     = a;
                srs[wn * BM + rr + 8] = b;
            }
        }
        __syncthreads();
        if (tid < BM) {
            float part = srs[tid] + srs[BM + tid];
            rsp[((size_t)blockIdx.z * (size_t)M + m0 + tid) * 8 + blockIdx.x] = part;
        }
    }
}

// ---------------- 1/rowsum from nt deterministic partials ----------------
__global__ void rowsum_reduce_kernel(const float* __restrict__ rsp,
                                     float* __restrict__ rinv, int n, int nt) {
    int i = blockIdx.x * blockDim.x + threadIdx.x;
    if (i < n) {
        const float* p = rsp + (size_t)i * 8;
        float s = 0.f;
        for (int j = 0; j < nt; ++j) s += p[j];
        rinv[i] = 1.0f / s;
    }
}

// ---------------- split fp32 -> fp16 pair (elementwise) ----------------
__global__ void split_kernel(const float4* __restrict__ in, uint2* __restrict__ outH,
                             uint2* __restrict__ outL, int n4) {
    int i = blockIdx.x * blockDim.x + threadIdx.x;
    if (i < n4) {
        uint2 H, L; split4(in[i], H, L);
        outH[i] = H; outL[i] = L;
    }
}

// ---------------- dm int32 -> uint8 ----------------
__global__ void dm8_kernel(const int4* __restrict__ in, uchar4* __restrict__ out, int n4) {
    int i = blockIdx.x * blockDim.x + threadIdx.x;
    if (i < n4) {
        int4 v = in[i];
        out[i] = make_uchar4((uint8_t)v.x, (uint8_t)v.y, (uint8_t)v.z, (uint8_t)v.w);
    }
}

// ---------------- batched transpose + split: out[z][C,R] = in[z][R,C]^T ----------------
__global__ void transpose_split_kernel(const float* __restrict__ in, size_t zsIn,
                                       f16* __restrict__ outH, f16* __restrict__ outL,
                                       size_t zsOut, int R, int Ccols) {
    __shared__ float tile[32][33];
    in   += (size_t)blockIdx.z * zsIn;
    outH += (size_t)blockIdx.z * zsOut;
    outL += (size_t)blockIdx.z * zsOut;
    int c0 = blockIdx.x * 32, r0 = blockIdx.y * 32;
    int x = threadIdx.x, y = threadIdx.y;           // 32 x 8
    #pragma unroll
    for (int j = 0; j < 32; j += 8)
        tile[y + j][x] = in[(size_t)(r0 + y + j) * Ccols + c0 + x];
    __syncthreads();
    #pragma unroll
    for (int j = 0; j < 32; j += 8) {
        float v = tile[x][y + j];
        f16 h = __float2half(v);
        f16 l = __float2half(v - __half2float(h));
        size_t o = (size_t)(c0 + y + j) * R + r0 + x;
        outH[o] = h; outL[o] = l;
    }
}

// ---------------- transpose pair input (recombine) + re-split ----------------
__global__ void transpose_resplit_kernel(const f16* __restrict__ inH,
                                         const f16* __restrict__ inL,
                                         f16* __restrict__ outH, f16* __restrict__ outL,
                                         int R, int Ccols) {
    __shared__ float tile[32][33];
    int c0 = blockIdx.x * 32, r0 = blockIdx.y * 32;
    int x = threadIdx.x, y = threadIdx.y;
    #pragma unroll
    for (int j = 0; j < 32; j += 8) {
        size_t o = (size_t)(r0 + y + j) * Ccols + c0 + x;
        tile[y + j][x] = __half2float(inH[o]) + __half2float(inL[o]);
    }
    __syncthreads();
    #pragma unroll
    for (int j = 0; j < 32; j += 8) {
        float v = tile[x][y + j];
        f16 h = __float2half(v);
        f16 l = __float2half(v - __half2float(h));
        size_t o = (size_t)(c0 + y + j) * R + r0 + x;
        outH[o] = h; outL[o] = l;
    }
}

// ---------------- fused q bias ----------------
__global__ void fuse_bias_kernel(const float* __restrict__ bproj,
                                 const float* __restrict__ Wq,
                                 const float* __restrict__ bq,
                                 float* __restrict__ out) {
    int o = blockIdx.x * blockDim.x + threadIdx.x;
    float s = bq[o];
    for (int k = 0; k < HID; k++) s += bproj[k] * Wq[(size_t)k * HID + o];
    out[o] = s;
}

// ---------------- copy bk/bv into adjacent scratch [l][2][HID] ----------------
__global__ void copy_bkv_kernel(const float* __restrict__ bk, const float* __restrict__ bv,
                                float* __restrict__ out) {
    int i = blockIdx.x * blockDim.x + threadIdx.x;      // NLAYER*HID
    int l = i / HID, c = i % HID;
    out[(l * 2) * HID + c]     = bk[i];
    out[(l * 2 + 1) * HID + c] = bv[i];
}

// ---------------- community preprocessing (deterministic, stable) ----------------
__global__ void hist_kernel(const int* __restrict__ ntc) {
    __shared__ int sh[C_COMM];
    int chunk = blockIdx.x;
    for (int i = threadIdx.x; i < C_COMM; i += blockDim.x) sh[i] = 0;
    __syncthreads();
    atomicAdd(&sh[ntc[chunk * CHUNK + threadIdx.x]], 1);
    __syncthreads();
    for (int i = threadIdx.x; i < C_COMM; i += blockDim.x)
        g_hist[chunk * C_COMM + i] = sh[i];
}

__global__ void chunk_scan_kernel() {
    int c = blockIdx.x;
    __shared__ int s[NCHUNK];
    int t = threadIdx.x;
    int own = g_hist[t * C_COMM + c];
    s[t] = own;
    __syncthreads();
    for (int off = 1; off < NCHUNK; off <<= 1) {
        int v = (t >= off) ? s[t - off] : 0;
        __syncthreads();
        s[t] += v;
        __syncthreads();
    }
    g_chunkbase[t * C_COMM + c] = s[t] - own;
    if (t == NCHUNK - 1) g_counts[c] = s[t];
}

__global__ void offsets_kernel() {
    __shared__ int s[C_COMM];
    int t = threadIdx.x;
    int own = g_counts[t];
    s[t] = own;
    __syncthreads();
    for (int off = 1; off < C_COMM; off <<= 1) {
        int v = (t >= off) ? s[t - off] : 0;
        __syncthreads();
        s[t] += v;
        __syncthreads();
    }
    g_offsets[t] = s[t] - own;
    g_logc[t]    = logf((float)own);
    g_inv[t]     = 1.0f / (float)(own > 0 ? own : 1);
}

__global__ void scatter_kernel(const int* __restrict__ ntc) {
    __shared__ int s[CHUNK];
    int chunk = blockIdx.x;
    int t = threadIdx.x;
    int node = chunk * CHUNK + t;
    int c = ntc[node];
    s[t] = c;
    __syncthreads();
    int lrank = 0;
    for (int j = 0; j < t; j++) lrank += (s[j] == c);
    g_members[g_offsets[c] + g_chunkbase[chunk * C_COMM + c] + lrank] = node;
}

__global__ void comm_avg_kernel() {
    int c = blockIdx.x;
    int t = threadIdx.x;
    int off = g_offsets[c], cnt = g_counts[c];
    float a0 = 0.f, a1 = 0.f;
    for (int m = 0; m < cnt; m++) {
        const float* row = g_h + (size_t)g_members[off + m] * HID;
        a0 += row[t];
        a1 += row[t + 256];
    }
    float inv = g_inv[c];
    a0 *= inv; a1 *= inv;
    f16 h0 = __float2half(a0), h1 = __float2half(a1);
    g_cmh[c * HID + t]       = h0;
    g_cmh[c * HID + t + 256] = h1;
    g_cml[c * HID + t]       = __float2half(a0 - __half2float(h0));
    g_cml[c * HID + t + 256] = __float2half(a1 - __half2float(h1));
}

__global__ void bias_table_kernel(const float* __restrict__ emb,
                                  const float* __restrict__ w,
                                  const float* __restrict__ bptr) {
    int i = blockIdx.x;
    int t = threadIdx.x;
    float s = emb[i * HID + t]       * w[t]
            + emb[i * HID + t + 128] * w[t + 128]
            + emb[i * HID + t + 256] * w[t + 256]
            + emb[i * HID + t + 384] * w[t + 384];
    for (int o = 16; o; o >>= 1) s += __shfl_xor_sync(0xFFFFFFFFu, s, o);
    __shared__ float r[4];
    if ((t & 31) == 0) r[t >> 5] = s;
    __syncthreads();
    if (t == 0) g_table[i] = r[0] + r[1] + r[2] + r[3] + bptr[0];
}

// warp-per-row LayerNorm + ReLU; fp32 (optional) + fp16 pair outputs
__global__ void ln_relu_kernel(const float* __restrict__ in, float* __restrict__ outF,
                               f16* __restrict__ outH, f16* __restrict__ outL,
                               const float* __restrict__ g, const float* __restrict__ b) {
    int w = threadIdx.x >> 5, lane = threadIdx.x & 31;
    size_t row = (size_t)blockIdx.x * 8 + w;
    const float* x = in + row * HID;
    float4 v[4];
    float s = 0.f, q = 0.f;
    #pragma unroll
    for (int k = 0; k < 4; k++) {
        v[k] = *reinterpret_cast<const float4*>(x + k * 128 + lane * 4);
        s += v[k].x + v[k].y + v[k].z + v[k].w;
        q += v[k].x * v[k].x + v[k].y * v[k].y + v[k].z * v[k].z + v[k].w * v[k].w;
    }
    #pragma unroll
    for (int o = 16; o; o >>= 1) {
        s += __shfl_xor_sync(0xFFFFFFFFu, s, o);
        q += __shfl_xor_sync(0xFFFFFFFFu, q, o);
    }
    float mean = s * (1.0f / HID);
    float var  = q * (1.0f / HID) - mean * mean;
    float rstd = rsqrtf(var + EPS);
    #pragma unroll
    for (int k = 0; k < 4; k++) {
        int c = k * 128 + lane * 4;
        float4 gg = *reinterpret_cast<const float4*>(g + c);
        float4 bb = *reinterpret_cast<const float4*>(b + c);
        float4 y;
        y.x = fmaxf((v[k].x - mean) * rstd * gg.x + bb.x, 0.f);
        y.y = fmaxf((v[k].y - mean) * rstd * gg.y + bb.y, 0.f);
        y.z = fmaxf((v[k].z - mean) * rstd * gg.z + bb.z, 0.f);
        y.w = fmaxf((v[k].w - mean) * rstd * gg.w + bb.w, 0.f);
        if (outF) *reinterpret_cast<float4*>(outF + row * HID + c) = y;
        uint2 H, L; split4(y, H, L);
        *reinterpret_cast<uint2*>(outH + row * HID + c) = H;
        *reinterpret_cast<uint2*>(outL + row * HID + c) = L;
    }
}

// ---------------- host-side helpers ----------------
static const int SMEM_128_T2 = 3 * (2 * 10240 + 10240);      // 92160
static const int SMEM_64_T3  = 3 * (2 * 10240 + 2 * 5120);   // 92160
static const int SMEM_64_T2  = 3 * (2 * 10240 + 5120);       // 76800

static void tc_nn(int M, int Nc, int K,
                  const f16* Ah, const f16* Al, int lda,
                  const f16* Bth, const f16* Btl,
                  const float* bias,
                  float* Cf, f16* Coh, f16* Col, int ldc)
{
    if (Nc % 128 == 0) {
        dim3 g(Nc / 128, M / 128, 1);
        mma_gemm<128, 0, 2><<<g, 256, SMEM_128_T2>>>(M, K, Ah, Al, lda, 0, Bth, Btl, K, 0,
                                                     bias, 0, Cf, Coh, Col, ldc, 0,
                                                     0.f, nullptr, nullptr, nullptr, 0,
                                                     nullptr, nullptr);
    } else {
        dim3 g(Nc / 64, M / 128, 1);
        mma_gemm<64, 0, 2><<<g, 256, SMEM_64_T2>>>(M, K, Ah, Al, lda, 0, Bth, Btl, K, 0,
                                                   bias, 0, Cf, Coh, Col, ldc, 0,
                                                   0.f, nullptr, nullptr, nullptr, 0,
                                                   nullptr, nullptr);
    }
}

extern "C" void kernel_launch(void* const* d_in, const int* in_sizes, int n_in,
                              void* d_out, int out_size)
{
    // ---- input mapping (auto-detect metadata order) ----
    const float *x      = (const float*)d_in[0];
    const int   *dm     = (const int*)  d_in[1];
    const int   *ntc    = (const int*)  d_in[2];
    const float *W_in1  = (const float*)d_in[3];
    const float *b_in1  = (const float*)d_in[4];
    const float *ln_in_g= (const float*)d_in[5];
    const float *ln_in_b= (const float*)d_in[6];
    const float *W_in2  = (const float*)d_in[7];
    const float *b_in2  = (const float*)d_in[8];
    const float *Wproj, *Wq, *Wk, *Wv, *ffW1, *ffW2;
    const float *bproj, *bq, *bk, *bv, *ffb1, *ffb2;
    const float *dis_emb, *dis_w, *dis_b;
    const float *ffg1, *ffbeta1, *ffg2, *ffbeta2, *Wout, *bout;

    if (in_sizes[10] == NLAYER * HID * HID) {
        Wproj  = (const float*)d_in[9];  Wq     = (const float*)d_in[10];
        Wk     = (const float*)d_in[11]; Wv     = (const float*)d_in[12];
        ffW1   = (const float*)d_in[13]; ffW2   = (const float*)d_in[14];
        bproj  = (const float*)d_in[15]; bq     = (const float*)d_in[16];
        bk     = (const float*)d_in[17]; bv     = (const float*)d_in[18];
        ffb1   = (const float*)d_in[19]; ffb2   = (const float*)d_in[20];
        dis_emb= (const float*)d_in[21]; dis_w  = (const float*)d_in[22];
        dis_b  = (const float*)d_in[23];
        ffg1   = (const float*)d_in[24]; ffbeta1= (const float*)d_in[25];
        ffg2   = (const float*)d_in[26]; ffbeta2= (const float*)d_in[27];
        Wout   = (const float*)d_in[28]; bout   = (const float*)d_in[29];
    } else {
        Wproj  = (const float*)d_in[9];  bproj  = (const float*)d_in[10];
        Wq     = (const float*)d_in[11]; bq     = (const float*)d_in[12];
        Wk     = (const float*)d_in[13]; bk     = (const float*)d_in[14];
        Wv     = (const float*)d_in[15]; bv     = (const float*)d_in[16];
        dis_emb= (const float*)d_in[17]; dis_w  = (const float*)d_in[18];
        dis_b  = (const float*)d_in[19];
        ffW1   = (const float*)d_in[20]; ffb1   = (const float*)d_in[21];
        ffg1   = (const float*)d_in[22]; ffbeta1= (const float*)d_in[23];
        ffW2   = (const float*)d_in[24]; ffb2   = (const float*)d_in[25];
        ffg2   = (const float*)d_in[26]; ffbeta2= (const float*)d_in[27];
        Wout   = (const float*)d_in[28]; bout   = (const float*)d_in[29];
    }

    cudaFuncSetAttribute(mma_gemm<128, 0, 2>, cudaFuncAttributeMaxDynamicSharedMemorySize, SMEM_128_T2);
    cudaFuncSetAttribute(mma_gemm<128, 1, 2>, cudaFuncAttributeMaxDynamicSharedMemorySize, SMEM_128_T2);
    cudaFuncSetAttribute(mma_gemm<64, 0, 2>,  cudaFuncAttributeMaxDynamicSharedMemorySize, SMEM_64_T2);
    cudaFuncSetAttribute(mma_gemm<64, 0, 3>,  cudaFuncAttributeMaxDynamicSharedMemorySize, SMEM_64_T3);

    // ---- scratch pointers ----
    float *p_h, *p_t0, *p_t1, *p_logc, *p_table, *p_bfq, *p_bkv, *p_rsp, *p_rinv;
    f16 *p_xh, *p_xl, *p_hh, *p_hl, *p_t0h, *p_t0l, *p_t1h, *p_t1l, *p_qh, *p_ql;
    f16 *p_ph, *p_pl, *p_cmh, *p_cml, *p_kvh, *p_kvl, *p_vth, *p_vtl, *p_wh, *p_wl;
    uint8_t *p_dm8;
    cudaGetSymbolAddress((void**)&p_h,    g_h);
    cudaGetSymbolAddress((void**)&p_t0,   g_t0);
    cudaGetSymbolAddress((void**)&p_t1,   g_t1);
    cudaGetSymbolAddress((void**)&p_logc, g_logc);
    cudaGetSymbolAddress((void**)&p_table,g_table);
    cudaGetSymbolAddress((void**)&p_bfq,  g_bfq);
    cudaGetSymbolAddress((void**)&p_bkv,  g_bkv);
    cudaGetSymbolAddress((void**)&p_rsp,  g_rsp);
    cudaGetSymbolAddress((void**)&p_rinv, g_rinv);
    cudaGetSymbolAddress((void**)&p_dm8,  g_dm8);
    cudaGetSymbolAddress((void**)&p_xh,  g_xh);  cudaGetSymbolAddress((void**)&p_xl,  g_xl);
    cudaGetSymbolAddress((void**)&p_hh,  g_hh);  cudaGetSymbolAddress((void**)&p_hl,  g_hl);
    cudaGetSymbolAddress((void**)&p_t0h, g_t0h); cudaGetSymbolAddress((void**)&p_t0l, g_t0l);
    cudaGetSymbolAddress((void**)&p_t1h, g_t1h); cudaGetSymbolAddress((void**)&p_t1l, g_t1l);
    cudaGetSymbolAddress((void**)&p_qh,  g_qh);  cudaGetSymbolAddress((void**)&p_ql,  g_ql);
    cudaGetSymbolAddress((void**)&p_ph,  g_ph);  cudaGetSymbolAddress((void**)&p_pl,  g_pl);
    cudaGetSymbolAddress((void**)&p_cmh, g_cmh); cudaGetSymbolAddress((void**)&p_cml, g_cml);
    cudaGetSymbolAddress((void**)&p_kvh, g_kvh); cudaGetSymbolAddress((void**)&p_kvl, g_kvl);
    cudaGetSymbolAddress((void**)&p_vth, g_vth); cudaGetSymbolAddress((void**)&p_vtl, g_vtl);
    cudaGetSymbolAddress((void**)&p_wh,  g_wh);  cudaGetSymbolAddress((void**)&p_wl,  g_wl);
    #define WH(i) (p_wh + (size_t)(i) * HID * HID)
    #define WL(i) (p_wl + (size_t)(i) * HID * HID)

    const float scale = 1.0f / sqrtf((float)DHEAD);
    const size_t W2 = (size_t)HID * HID;

    // ---- weight preprocessing (batched) ----
    // slots: 0=W_in1T 1=W_in2T; layer l: s0=2+l*5 {0:WfqT,1:WkT,2:WvT,3:ffW1T,4:ffW2T};
    // 12=WoutT; 13,14=WqT l0,l1; 15,16=Wproj split l0,l1
    {
        dim3 b(32, 8);
        transpose_split_kernel<<<dim3(HID / 32, IN_DIM / 32, 1), b>>>(
            W_in1, 0, WH(0), WL(0), 0, IN_DIM, HID);
        transpose_split_kernel<<<dim3(HID / 32, HID / 32, 1), b>>>(
            W_in2, 0, WH(1), WL(1), 0, HID, HID);
        transpose_split_kernel<<<dim3(OUT_DIM / 32, HID / 32, 1), b>>>(
            Wout, 0, WH(12), WL(12), 0, HID, OUT_DIM);
        transpose_split_kernel<<<dim3(HID / 32, HID / 32, NLAYER), b>>>(
            Wq, W2, WH(13), WL(13), W2, HID, HID);
        transpose_split_kernel<<<dim3(HID / 32, HID / 32, NLAYER), b>>>(
            Wk, W2, WH(3), WL(3), 5 * W2, HID, HID);
        transpose_split_kernel<<<dim3(HID / 32, HID / 32, NLAYER), b>>>(
            Wv, W2, WH(4), WL(4), 5 * W2, HID, HID);
        transpose_split_kernel<<<dim3(HID / 32, HID / 32, NLAYER), b>>>(
            ffW1, W2, WH(5), WL(5), 5 * W2, HID, HID);
        transpose_split_kernel<<<dim3(HID / 32, HID / 32, NLAYER), b>>>(
            ffW2, W2, WH(6), WL(6), 5 * W2, HID, HID);
    }
    split_kernel<<<N_NODES * IN_DIM / 1024, 256>>>((const float4*)x, (uint2*)p_xh, (uint2*)p_xl,
                                                   N_NODES * IN_DIM / 4);
    split_kernel<<<NLAYER * HID * HID / 1024, 256>>>((const float4*)Wproj,
                                                     (uint2*)WH(15), (uint2*)WL(15),
                                                     NLAYER * HID * HID / 4);
    // fused q weight (both layers, 3-term for precision): WfqT = WqT . Wproj^T-form
    {
        dim3 g(HID / 64, HID / 128, NLAYER);
        mma_gemm<64, 0, 3><<<g, 256, SMEM_64_T3>>>(HID, HID,
                                                   WH(13), WL(13), HID, W2,
                                                   WH(15), WL(15), HID, W2,
                                                   nullptr, 0, nullptr, WH(2), WL(2), HID, 5 * W2,
                                                   0.f, nullptr, nullptr, nullptr, 0,
                                                   nullptr, nullptr);
    }
    for (int l = 0; l < NLAYER; l++)
        fuse_bias_kernel<<<HID / 256, 256>>>(bproj + (size_t)l * HID,
                                             Wq + (size_t)l * W2,
                                             bq + (size_t)l * HID, p_bfq + (size_t)l * HID);
    copy_bkv_kernel<<<NLAYER * HID / 256, 256>>>(bk, bv, p_bkv);
    dm8_kernel<<<(int)((size_t)N_NODES * C_COMM / 1024), 256>>>(
        (const int4*)dm, (uchar4*)p_dm8, (int)((size_t)N_NODES * C_COMM / 4));

    // ---- community preprocessing (deterministic) ----
    hist_kernel      <<<NCHUNK, CHUNK>>>(ntc);
    chunk_scan_kernel<<<C_COMM, NCHUNK>>>();
    offsets_kernel   <<<1, C_COMM>>>();
    scatter_kernel   <<<NCHUNK, CHUNK>>>(ntc);

    // ---- fc_in ----
    tc_nn(N_NODES, HID, IN_DIM, p_xh, p_xl, IN_DIM, WH(0), WL(0), b_in1,
          p_t0, nullptr, nullptr, HID);
    ln_relu_kernel<<<N_NODES / 8, 256>>>(p_t0, nullptr, p_t0h, p_t0l, ln_in_g, ln_in_b);
    tc_nn(N_NODES, HID, HID, p_t0h, p_t0l, HID, WH(1), WL(1), b_in2,
          p_h, p_hh, p_hl, HID);

    // ---- layers ----
    for (int l = 0; l < NLAYER; l++) {
        int s0 = 2 + l * 5;
        bias_table_kernel<<<NDIST, 128>>>(dis_emb + (size_t)l * NDIST * HID,
                                          dis_w + (size_t)l * HID, dis_b + l);
        comm_avg_kernel<<<C_COMM, 256>>>();

        // q = h @ WfqT^T + bfq
        tc_nn(N_NODES, HID, HID, p_hh, p_hl, HID, WH(s0), WL(s0),
              p_bfq + (size_t)l * HID, nullptr, p_qh, p_ql, HID);
        // k and v in one launch (z: 0=k, 1=v), pair outputs adjacent
        {
            dim3 g(HID / 128, C_COMM / 128, 2);
            mma_gemm<128, 0, 2><<<g, 256, SMEM_128_T2>>>(
                C_COMM, HID,
                p_cmh, p_cml, HID, 0,
                WH(s0 + 1), WL(s0 + 1), HID, W2,
                p_bkv + (size_t)l * 2 * HID, HID,
                nullptr, p_kvh, p_kvl, HID, (size_t)C_COMM * HID,
                0.f, nullptr, nullptr, nullptr, 0,
                nullptr, nullptr);
        }
        transpose_resplit_kernel<<<dim3(HID / 32, C_COMM / 32), dim3(32, 8)>>>(
            p_kvh + (size_t)C_COMM * HID, p_kvl + (size_t)C_COMM * HID,
            p_vth, p_vtl, C_COMM, HID);

        // dots per head: fused exp epilogue -> unnormalized e pairs + row partial sums
        {
            dim3 g(C_COMM / 128, N_NODES / 128, NHEAD);
            mma_gemm<128, 1, 2><<<g, 256, SMEM_128_T2>>>(
                N_NODES, DHEAD,
                p_qh, p_ql, HID, (size_t)DHEAD,
                p_kvh, p_kvl, HID, (size_t)DHEAD,
                nullptr, 0,
                nullptr, p_ph, p_pl, C_COMM, (size_t)N_NODES * C_COMM,
                scale, p_logc, p_table, p_dm8, C_COMM,
                p_rsp, nullptr);
        }
        rowsum_reduce_kernel<<<NHEAD * N_NODES / 256, 256>>>(p_rsp, p_rinv,
                                                             NHEAD * N_NODES, C_COMM / 128);

        // AV per head: multiply by 1/rowsum in epilogue -> t0 split
        {
            dim3 g(DHEAD / 128, N_NODES / 128, NHEAD);
            mma_gemm<128, 0, 2><<<g, 256, SMEM_128_T2>>>(
                N_NODES, C_COMM,
                p_ph, p_pl, C_COMM, (size_t)N_NODES * C_COMM,
                p_vth, p_vtl, C_COMM, (size_t)DHEAD * C_COMM,
                nullptr, 0,
                nullptr, p_t0h, p_t0l, HID, (size_t)DHEAD,
                0.f, nullptr, nullptr, nullptr, 0,
                nullptr, p_rinv);
        }

        tc_nn(N_NODES, HID, HID, p_t0h, p_t0l, HID, WH(s0 + 3), WL(s0 + 3),
              ffb1 + (size_t)l * HID, p_t1, nullptr, nullptr, HID);
        ln_relu_kernel<<<N_NODES / 8, 256>>>(p_t1, nullptr, p_t1h, p_t1l,
                                             ffg1 + (size_t)l * HID, ffbeta1 + (size_t)l * HID);
        tc_nn(N_NODES, HID, HID, p_t1h, p_t1l, HID, WH(s0 + 4), WL(s0 + 4),
              ffb2 + (size_t)l * HID, p_t0, nullptr, nullptr, HID);
        ln_relu_kernel<<<N_NODES / 8, 256>>>(p_t0, p_h, p_hh, p_hl,
                                             ffg2 + (size_t)l * HID, ffbeta2 + (size_t)l * HID);
    }

    // ---- output projection ----
    tc_nn(N_NODES, OUT_DIM, HID, p_hh, p_hl, HID, WH(12), WL(12), bout,
          (float*)d_out, nullptr, nullptr, OUT_DIM);
}

// round 16
// speedup vs baseline: 4.0998x; 1.0808x over previous
#include <cuda_runtime.h>
#include <cuda_fp16.h>
#include <math.h>
#include <stdint.h>

// ---------------- problem constants ----------------
#define N_NODES 32768
#define C_COMM  512
#define IN_DIM  128
#define HID     512
#define NHEAD   4
#define DHEAD   128
#define NLAYER  2
#define OUT_DIM 64
#define NDIST   31
#define EPS     1e-5f

#define CHUNK   256
#define NCHUNK  (N_NODES / CHUNK)   // 128

typedef __half f16;

// ---------------- scratch (device globals; no allocation allowed) ----------------
__device__ float g_h   [N_NODES * HID];
__device__ float g_t0  [N_NODES * HID];
__device__ float g_t1  [N_NODES * HID];
__device__ float g_bfq [NLAYER * HID];
__device__ float g_bkv [NLAYER * 2 * HID];
__device__ float g_rsp [(size_t)NHEAD * N_NODES * 8];
__device__ float g_rinv[(size_t)NHEAD * N_NODES];

__device__ f16 g_xh [N_NODES * IN_DIM], g_xl [N_NODES * IN_DIM];
__device__ f16 g_hh [N_NODES * HID],    g_hl [N_NODES * HID];
__device__ f16 g_t0h[N_NODES * HID],    g_t0l[N_NODES * HID];
__device__ f16 g_t1h[N_NODES * HID],    g_t1l[N_NODES * HID];
__device__ f16 g_qh [N_NODES * HID],    g_ql [N_NODES * HID];
__device__ f16 g_ph [(size_t)NHEAD * N_NODES * C_COMM];   // unnormalized exp (hi only)
__device__ f16 g_cmh[C_COMM * HID],     g_cml[C_COMM * HID];
__device__ f16 g_kvh[2 * C_COMM * HID];                    // [k; v] hi only
__device__ f16 g_vth[HID * C_COMM];
__device__ f16 g_wh [17][HID * HID],    g_wl [17][HID * HID];
__device__ uint8_t g_dm8[(size_t)N_NODES * C_COMM];

__device__ int   g_hist     [NCHUNK * C_COMM];
__device__ int   g_chunkbase[NCHUNK * C_COMM];
__device__ int   g_counts [C_COMM];
__device__ int   g_offsets[C_COMM];
__device__ int   g_members[N_NODES];
__device__ float g_logc[C_COMM];
__device__ float g_inv [C_COMM];
__device__ float g_table[NDIST];

// ---------------- small PTX helpers (all sm_80-compatible) ----------------
__device__ __forceinline__ uint32_t smem_u32(const void* p) {
    uint32_t a;
    asm("{ .reg .u64 t; cvta.to.shared.u64 t, %1; cvt.u32.u64 %0, t; }" : "=r"(a) : "l"(p));
    return a;
}

__device__ __forceinline__ void cpa16(uint32_t dst, const void* src) {
    asm volatile("{ .reg .u64 g; cvta.to.global.u64 g, %1; cp.async.cg.shared.global [%0], [g], 16; }"
                 :: "r"(dst), "l"(src));
}
#define CP_COMMIT() asm volatile("cp.async.commit_group;" ::: "memory")
#define CP_WAIT1()  asm volatile("cp.async.wait_group 1;" ::: "memory")

__device__ __forceinline__ void ldm4(uint32_t* r, uint32_t addr) {
    asm volatile("ldmatrix.sync.aligned.m8n8.x4.shared.b16 {%0,%1,%2,%3}, [%4];"
                 : "=r"(r[0]), "=r"(r[1]), "=r"(r[2]), "=r"(r[3]) : "r"(addr));
}

__device__ __forceinline__ void mma_f16(float* d, const uint32_t* a, const uint32_t* b) {
    asm volatile(
        "mma.sync.aligned.m16n8k16.row.col.f32.f16.f16.f32 "
        "{%0,%1,%2,%3}, {%4,%5,%6,%7}, {%8,%9}, {%0,%1,%2,%3};"
        : "+f"(d[0]), "+f"(d[1]), "+f"(d[2]), "+f"(d[3])
        : "r"(a[0]), "r"(a[1]), "r"(a[2]), "r"(a[3]), "r"(b[0]), "r"(b[1]));
}

// split fp32x4 -> fp16 hi quad + fp16 lo quad
__device__ __forceinline__ void split4(float4 v, uint2& H, uint2& L) {
    f16 hx = __float2half(v.x), hy = __float2half(v.y);
    f16 hz = __float2half(v.z), hw = __float2half(v.w);
    H.x = (uint32_t)__half_as_ushort(hx) | ((uint32_t)__half_as_ushort(hy) << 16);
    H.y = (uint32_t)__half_as_ushort(hz) | ((uint32_t)__half_as_ushort(hw) << 16);
    f16 lx = __float2half(v.x - __half2float(hx));
    f16 ly = __float2half(v.y - __half2float(hy));
    f16 lz = __float2half(v.z - __half2float(hz));
    f16 lw = __float2half(v.w - __half2float(hw));
    L.x = (uint32_t)__half_as_ushort(lx) | ((uint32_t)__half_as_ushort(ly) << 16);
    L.y = (uint32_t)__half_as_ushort(lz) | ((uint32_t)__half_as_ushort(lw) << 16);
}

__device__ __forceinline__ uint32_t pack_hi_lo(float a, float b, uint32_t& outlo) {
    f16 ha = __float2half(a), hb = __float2half(b);
    f16 la = __float2half(a - __half2float(ha));
    f16 lb = __float2half(b - __half2float(hb));
    outlo = (uint32_t)__half_as_ushort(la) | ((uint32_t)__half_as_ushort(lb) << 16);
    return (uint32_t)__half_as_ushort(ha) | ((uint32_t)__half_as_ushort(hb) << 16);
}

__device__ __forceinline__ uint32_t pack_hi(float a, float b) {
    return (uint32_t)__half_as_ushort(__float2half(a)) |
           ((uint32_t)__half_as_ushort(__float2half(b)) << 16);
}

// ---------------- warp-MMA GEMM on pre-split fp16 pairs ----------------
// TERMS==3: (Ah+Al)(Bh+Bl)^T.  TERMS==2: (Ah+Al)Bh^T.  TERMS==1: Ah Bh^T.
// BM=128 x BN tile, 8 warps (4m x 2n), 3-stage cp.async pipeline, 2 CTAs/SM.
// EPI==0: +bias[z*bstride + col], optional rowinv scaling, fp32/pair out (Col nullable).
// EPI==1: dots epilogue -> e = exp(d*scale + logc + table[dm8]); e hi (+lo if Col)
//         + deterministic per-row partial sums to rsp[row*8 + blockIdx.x].
template<int BN, int EPI, int TERMS>
__global__ __launch_bounds__(256, 2)
void mma_gemm(int M, int K,
              const f16* __restrict__ Ah, const f16* __restrict__ Al, int lda, size_t zsA,
              const f16* __restrict__ Bh, const f16* __restrict__ Bl, int ldb, size_t zsB,
              const float* __restrict__ bias, int bstride,
              float* __restrict__ Cf, f16* __restrict__ Coh, f16* __restrict__ Col,
              int ldc, size_t zsC,
              float scale, const float* __restrict__ logc,
              const float* __restrict__ table,
              const uint8_t* __restrict__ dm, int dmld,
              float* __restrict__ rsp, const float* __restrict__ rowinv)
{
    constexpr int BM  = 128;
    constexpr int LDS = 40;                  // f16 elems per smem row (80B stride)
    constexpr int NW_N = 2;
    constexpr int NW_M = 4;
    constexpr int WM  = BM / NW_M;           // 32
    constexpr int MI  = WM / 16;             // 2
    constexpr int WN  = BN / NW_N;           // 32 or 64
    constexpr int NI  = WN / 8;              // 4 or 8
    constexpr int NG  = NI / 2;
    constexpr int NBT = BN * 4 / 256;
    constexpr int ABUF = (TERMS >= 2) ? 2 : 1;
    constexpr int ASZ = BM * LDS * 2;        // 10240 B per A matrix
    constexpr int BSZ = BN * LDS * 2;
    constexpr int STAGE = ABUF * ASZ + (TERMS == 3 ? 2 : 1) * BSZ;

    extern __shared__ char smem[];
    const uint32_t uS = smem_u32(smem);

    Ah += (size_t)blockIdx.z * zsA;
    if (TERMS >= 2) Al += (size_t)blockIdx.z * zsA;
    Bh += (size_t)blockIdx.z * zsB;
    if (TERMS == 3) Bl += (size_t)blockIdx.z * zsB;
    const int m0 = blockIdx.y * BM, n0 = blockIdx.x * BN;
    const int tid = threadIdx.x, lane = tid & 31, wid = tid >> 5;
    const int wm = wid % NW_M, wn = wid / NW_M;
    const int mbase = wm * WM, nbase = wn * WN;
    const int lr = lane & 15, lc8 = (lane >> 4) * 8;

    const int nch = K >> 5;

    auto issue = [&](int s, int kc) {
        const uint32_t sb = uS + (uint32_t)(s * STAGE);
        const int k0 = kc << 5;
        #pragma unroll
        for (int t = 0; t < 2; ++t) {
            int j = tid + t * 256, row = j >> 2, ck = j & 3;
            uint32_t off = (uint32_t)(row * 80 + ck * 16);
            size_t so = (size_t)(m0 + row) * lda + k0 + ck * 8;
            cpa16(sb + off, Ah + so);
            if (TERMS >= 2) cpa16(sb + ASZ + off, Al + so);
        }
        #pragma unroll
        for (int t = 0; t < NBT; ++t) {
            int j = tid + t * 256, row = j >> 2, ck = j & 3;
            uint32_t off = (uint32_t)(row * 80 + ck * 16);
            size_t so = (size_t)(n0 + row) * ldb + k0 + ck * 8;
            cpa16(sb + ABUF * ASZ + off, Bh + so);
            if (TERMS == 3) cpa16(sb + ABUF * ASZ + BSZ + off, Bl + so);
        }
    };

    float acc[MI][NI][4];
    #pragma unroll
    for (int mi = 0; mi < MI; ++mi)
        #pragma unroll
        for (int ni = 0; ni < NI; ++ni)
            #pragma unroll
            for (int q = 0; q < 4; ++q) acc[mi][ni][q] = 0.f;

    issue(0, 0); CP_COMMIT();
    if (nch > 1) issue(1, 1);
    CP_COMMIT();

    for (int ch = 0; ch < nch; ++ch) {
        CP_WAIT1();
        __syncthreads();   // publishes chunk ch AND closes stage (ch+2)%3's readers

        int nx = ch + 2;
        if (nx < nch) issue(nx % 3, nx);
        CP_COMMIT();

        const uint32_t sb = uS + (uint32_t)((ch % 3) * STAGE);
        const uint32_t uAh = sb, uAl = sb + ASZ;
        const uint32_t uBh = sb + ABUF * ASZ, uBl = sb + ABUF * ASZ + BSZ;
        #pragma unroll
        for (int ks = 0; ks < 2; ++ks) {
            uint32_t ah[MI][4], al[MI][4];
            #pragma unroll
            for (int mi = 0; mi < MI; ++mi) {
                uint32_t off = (uint32_t)((mbase + mi * 16 + lr) * LDS + ks * 16 + lc8) * 2;
                ldm4(ah[mi], uAh + off);
                if (TERMS >= 2) ldm4(al[mi], uAl + off);
            }
            uint32_t bh[NI][2], bl[NI][2], r[4];
            #pragma unroll
            for (int g = 0; g < NG; ++g) {
                uint32_t offg = (uint32_t)((nbase + g * 16 + lr) * LDS + ks * 16 + lc8) * 2;
                ldm4(r, uBh + offg);
                bh[2 * g][0] = r[0]; bh[2 * g][1] = r[2];
                bh[2 * g + 1][0] = r[1]; bh[2 * g + 1][1] = r[3];
                if (TERMS == 3) {
                    ldm4(r, uBl + offg);
                    bl[2 * g][0] = r[0]; bl[2 * g][1] = r[2];
                    bl[2 * g + 1][0] = r[1]; bl[2 * g + 1][1] = r[3];
                }
            }
            #pragma unroll
            for (int mi = 0; mi < MI; ++mi)
                #pragma unroll
                for (int ni = 0; ni < NI; ++ni) {
                    mma_f16(acc[mi][ni], ah[mi], bh[ni]);
                    if (TERMS >= 2) mma_f16(acc[mi][ni], al[mi], bh[ni]);
                    if (TERMS == 3) mma_f16(acc[mi][ni], ah[mi], bl[ni]);
                }
        }
    }

    if (EPI == 0) {
        #pragma unroll
        for (int mi = 0; mi < MI; ++mi) {
            int r0 = m0 + mbase + mi * 16 + (lane >> 2);
            float s0 = 1.f, s1 = 1.f;
            if (rowinv) {
                s0 = rowinv[(size_t)blockIdx.z * M + r0];
                s1 = rowinv[(size_t)blockIdx.z * M + r0 + 8];
            }
            #pragma unroll
            for (int ni = 0; ni < NI; ++ni) {
                int cc = n0 + nbase + ni * 8 + (lane & 3) * 2;
                float d0 = acc[mi][ni][0], d1 = acc[mi][ni][1];
                float d2 = acc[mi][ni][2], d3 = acc[mi][ni][3];
                if (bias) {
                    const float* bz = bias + (size_t)blockIdx.z * bstride;
                    float b0 = bz[cc], b1 = bz[cc + 1];
                    d0 += b0; d1 += b1; d2 += b0; d3 += b1;
                }
                d0 *= s0; d1 *= s0; d2 *= s1; d3 *= s1;
                size_t o0 = (size_t)blockIdx.z * zsC + (size_t)r0 * ldc + cc;
                size_t o1 = (size_t)blockIdx.z * zsC + (size_t)(r0 + 8) * ldc + cc;
                if (Cf) {
                    *reinterpret_cast<float2*>(Cf + o0) = make_float2(d0, d1);
                    *reinterpret_cast<float2*>(Cf + o1) = make_float2(d2, d3);
                }
                if (Coh) {
                    if (Col) {
                        uint32_t lo0, lo1;
                        uint32_t hi0 = pack_hi_lo(d0, d1, lo0);
                        uint32_t hi1 = pack_hi_lo(d2, d3, lo1);
                        *reinterpret_cast<uint32_t*>(Coh + o0) = hi0;
                        *reinterpret_cast<uint32_t*>(Col + o0) = lo0;
                        *reinterpret_cast<uint32_t*>(Coh + o1) = hi1;
                        *reinterpret_cast<uint32_t*>(Col + o1) = lo1;
                    } else {
                        *reinterpret_cast<uint32_t*>(Coh + o0) = pack_hi(d0, d1);
                        *reinterpret_cast<uint32_t*>(Coh + o1) = pack_hi(d2, d3);
                    }
                }
            }
        }
    } else {
        float rs0[MI], rs1[MI];
        #pragma unroll
        for (int mi = 0; mi < MI; ++mi) { rs0[mi] = 0.f; rs1[mi] = 0.f; }
        #pragma unroll
        for (int mi = 0; mi < MI; ++mi) {
            int r0 = m0 + mbase + mi * 16 + (lane >> 2);
            #pragma unroll
            for (int ni = 0; ni < NI; ++ni) {
                int cc = n0 + nbase + ni * 8 + (lane & 3) * 2;
                float lg0 = logc[cc], lg1 = logc[cc + 1];
                uchar2 dd0 = *reinterpret_cast<const uchar2*>(dm + (size_t)r0 * dmld + cc);
                uchar2 dd1 = *reinterpret_cast<const uchar2*>(dm + (size_t)(r0 + 8) * dmld + cc);
                float e0 = __expf(acc[mi][ni][0] * scale + lg0 + table[dd0.x]);
                float e1 = __expf(acc[mi][ni][1] * scale + lg1 + table[dd0.y]);
                float e2 = __expf(acc[mi][ni][2] * scale + lg0 + table[dd1.x]);
                float e3 = __expf(acc[mi][ni][3] * scale + lg1 + table[dd1.y]);
                size_t o0 = (size_t)blockIdx.z * zsC + (size_t)r0 * ldc + cc;
                size_t o1 = (size_t)blockIdx.z * zsC + (size_t)(r0 + 8) * ldc + cc;
                *reinterpret_cast<uint32_t*>(Coh + o0) = pack_hi(e0, e1);
                *reinterpret_cast<uint32_t*>(Coh + o1) = pack_hi(e2, e3);
                rs0[mi] += e0 + e1;
                rs1[mi] += e2 + e3;
            }
        }
        __syncthreads();
        float* srs = reinterpret_cast<float*>(smem);
        #pragma unroll
        for (int mi = 0; mi < MI; ++mi) {
            float a = rs0[mi];
            a += __shfl_xor_sync(0xFFFFFFFFu, a, 1);
            a += __shfl_xor_sync(0xFFFFFFFFu, a, 2);
            float b = rs1[mi];
            b += __shfl_xor_sync(0xFFFFFFFFu, b, 1);
            b += __shfl_xor_sync(0xFFFFFFFFu, b, 2);
            if ((lane & 3) == 0) {
                int rr = mbase + mi * 16 + (lane >> 2);
                srs[wn * BM + rr]     = a;
                srs[wn * BM + rr + 8] = b;
            }
        }
        __syncthreads();
        if (tid < BM) {
            float part = srs[tid] + srs[BM + tid];
            rsp[((size_t)blockIdx.z * (size_t)M + m0 + tid) * 8 + blockIdx.x] = part;
        }
    }
}

// ---------------- 1/rowsum from nt deterministic partials ----------------
__global__ void rowsum_reduce_kernel(const float* __restrict__ rsp,
                                     float* __restrict__ rinv, int n, int nt) {
    int i = blockIdx.x * blockDim.x + threadIdx.x;
    if (i < n) {
        const float* p = rsp + (size_t)i * 8;
        float s = 0.f;
        for (int j = 0; j < nt; ++j) s += p[j];
        rinv[i] = 1.0f / s;
    }
}

// ---------------- split fp32 -> fp16 pair (elementwise) ----------------
__global__ void split_kernel(const float4* __restrict__ in, uint2* __restrict__ outH,
                             uint2* __restrict__ outL, int n4) {
    int i = blockIdx.x * blockDim.x + threadIdx.x;
    if (i < n4) {
        uint2 H, L; split4(in[i], H, L);
        outH[i] = H; outL[i] = L;
    }
}

// ---------------- dm int32 -> uint8 ----------------
__global__ void dm8_kernel(const int4* __restrict__ in, uchar4* __restrict__ out, int n4) {
    int i = blockIdx.x * blockDim.x + threadIdx.x;
    if (i < n4) {
        int4 v = in[i];
        out[i] = make_uchar4((uint8_t)v.x, (uint8_t)v.y, (uint8_t)v.z, (uint8_t)v.w);
    }
}

// ---------------- batched transpose + split: out[z][C,R] = in[z][R,C]^T ----------------
__global__ void transpose_split_kernel(const float* __restrict__ in, size_t zsIn,
                                       f16* __restrict__ outH, f16* __restrict__ outL,
                                       size_t zsOut, int R, int Ccols) {
    __shared__ float tile[32][33];
    in   += (size_t)blockIdx.z * zsIn;
    outH += (size_t)blockIdx.z * zsOut;
    if (outL) outL += (size_t)blockIdx.z * zsOut;
    int c0 = blockIdx.x * 32, r0 = blockIdx.y * 32;
    int x = threadIdx.x, y = threadIdx.y;           // 32 x 8
    #pragma unroll
    for (int j = 0; j < 32; j += 8)
        tile[y + j][x] = in[(size_t)(r0 + y + j) * Ccols + c0 + x];
    __syncthreads();
    #pragma unroll
    for (int j = 0; j < 32; j += 8) {
        float v = tile[x][y + j];
        f16 h = __float2half(v);
        size_t o = (size_t)(c0 + y + j) * R + r0 + x;
        outH[o] = h;
        if (outL) outL[o] = __float2half(v - __half2float(h));
    }
}

// ---------------- f16 transpose: out[C,R] = in[R,C]^T ----------------
__global__ void transpose_f16_kernel(const f16* __restrict__ in,
                                     f16* __restrict__ out, int R, int Ccols) {
    __shared__ f16 tile[32][33];
    int c0 = blockIdx.x * 32, r0 = blockIdx.y * 32;
    int x = threadIdx.x, y = threadIdx.y;
    #pragma unroll
    for (int j = 0; j < 32; j += 8)
        tile[y + j][x] = in[(size_t)(r0 + y + j) * Ccols + c0 + x];
    __syncthreads();
    #pragma unroll
    for (int j = 0; j < 32; j += 8)
        out[(size_t)(c0 + y + j) * R + r0 + x] = tile[x][y + j];
}

// ---------------- fused q bias ----------------
__global__ void fuse_bias_kernel(const float* __restrict__ bproj,
                                 const float* __restrict__ Wq,
                                 const float* __restrict__ bq,
                                 float* __restrict__ out) {
    int o = blockIdx.x * blockDim.x + threadIdx.x;
    float s = bq[o];
    for (int k = 0; k < HID; k++) s += bproj[k] * Wq[(size_t)k * HID + o];
    out[o] = s;
}

// ---------------- copy bk/bv into adjacent scratch [l][2][HID] ----------------
__global__ void copy_bkv_kernel(const float* __restrict__ bk, const float* __restrict__ bv,
                                float* __restrict__ out) {
    int i = blockIdx.x * blockDim.x + threadIdx.x;      // NLAYER*HID
    int l = i / HID, c = i % HID;
    out[(l * 2) * HID + c]     = bk[i];
    out[(l * 2 + 1) * HID + c] = bv[i];
}

// ---------------- community preprocessing (deterministic, stable) ----------------
__global__ void hist_kernel(const int* __restrict__ ntc) {
    __shared__ int sh[C_COMM];
    int chunk = blockIdx.x;
    for (int i = threadIdx.x; i < C_COMM; i += blockDim.x) sh[i] = 0;
    __syncthreads();
    atomicAdd(&sh[ntc[chunk * CHUNK + threadIdx.x]], 1);
    __syncthreads();
    for (int i = threadIdx.x; i < C_COMM; i += blockDim.x)
        g_hist[chunk * C_COMM + i] = sh[i];
}

__global__ void chunk_scan_kernel() {
    int c = blockIdx.x;
    __shared__ int s[NCHUNK];
    int t = threadIdx.x;
    int own = g_hist[t * C_COMM + c];
    s[t] = own;
    __syncthreads();
    for (int off = 1; off < NCHUNK; off <<= 1) {
        int v = (t >= off) ? s[t - off] : 0;
        __syncthreads();
        s[t] += v;
        __syncthreads();
    }
    g_chunkbase[t * C_COMM + c] = s[t] - own;
    if (t == NCHUNK - 1) g_counts[c] = s[t];
}

__global__ void offsets_kernel() {
    __shared__ int s[C_COMM];
    int t = threadIdx.x;
    int own = g_counts[t];
    s[t] = own;
    __syncthreads();
    for (int off = 1; off < C_COMM; off <<= 1) {
        int v = (t >= off) ? s[t - off] : 0;
        __syncthreads();
        s[t] += v;
        __syncthreads();
    }
    g_offsets[t] = s[t] - own;
    g_logc[t]    = logf((float)own);
    g_inv[t]     = 1.0f / (float)(own > 0 ? own : 1);
}

__global__ void scatter_kernel(const int* __restrict__ ntc) {
    __shared__ int s[CHUNK];
    int chunk = blockIdx.x;
    int t = threadIdx.x;
    int node = chunk * CHUNK + t;
    int c = ntc[node];
    s[t] = c;
    __syncthreads();
    int lrank = 0;
    for (int j = 0; j < t; j++) lrank += (s[j] == c);
    g_members[g_offsets[c] + g_chunkbase[chunk * C_COMM + c] + lrank] = node;
}

__global__ void comm_avg_kernel() {
    int c = blockIdx.x;
    int t = threadIdx.x;
    int off = g_offsets[c], cnt = g_counts[c];
    float a0 = 0.f, a1 = 0.f;
    for (int m = 0; m < cnt; m++) {
        const float* row = g_h + (size_t)g_members[off + m] * HID;
        a0 += row[t];
        a1 += row[t + 256];
    }
    float inv = g_inv[c];
    a0 *= inv; a1 *= inv;
    f16 h0 = __float2half(a0), h1 = __float2half(a1);
    g_cmh[c * HID + t]       = h0;
    g_cmh[c * HID + t + 256] = h1;
    g_cml[c * HID + t]       = __float2half(a0 - __half2float(h0));
    g_cml[c * HID + t + 256] = __float2half(a1 - __half2float(h1));
}

__global__ void bias_table_kernel(const float* __restrict__ emb,
                                  const float* __restrict__ w,
                                  const float* __restrict__ bptr) {
    int i = blockIdx.x;
    int t = threadIdx.x;
    float s = emb[i * HID + t]       * w[t]
            + emb[i * HID + t + 128] * w[t + 128]
            + emb[i * HID + t + 256] * w[t + 256]
            + emb[i * HID + t + 384] * w[t + 384];
    for (int o = 16; o; o >>= 1) s += __shfl_xor_sync(0xFFFFFFFFu, s, o);
    __shared__ float r[4];
    if ((t & 31) == 0) r[t >> 5] = s;
    __syncthreads();
    if (t == 0) g_table[i] = r[0] + r[1] + r[2] + r[3] + bptr[0];
}

// warp-per-row LayerNorm + ReLU; fp32 (optional) + fp16 pair outputs
__global__ void ln_relu_kernel(const float* __restrict__ in, float* __restrict__ outF,
                               f16* __restrict__ outH, f16* __restrict__ outL,
                               const float* __restrict__ g, const float* __restrict__ b) {
    int w = threadIdx.x >> 5, lane = threadIdx.x & 31;
    size_t row = (size_t)blockIdx.x * 8 + w;
    const float* x = in + row * HID;
    float4 v[4];
    float s = 0.f, q = 0.f;
    #pragma unroll
    for (int k = 0; k < 4; k++) {
        v[k] = *reinterpret_cast<const float4*>(x + k * 128 + lane * 4);
        s += v[k].x + v[k].y + v[k].z + v[k].w;
        q += v[k].x * v[k].x + v[k].y * v[k].y + v[k].z * v[k].z + v[k].w * v[k].w;
    }
    #pragma unroll
    for (int o = 16; o; o >>= 1) {
        s += __shfl_xor_sync(0xFFFFFFFFu, s, o);
        q += __shfl_xor_sync(0xFFFFFFFFu, q, o);
    }
    float mean = s * (1.0f / HID);
    float var  = q * (1.0f / HID) - mean * mean;
    float rstd = rsqrtf(var + EPS);
    #pragma unroll
    for (int k = 0; k < 4; k++) {
        int c = k * 128 + lane * 4;
        float4 gg = *reinterpret_cast<const float4*>(g + c);
        float4 bb = *reinterpret_cast<const float4*>(b + c);
        float4 y;
        y.x = fmaxf((v[k].x - mean) * rstd * gg.x + bb.x, 0.f);
        y.y = fmaxf((v[k].y - mean) * rstd * gg.y + bb.y, 0.f);
        y.z = fmaxf((v[k].z - mean) * rstd * gg.z + bb.z, 0.f);
        y.w = fmaxf((v[k].w - mean) * rstd * gg.w + bb.w, 0.f);
        if (outF) *reinterpret_cast<float4*>(outF + row * HID + c) = y;
        uint2 H, L; split4(y, H, L);
        *reinterpret_cast<uint2*>(outH + row * HID + c) = H;
        *reinterpret_cast<uint2*>(outL + row * HID + c) = L;
    }
}

// ---------------- host-side helpers ----------------
static const int SMEM_128_T2 = 3 * (2 * 10240 + 10240);      // 92160
static const int SMEM_128_T1 = 3 * (10240 + 10240);          // 61440
static const int SMEM_64_T3  = 3 * (2 * 10240 + 2 * 5120);   // 92160
static const int SMEM_64_T2  = 3 * (2 * 10240 + 5120);       // 76800

static void tc_nn(int M, int Nc, int K,
                  const f16* Ah, const f16* Al, int lda,
                  const f16* Bth, const float* bias,
                  float* Cf, f16* Coh, f16* Col, int ldc)
{
    if (Nc % 128 == 0) {
        dim3 g(Nc / 128, M / 128, 1);
        mma_gemm<128, 0, 2><<<g, 256, SMEM_128_T2>>>(M, K, Ah, Al, lda, 0, Bth, nullptr, K, 0,
                                                     bias, 0, Cf, Coh, Col, ldc, 0,
                                                     0.f, nullptr, nullptr, nullptr, 0,
                                                     nullptr, nullptr);
    } else {
        dim3 g(Nc / 64, M / 128, 1);
        mma_gemm<64, 0, 2><<<g, 256, SMEM_64_T2>>>(M, K, Ah, Al, lda, 0, Bth, nullptr, K, 0,
                                                   bias, 0, Cf, Coh, Col, ldc, 0,
                                                   0.f, nullptr, nullptr, nullptr, 0,
                                                   nullptr, nullptr);
    }
}

extern "C" void kernel_launch(void* const* d_in, const int* in_sizes, int n_in,
                              void* d_out, int out_size)
{
    // ---- input mapping (auto-detect metadata order) ----
    const float *x      = (const float*)d_in[0];
    const int   *dm     = (const int*)  d_in[1];
    const int   *ntc    = (const int*)  d_in[2];
    const float *W_in1  = (const float*)d_in[3];
    const float *b_in1  = (const float*)d_in[4];
    const float *ln_in_g= (const float*)d_in[5];
    const float *ln_in_b= (const float*)d_in[6];
    const float *W_in2  = (const float*)d_in[7];
    const float *b_in2  = (const float*)d_in[8];
    const float *Wproj, *Wq, *Wk, *Wv, *ffW1, *ffW2;
    const float *bproj, *bq, *bk, *bv, *ffb1, *ffb2;
    const float *dis_emb, *dis_w, *dis_b;
    const float *ffg1, *ffbeta1, *ffg2, *ffbeta2, *Wout, *bout;

    if (in_sizes[10] == NLAYER * HID * HID) {
        Wproj  = (const float*)d_in[9];  Wq     = (const float*)d_in[10];
        Wk     = (const float*)d_in[11]; Wv     = (const float*)d_in[12];
        ffW1   = (const float*)d_in[13]; ffW2   = (const float*)d_in[14];
        bproj  = (const float*)d_in[15]; bq     = (const float*)d_in[16];
        bk     = (const float*)d_in[17]; bv     = (const float*)d_in[18];
        ffb1   = (const float*)d_in[19]; ffb2   = (const float*)d_in[20];
        dis_emb= (const float*)d_in[21]; dis_w  = (const float*)d_in[22];
        dis_b  = (const float*)d_in[23];
        ffg1   = (const float*)d_in[24]; ffbeta1= (const float*)d_in[25];
        ffg2   = (const float*)d_in[26]; ffbeta2= (const float*)d_in[27];
        Wout   = (const float*)d_in[28]; bout   = (const float*)d_in[29];
    } else {
        Wproj  = (const float*)d_in[9];  bproj  = (const float*)d_in[10];
        Wq     = (const float*)d_in[11]; bq     = (const float*)d_in[12];
        Wk     = (const float*)d_in[13]; bk     = (const float*)d_in[14];
        Wv     = (const float*)d_in[15]; bv     = (const float*)d_in[16];
        dis_emb= (const float*)d_in[17]; dis_w  = (const float*)d_in[18];
        dis_b  = (const float*)d_in[19];
        ffW1   = (const float*)d_in[20]; ffb1   = (const float*)d_in[21];
        ffg1   = (const float*)d_in[22]; ffbeta1= (const float*)d_in[23];
        ffW2   = (const float*)d_in[24]; ffb2   = (const float*)d_in[25];
        ffg2   = (const float*)d_in[26]; ffbeta2= (const float*)d_in[27];
        Wout   = (const float*)d_in[28]; bout   = (const float*)d_in[29];
    }

    cudaFuncSetAttribute(mma_gemm<128, 0, 2>, cudaFuncAttributeMaxDynamicSharedMemorySize, SMEM_128_T2);
    cudaFuncSetAttribute(mma_gemm<128, 1, 2>, cudaFuncAttributeMaxDynamicSharedMemorySize, SMEM_128_T2);
    cudaFuncSetAttribute(mma_gemm<128, 0, 1>, cudaFuncAttributeMaxDynamicSharedMemorySize, SMEM_128_T1);
    cudaFuncSetAttribute(mma_gemm<64, 0, 2>,  cudaFuncAttributeMaxDynamicSharedMemorySize, SMEM_64_T2);
    cudaFuncSetAttribute(mma_gemm<64, 0, 3>,  cudaFuncAttributeMaxDynamicSharedMemorySize, SMEM_64_T3);

    // ---- scratch pointers ----
    float *p_h, *p_t0, *p_t1, *p_logc, *p_table, *p_bfq, *p_bkv, *p_rsp, *p_rinv;
    f16 *p_xh, *p_xl, *p_hh, *p_hl, *p_t0h, *p_t0l, *p_t1h, *p_t1l, *p_qh, *p_ql;
    f16 *p_ph, *p_cmh, *p_cml, *p_kvh, *p_vth, *p_wh, *p_wl;
    uint8_t *p_dm8;
    cudaGetSymbolAddress((void**)&p_h,    g_h);
    cudaGetSymbolAddress((void**)&p_t0,   g_t0);
    cudaGetSymbolAddress((void**)&p_t1,   g_t1);
    cudaGetSymbolAddress((void**)&p_logc, g_logc);
    cudaGetSymbolAddress((void**)&p_table,g_table);
    cudaGetSymbolAddress((void**)&p_bfq,  g_bfq);
    cudaGetSymbolAddress((void**)&p_bkv,  g_bkv);
    cudaGetSymbolAddress((void**)&p_rsp,  g_rsp);
    cudaGetSymbolAddress((void**)&p_rinv, g_rinv);
    cudaGetSymbolAddress((void**)&p_dm8,  g_dm8);
    cudaGetSymbolAddress((void**)&p_xh,  g_xh);  cudaGetSymbolAddress((void**)&p_xl,  g_xl);
    cudaGetSymbolAddress((void**)&p_hh,  g_hh);  cudaGetSymbolAddress((void**)&p_hl,  g_hl);
    cudaGetSymbolAddress((void**)&p_t0h, g_t0h); cudaGetSymbolAddress((void**)&p_t0l, g_t0l);
    cudaGetSymbolAddress((void**)&p_t1h, g_t1h); cudaGetSymbolAddress((void**)&p_t1l, g_t1l);
    cudaGetSymbolAddress((void**)&p_qh,  g_qh);  cudaGetSymbolAddress((void**)&p_ql,  g_ql);
    cudaGetSymbolAddress((void**)&p_ph,  g_ph);
    cudaGetSymbolAddress((void**)&p_cmh, g_cmh); cudaGetSymbolAddress((void**)&p_cml, g_cml);
    cudaGetSymbolAddress((void**)&p_kvh, g_kvh);
    cudaGetSymbolAddress((void**)&p_vth, g_vth);
    cudaGetSymbolAddress((void**)&p_wh,  g_wh);  cudaGetSymbolAddress((void**)&p_wl,  g_wl);
    #define WH(i) (p_wh + (size_t)(i) * HID * HID)
    #define WL(i) (p_wl + (size_t)(i) * HID * HID)

    const float scale = 1.0f / sqrtf((float)DHEAD);
    const size_t W2 = (size_t)HID * HID;

    // ---- weight preprocessing (batched) ----
    // slots: 0=W_in1T 1=W_in2T; layer l: s0=2+l*5 {0:WfqT,1:WkT,2:WvT,3:ffW1T,4:ffW2T};
    // 12=WoutT; 13,14=WqT l0,l1 (pair); 15,16=Wproj split l0,l1 (pair)
    {
        dim3 b(32, 8);
        transpose_split_kernel<<<dim3(HID / 32, IN_DIM / 32, 1), b>>>(
            W_in1, 0, WH(0), nullptr, 0, IN_DIM, HID);
        transpose_split_kernel<<<dim3(HID / 32, HID / 32, 1), b>>>(
            W_in2, 0, WH(1), nullptr, 0, HID, HID);
        transpose_split_kernel<<<dim3(OUT_DIM / 32, HID / 32, 1), b>>>(
            Wout, 0, WH(12), nullptr, 0, HID, OUT_DIM);
        transpose_split_kernel<<<dim3(HID / 32, HID / 32, NLAYER), b>>>(
            Wq, W2, WH(13), WL(13), W2, HID, HID);
        transpose_split_kernel<<<dim3(HID / 32, HID / 32, NLAYER), b>>>(
            Wk, W2, WH(3), nullptr, 5 * W2, HID, HID);
        transpose_split_kernel<<<dim3(HID / 32, HID / 32, NLAYER), b>>>(
            Wv, W2, WH(4), nullptr, 5 * W2, HID, HID);
        transpose_split_kernel<<<dim3(HID / 32, HID / 32, NLAYER), b>>>(
            ffW1, W2, WH(5), nullptr, 5 * W2, HID, HID);
        transpose_split_kernel<<<dim3(HID / 32, HID / 32, NLAYER), b>>>(
            ffW2, W2, WH(6), nullptr, 5 * W2, HID, HID);
    }
    split_kernel<<<N_NODES * IN_DIM / 1024, 256>>>((const float4*)x, (uint2*)p_xh, (uint2*)p_xl,
                                                   N_NODES * IN_DIM / 4);
    split_kernel<<<NLAYER * HID * HID / 1024, 256>>>((const float4*)Wproj,
                                                     (uint2*)WH(15), (uint2*)WL(15),
                                                     NLAYER * HID * HID / 4);
    // fused q weight (both layers, 3-term for precision); output hi only (B-side use)
    {
        dim3 g(HID / 64, HID / 128, NLAYER);
        mma_gemm<64, 0, 3><<<g, 256, SMEM_64_T3>>>(HID, HID,
                                                   WH(13), WL(13), HID, W2,
                                                   WH(15), WL(15), HID, W2,
                                                   nullptr, 0, nullptr, WH(2), nullptr, HID, 5 * W2,
                                                   0.f, nullptr, nullptr, nullptr, 0,
                                                   nullptr, nullptr);
    }
    for (int l = 0; l < NLAYER; l++)
        fuse_bias_kernel<<<HID / 256, 256>>>(bproj + (size_t)l * HID,
                                             Wq + (size_t)l * W2,
                                             bq + (size_t)l * HID, p_bfq + (size_t)l * HID);
    copy_bkv_kernel<<<NLAYER * HID / 256, 256>>>(bk, bv, p_bkv);
    dm8_kernel<<<(int)((size_t)N_NODES * C_COMM / 1024), 256>>>(
        (const int4*)dm, (uchar4*)p_dm8, (int)((size_t)N_NODES * C_COMM / 4));

    // ---- community preprocessing (deterministic) ----
    hist_kernel      <<<NCHUNK, CHUNK>>>(ntc);
    chunk_scan_kernel<<<C_COMM, NCHUNK>>>();
    offsets_kernel   <<<1, C_COMM>>>();
    scatter_kernel   <<<NCHUNK, CHUNK>>>(ntc);

    // ---- fc_in ----
    tc_nn(N_NODES, HID, IN_DIM, p_xh, p_xl, IN_DIM, WH(0), b_in1,
          p_t0, nullptr, nullptr, HID);
    ln_relu_kernel<<<N_NODES / 8, 256>>>(p_t0, nullptr, p_t0h, p_t0l, ln_in_g, ln_in_b);
    tc_nn(N_NODES, HID, HID, p_t0h, p_t0l, HID, WH(1), b_in2,
          p_h, p_hh, p_hl, HID);

    // ---- layers ----
    for (int l = 0; l < NLAYER; l++) {
        int s0 = 2 + l * 5;
        bias_table_kernel<<<NDIST, 128>>>(dis_emb + (size_t)l * NDIST * HID,
                                          dis_w + (size_t)l * HID, dis_b + l);
        comm_avg_kernel<<<C_COMM, 256>>>();

        // q = h @ WfqT^T + bfq (pair out; q is A-side of dots)
        tc_nn(N_NODES, HID, HID, p_hh, p_hl, HID, WH(s0),
              p_bfq + (size_t)l * HID, nullptr, p_qh, p_ql, HID);
        // k and v in one launch (z: 0=k, 1=v); hi only (both B-side consumers)
        {
            dim3 g(HID / 128, C_COMM / 128, 2);
            mma_gemm<128, 0, 2><<<g, 256, SMEM_128_T2>>>(
                C_COMM, HID,
                p_cmh, p_cml, HID, 0,
                WH(s0 + 1), nullptr, HID, W2,
                p_bkv + (size_t)l * 2 * HID, HID,
                nullptr, p_kvh, nullptr, HID, (size_t)C_COMM * HID,
                0.f, nullptr, nullptr, nullptr, 0,
                nullptr, nullptr);
        }
        transpose_f16_kernel<<<dim3(HID / 32, C_COMM / 32), dim3(32, 8)>>>(
            p_kvh + (size_t)C_COMM * HID, p_vth, C_COMM, HID);

        // dots per head: fused exp epilogue -> e hi + row partial sums
        {
            dim3 g(C_COMM / 128, N_NODES / 128, NHEAD);
            mma_gemm<128, 1, 2><<<g, 256, SMEM_128_T2>>>(
                N_NODES, DHEAD,
                p_qh, p_ql, HID, (size_t)DHEAD,
                p_kvh, nullptr, HID, (size_t)DHEAD,
                nullptr, 0,
                nullptr, p_ph, nullptr, C_COMM, (size_t)N_NODES * C_COMM,
                scale, p_logc, p_table, p_dm8, C_COMM,
                p_rsp, nullptr);
        }
        rowsum_reduce_kernel<<<NHEAD * N_NODES / 256, 256>>>(p_rsp, p_rinv,
                                                             NHEAD * N_NODES, C_COMM / 128);

        // AV per head: 1-term (A = e hi), multiply by 1/rowsum -> t0 pair
        {
            dim3 g(DHEAD / 128, N_NODES / 128, NHEAD);
            mma_gemm<128, 0, 1><<<g, 256, SMEM_128_T1>>>(
                N_NODES, C_COMM,
                p_ph, nullptr, C_COMM, (size_t)N_NODES * C_COMM,
                p_vth, nullptr, C_COMM, (size_t)DHEAD * C_COMM,
                nullptr, 0,
                nullptr, p_t0h, p_t0l, HID, (size_t)DHEAD,
                0.f, nullptr, nullptr, nullptr, 0,
                nullptr, p_rinv);
        }

        tc_nn(N_NODES, HID, HID, p_t0h, p_t0l, HID, WH(s0 + 3),
              ffb1 + (size_t)l * HID, p_t1, nullptr, nullptr, HID);
        ln_relu_kernel<<<N_NODES / 8, 256>>>(p_t1, nullptr, p_t1h, p_t1l,
                                             ffg1 + (size_t)l * HID, ffbeta1 + (size_t)l * HID);
        tc_nn(N_NODES, HID, HID, p_t1h, p_t1l, HID, WH(s0 + 4),
              ffb2 + (size_t)l * HID, p_t0, nullptr, nullptr, HID);
        ln_relu_kernel<<<N_NODES / 8, 256>>>(p_t0, p_h, p_hh, p_hl,
                                             ffg2 + (size_t)l * HID, ffbeta2 + (size_t)l * HID);
    }

    // ---- output projection ----
    tc_nn(N_NODES, OUT_DIM, HID, p_hh, p_hl, HID, WH(12), bout,
          (float*)d_out, nullptr, nullptr, OUT_DIM);
}